// round 1
// baseline (speedup 1.0000x reference)
#include <cuda_runtime.h>
#include <math.h>

// Problem constants: B=4, T=2048, C=1024 (all dims divisible by 128/8 -> no edge guards)
#define BB 4
#define TT 2048
#define CC 1024

// Scratch (allocation-free rule: __device__ globals)
__device__ float g_Q[(size_t)BB * TT * CC];
__device__ float g_K[(size_t)BB * TT * CC];
__device__ float g_V[(size_t)BB * TT * CC];
__device__ float g_S[(size_t)BB * TT * TT];

// ---------------------------------------------------------------------------
// 128x128x8 SGEMM tile, NT variant: C[m,n] = alpha * sum_k A[m,k]*B[n,k]
// 256 threads, 8x8 microtile per thread.
// ---------------------------------------------------------------------------
__device__ __forceinline__ void gemm_nt_tile(
    const float* __restrict__ A, int lda,
    const float* __restrict__ Bm, int ldb,
    float* __restrict__ Cm, int ldc,
    int Ktot, int row0, int col0, float alpha)
{
    __shared__ float As[8][128];
    __shared__ float Bs[8][128];

    const int tid = threadIdx.x;
    const int r = tid >> 1;          // 0..127
    const int c = (tid & 1) * 4;     // 0 or 4
    const float* Ap = A + (size_t)(row0 + r) * lda + c;
    const float* Bp = Bm + (size_t)(col0 + r) * ldb + c;

    const int tx = tid & 15;         // col group
    const int ty = tid >> 4;         // row group

    float acc[8][8];
    #pragma unroll
    for (int i = 0; i < 8; i++)
        #pragma unroll
        for (int j = 0; j < 8; j++) acc[i][j] = 0.0f;

    for (int k0 = 0; k0 < Ktot; k0 += 8) {
        float4 a4 = *(const float4*)(Ap + k0);
        float4 b4 = *(const float4*)(Bp + k0);
        As[c + 0][r] = a4.x; As[c + 1][r] = a4.y; As[c + 2][r] = a4.z; As[c + 3][r] = a4.w;
        Bs[c + 0][r] = b4.x; Bs[c + 1][r] = b4.y; Bs[c + 2][r] = b4.z; Bs[c + 3][r] = b4.w;
        __syncthreads();

        #pragma unroll
        for (int kk = 0; kk < 8; kk++) {
            float ar[8], br[8];
            #pragma unroll
            for (int i = 0; i < 8; i++) ar[i] = As[kk][ty * 8 + i];
            #pragma unroll
            for (int j = 0; j < 8; j++) br[j] = Bs[kk][tx * 8 + j];
            #pragma unroll
            for (int i = 0; i < 8; i++)
                #pragma unroll
                for (int j = 0; j < 8; j++)
                    acc[i][j] = fmaf(ar[i], br[j], acc[i][j]);
        }
        __syncthreads();
    }

    #pragma unroll
    for (int i = 0; i < 8; i++) {
        float* cp = Cm + (size_t)(row0 + ty * 8 + i) * ldc + col0 + tx * 8;
        #pragma unroll
        for (int j = 0; j < 8; j++) cp[j] = acc[i][j] * alpha;
    }
}

// ---------------------------------------------------------------------------
// NN variant: C[m,n] = sum_k A[m,k]*B[k,n]
// ---------------------------------------------------------------------------
__device__ __forceinline__ void gemm_nn_tile(
    const float* __restrict__ A, int lda,
    const float* __restrict__ Bm, int ldb,
    float* __restrict__ Cm, int ldc,
    int Ktot, int row0, int col0)
{
    __shared__ float As[8][128];
    __shared__ float Bs[8][128];

    const int tid = threadIdx.x;
    const int r = tid >> 1;
    const int c = (tid & 1) * 4;
    const float* Ap = A + (size_t)(row0 + r) * lda + c;

    const int brw = tid >> 5;          // 0..7  (k row within tile)
    const int bcl = (tid & 31) * 4;    // 0..124
    const float* Bp = Bm + (size_t)brw * ldb + col0 + bcl;

    const int tx = tid & 15;
    const int ty = tid >> 4;

    float acc[8][8];
    #pragma unroll
    for (int i = 0; i < 8; i++)
        #pragma unroll
        for (int j = 0; j < 8; j++) acc[i][j] = 0.0f;

    for (int k0 = 0; k0 < Ktot; k0 += 8) {
        float4 a4 = *(const float4*)(Ap + k0);
        float4 b4 = *(const float4*)(Bp + (size_t)k0 * ldb);
        As[c + 0][r] = a4.x; As[c + 1][r] = a4.y; As[c + 2][r] = a4.z; As[c + 3][r] = a4.w;
        *(float4*)&Bs[brw][bcl] = b4;
        __syncthreads();

        #pragma unroll
        for (int kk = 0; kk < 8; kk++) {
            float ar[8], br[8];
            #pragma unroll
            for (int i = 0; i < 8; i++) ar[i] = As[kk][ty * 8 + i];
            #pragma unroll
            for (int j = 0; j < 8; j++) br[j] = Bs[kk][tx * 8 + j];
            #pragma unroll
            for (int i = 0; i < 8; i++)
                #pragma unroll
                for (int j = 0; j < 8; j++)
                    acc[i][j] = fmaf(ar[i], br[j], acc[i][j]);
        }
        __syncthreads();
    }

    #pragma unroll
    for (int i = 0; i < 8; i++) {
        float* cp = Cm + (size_t)(row0 + ty * 8 + i) * ldc + col0 + tx * 8;
        #pragma unroll
        for (int j = 0; j < 8; j++) cp[j] = acc[i][j];
    }
}

// ---------------------------------------------------------------------------
// Kernel 1: QKV projections. y = x @ W.T  (W is [Cout, Cin], row-major, NT gemm)
// grid: (CC/128, (BB*TT)/128, 3)
// ---------------------------------------------------------------------------
__global__ __launch_bounds__(256) void qkv_kernel(
    const float* __restrict__ x,
    const float* __restrict__ Wq,
    const float* __restrict__ Wk,
    const float* __restrict__ Wv)
{
    const float* W = (blockIdx.z == 0) ? Wq : (blockIdx.z == 1) ? Wk : Wv;
    float* out = (blockIdx.z == 0) ? g_Q : (blockIdx.z == 1) ? g_K : g_V;
    int row0 = blockIdx.y * 128;
    int col0 = blockIdx.x * 128;
    gemm_nt_tile(x, CC, W, CC, out, CC, CC, row0, col0, 1.0f);
}

// ---------------------------------------------------------------------------
// Kernel 2: S = scale * Q @ K^T, causal tile skip. grid: (TT/128, TT/128, BB)
// ---------------------------------------------------------------------------
__global__ __launch_bounds__(256) void qk_kernel()
{
    int b = blockIdx.z;
    int row0 = blockIdx.y * 128;
    int col0 = blockIdx.x * 128;
    if (col0 > row0 + 127) return;   // tile strictly above diagonal: softmax never reads it
    const float* Q = g_Q + (size_t)b * TT * CC;
    const float* K = g_K + (size_t)b * TT * CC;
    float* S = g_S + (size_t)b * TT * TT;
    gemm_nt_tile(Q, CC, K, CC, S, TT, CC, row0, col0, 0.03125f /* 1024^-0.5 */);
}

// ---------------------------------------------------------------------------
// Kernel 3: causal row softmax over S. grid: (TT, BB), 256 threads.
// Writes zeros above the diagonal so PV needs no mask.
// ---------------------------------------------------------------------------
__global__ __launch_bounds__(256) void softmax_kernel()
{
    int b = blockIdx.y;
    int t = blockIdx.x;
    float* row = g_S + ((size_t)b * TT + t) * TT;
    int n = t + 1;
    int tid = threadIdx.x;
    __shared__ float red[256];

    float m = -1e30f;
    for (int j = tid; j < n; j += 256) m = fmaxf(m, row[j]);
    red[tid] = m;
    __syncthreads();
    for (int s = 128; s > 0; s >>= 1) {
        if (tid < s) red[tid] = fmaxf(red[tid], red[tid + s]);
        __syncthreads();
    }
    m = red[0];
    __syncthreads();

    float sum = 0.0f;
    for (int j = tid; j < n; j += 256) {
        float e = __expf(row[j] - m);
        row[j] = e;
        sum += e;
    }
    red[tid] = sum;
    __syncthreads();
    for (int s = 128; s > 0; s >>= 1) {
        if (tid < s) red[tid] += red[tid + s];
        __syncthreads();
    }
    float inv = 1.0f / red[0];

    for (int j = tid; j < n; j += 256) row[j] *= inv;
    for (int j = n + tid; j < TT; j += 256) row[j] = 0.0f;
}

// ---------------------------------------------------------------------------
// Kernel 4: O = P @ V, K-loop truncated at row-tile end (causal).
// grid: (CC/128, TT/128, BB)
// ---------------------------------------------------------------------------
__global__ __launch_bounds__(256) void pv_kernel(float* __restrict__ out)
{
    int b = blockIdx.z;
    int row0 = blockIdx.y * 128;
    int col0 = blockIdx.x * 128;
    const float* P = g_S + (size_t)b * TT * TT;
    const float* V = g_V + (size_t)b * TT * CC;
    float* O = out + (size_t)b * TT * CC;
    int Ktot = row0 + 128;           // rows in this tile only attend to keys < row0+128
    gemm_nn_tile(P, TT, V, CC, O, CC, Ktot, row0, col0);
}

// ---------------------------------------------------------------------------
extern "C" void kernel_launch(void* const* d_in, const int* in_sizes, int n_in,
                              void* d_out, int out_size)
{
    const float* x  = (const float*)d_in[0];
    const float* Wq = (const float*)d_in[1];
    const float* Wk = (const float*)d_in[2];
    const float* Wv = (const float*)d_in[3];
    float* out = (float*)d_out;

    qkv_kernel<<<dim3(CC / 128, (BB * TT) / 128, 3), 256>>>(x, Wq, Wk, Wv);
    qk_kernel<<<dim3(TT / 128, TT / 128, BB), 256>>>();
    softmax_kernel<<<dim3(TT, BB), 256>>>();
    pv_kernel<<<dim3(CC / 128, TT / 128, BB), 256>>>(out);
}

// round 3
// speedup vs baseline: 2.4543x; 2.4543x over previous
#include <cuda_runtime.h>
#include <cuda_bf16.h>
#include <stdint.h>
#include <math.h>

#define BB 4
#define TT 2048
#define CC 1024
#define NTOK 8192   // BB*TT

typedef __nv_bfloat16 bf16;

// ---------------- scratch (__device__ globals; allocation-free rule) -------
__device__ __align__(256) bf16 g_Xhi[NTOK * CC];
__device__ __align__(256) bf16 g_Xlo[NTOK * CC];
__device__ __align__(256) bf16 g_Whi[3 * CC * CC];
__device__ __align__(256) bf16 g_Wlo[3 * CC * CC];
__device__ __align__(256) bf16 g_Qhi[NTOK * CC];
__device__ __align__(256) bf16 g_Qlo[NTOK * CC];
__device__ __align__(256) bf16 g_Khi[NTOK * CC];
__device__ __align__(256) bf16 g_Klo[NTOK * CC];
__device__ __align__(256) bf16 g_Vhi[NTOK * CC];     // natural [token][channel]
__device__ __align__(256) bf16 g_Vlo[NTOK * CC];
__device__ __align__(256) float g_S[(size_t)BB * TT * TT];
__device__ __align__(256) bf16 g_Phi[(size_t)BB * TT * TT];
__device__ __align__(256) bf16 g_Plo[(size_t)BB * TT * TT];

// ---------------- helpers ---------------------------------------------------
__device__ __forceinline__ uint32_t smem_u32(const void* p) {
    uint32_t a;
    asm("{ .reg .u64 t; cvta.to.shared.u64 t, %1; cvt.u32.u64 %0, t; }" : "=r"(a) : "l"(p));
    return a;
}
__device__ __forceinline__ void cp16(uint32_t s, const void* g) {
    asm volatile("cp.async.cg.shared.global [%0], [%1], 16;" :: "r"(s), "l"(g));
}
#define CP_COMMIT() asm volatile("cp.async.commit_group;" ::: "memory")
#define CP_WAIT1()  asm volatile("cp.async.wait_group 1;" ::: "memory")

__device__ __forceinline__ void ldsm4(uint32_t a, uint32_t& r0, uint32_t& r1,
                                      uint32_t& r2, uint32_t& r3) {
    asm volatile("ldmatrix.sync.aligned.m8n8.x4.shared.b16 {%0,%1,%2,%3}, [%4];"
                 : "=r"(r0), "=r"(r1), "=r"(r2), "=r"(r3) : "r"(a));
}
__device__ __forceinline__ void ldsm4t(uint32_t a, uint32_t& r0, uint32_t& r1,
                                       uint32_t& r2, uint32_t& r3) {
    asm volatile("ldmatrix.sync.aligned.m8n8.x4.trans.shared.b16 {%0,%1,%2,%3}, [%4];"
                 : "=r"(r0), "=r"(r1), "=r"(r2), "=r"(r3) : "r"(a));
}
__device__ __forceinline__ void mma16816(float* c, const uint32_t* a, uint32_t b0, uint32_t b1) {
    asm volatile(
        "mma.sync.aligned.m16n8k16.row.col.f32.bf16.bf16.f32 "
        "{%0,%1,%2,%3}, {%4,%5,%6,%7}, {%8,%9}, {%0,%1,%2,%3};"
        : "+f"(c[0]), "+f"(c[1]), "+f"(c[2]), "+f"(c[3])
        : "r"(a[0]), "r"(a[1]), "r"(a[2]), "r"(a[3]), "r"(b0), "r"(b1));
}

__device__ __forceinline__ uint32_t bfpack(float a, float b) {
    __nv_bfloat162 h = __floats2bfloat162_rn(a, b);
    return *reinterpret_cast<uint32_t*>(&h);
}
// pack hi parts; compute+pack lo residuals
__device__ __forceinline__ void store_split(bf16* hi, bf16* lo, size_t idx, float a, float b) {
    bf16 h0 = __float2bfloat16_rn(a), h1 = __float2bfloat16_rn(b);
    *(uint32_t*)(hi + idx) = bfpack(a, b);
    *(uint32_t*)(lo + idx) = bfpack(a - __bfloat162float(h0), b - __bfloat162float(h1));
}

// smem: A bufs 2x18432, B bufs 2x18432 (trans-B tile 64x272B=17408 fits)
#define ABUF_B 18432
#define SMEM_BYTES (4 * ABUF_B)
#define PAD_NT 144   // bytes per 64-elem row (128B + 16 pad)
#define PAD_TR 272   // bytes per 128-elem row (256B + 16 pad)

extern __shared__ char dsm[];

// ---------------------------------------------------------------------------
// 128x128 tile, 3-term split-bf16 GEMM: C = sum_k A[row0+m, k] * B(k, col0+n)
// NT: B stored [n][k] (k contiguous). TRANSB: B stored [k][n] (n contiguous).
// acc: float[64] = [mt][nt][4]
// ---------------------------------------------------------------------------
template <bool TRANSB>
__device__ __forceinline__ void run_gemm(
    const bf16* __restrict__ Ahi, const bf16* __restrict__ Alo, int lda,
    const bf16* __restrict__ Bhi, const bf16* __restrict__ Blo, int ldb,
    int Ktot, int row0, int col0, float* acc)
{
    const int tid = threadIdx.x;
    const int wid = tid >> 5, lane = tid & 31;
    const int wm = (wid >> 2) * 64, wn = (wid & 3) * 32;
    const uint32_t smem = smem_u32(dsm);
    const int nk = Ktot >> 6;
    const int NSTEP = 3 * nk;

    auto load_tile = [&](int s, int buf) {
        const int term = s / nk;
        const int kk0 = (s - term * nk) << 6;
        const bf16* A = (term == 2) ? Alo : Ahi;
        const bf16* B = (term == 1) ? Blo : Bhi;
        const uint32_t sA = smem + buf * ABUF_B;
        const uint32_t sB = smem + (2 + buf) * ABUF_B;
        #pragma unroll
        for (int i = 0; i < 4; i++) {
            int c = tid + i * 256;                 // 0..1023
            int r = c >> 3, kc = c & 7;
            cp16(sA + r * PAD_NT + kc * 16,
                 A + (size_t)(row0 + r) * lda + kk0 + kc * 8);
            if (!TRANSB) {
                cp16(sB + r * PAD_NT + kc * 16,
                     B + (size_t)(col0 + r) * ldb + kk0 + kc * 8);
            } else {
                int rt = c >> 4, nc = c & 15;
                cp16(sB + rt * PAD_TR + nc * 16,
                     B + (size_t)(kk0 + rt) * ldb + col0 + nc * 8);
            }
        }
    };

    load_tile(0, 0); CP_COMMIT();
    load_tile(1, 1); CP_COMMIT();

    for (int s = 0; s < NSTEP; s++) {
        const int buf = s & 1;
        const uint32_t sA = smem + buf * ABUF_B;
        const uint32_t sB = smem + (2 + buf) * ABUF_B;
        CP_WAIT1();
        __syncthreads();

        #pragma unroll
        for (int kk = 0; kk < 4; kk++) {
            uint32_t aF[4][4];
            #pragma unroll
            for (int mt = 0; mt < 4; mt++) {
                uint32_t a = sA + (uint32_t)(wm + mt * 16 + (lane & 7) + ((lane >> 3) & 1) * 8) * PAD_NT
                           + kk * 32 + ((lane >> 4) & 1) * 16;
                ldsm4(a, aF[mt][0], aF[mt][1], aF[mt][2], aF[mt][3]);
            }
            uint32_t bF[4][2];
            #pragma unroll
            for (int pr = 0; pr < 2; pr++) {
                uint32_t r0, r1, r2, r3;
                if (!TRANSB) {
                    uint32_t a = sB + (uint32_t)(wn + pr * 16 + (lane & 7) + ((lane >> 3) & 1) * 8) * PAD_NT
                               + kk * 32 + ((lane >> 4) & 1) * 16;
                    ldsm4(a, r0, r1, r2, r3);
                } else {
                    uint32_t a = sB + (uint32_t)(kk * 16 + (lane & 7) + ((lane >> 4) & 1) * 8) * PAD_TR
                               + (wn + pr * 16) * 2 + ((lane >> 3) & 1) * 16;
                    ldsm4t(a, r0, r1, r2, r3);
                }
                bF[pr * 2 + 0][0] = r0; bF[pr * 2 + 0][1] = r2;
                bF[pr * 2 + 1][0] = r1; bF[pr * 2 + 1][1] = r3;
            }
            #pragma unroll
            for (int mt = 0; mt < 4; mt++)
                #pragma unroll
                for (int nt = 0; nt < 4; nt++)
                    mma16816(acc + (mt * 4 + nt) * 4, aF[mt], bF[nt][0], bF[nt][1]);
        }

        __syncthreads();
        if (s + 2 < NSTEP) load_tile(s + 2, buf);
        CP_COMMIT();
    }
}

// ---------------------------------------------------------------------------
// Kernel: QKV projection. grid (8, 64, 3). out z=0:Q z=1:K z=2:V, split hi/lo.
// ---------------------------------------------------------------------------
__global__ __launch_bounds__(256) void qkv_gemm()
{
    const int z = blockIdx.z;
    const int row0 = blockIdx.y * 128;       // token
    const int col0 = blockIdx.x * 128;       // out channel
    float acc[64];
    #pragma unroll
    for (int i = 0; i < 64; i++) acc[i] = 0.0f;
    run_gemm<false>(g_Xhi, g_Xlo, CC,
                    g_Whi + (size_t)z * CC * CC, g_Wlo + (size_t)z * CC * CC, CC,
                    CC, row0, col0, acc);
    bf16* ohi = (z == 0) ? g_Qhi : (z == 1) ? g_Khi : g_Vhi;
    bf16* olo = (z == 0) ? g_Qlo : (z == 1) ? g_Klo : g_Vlo;
    const int wid = threadIdx.x >> 5, lane = threadIdx.x & 31;
    const int rbase = row0 + (wid >> 2) * 64 + (lane >> 2);
    const int cbase = col0 + (wid & 3) * 32 + 2 * (lane & 3);
    #pragma unroll
    for (int mt = 0; mt < 4; mt++)
        #pragma unroll
        for (int nt = 0; nt < 4; nt++) {
            const float* c = acc + (mt * 4 + nt) * 4;
            size_t r = rbase + mt * 16, cc = cbase + nt * 8;
            store_split(ohi, olo, r * CC + cc, c[0], c[1]);
            store_split(ohi, olo, (r + 8) * CC + cc, c[2], c[3]);
        }
}

// ---------------------------------------------------------------------------
// Kernel: S = scale * Q K^T, causal tile skip. grid (16, 16, 4)
// ---------------------------------------------------------------------------
__global__ __launch_bounds__(256) void qk_gemm()
{
    const int row0 = blockIdx.y * 128;
    const int col0 = blockIdx.x * 128;
    if (col0 > row0 + 127) return;
    const int b = blockIdx.z;
    const size_t qo = (size_t)b * TT * CC;
    float acc[64];
    #pragma unroll
    for (int i = 0; i < 64; i++) acc[i] = 0.0f;
    run_gemm<false>(g_Qhi + qo, g_Qlo + qo, CC, g_Khi + qo, g_Klo + qo, CC,
                    CC, row0, col0, acc);
    const int wid = threadIdx.x >> 5, lane = threadIdx.x & 31;
    const int rbase = row0 + (wid >> 2) * 64 + (lane >> 2);
    const int cbase = col0 + (wid & 3) * 32 + 2 * (lane & 3);
    float* S = g_S + (size_t)b * TT * TT;
    #pragma unroll
    for (int mt = 0; mt < 4; mt++)
        #pragma unroll
        for (int nt = 0; nt < 4; nt++) {
            const float* c = acc + (mt * 4 + nt) * 4;
            size_t r = rbase + mt * 16, cc = cbase + nt * 8;
            *(float2*)(S + r * TT + cc) = make_float2(c[0] * 0.03125f, c[1] * 0.03125f);
            *(float2*)(S + (r + 8) * TT + cc) = make_float2(c[2] * 0.03125f, c[3] * 0.03125f);
        }
}

// ---------------------------------------------------------------------------
// Kernel: causal softmax + split P to bf16 hi/lo. grid (2048, 4)
// ---------------------------------------------------------------------------
__global__ __launch_bounds__(256) void softmax_split()
{
    const int b = blockIdx.y, t = blockIdx.x;
    float* row = g_S + ((size_t)b * TT + t) * TT;
    bf16* ph = g_Phi + ((size_t)b * TT + t) * TT;
    bf16* pl = g_Plo + ((size_t)b * TT + t) * TT;
    const int n = t + 1;
    const int nend = ((t >> 7) + 1) << 7;
    const int tid = threadIdx.x;
    __shared__ float red[256];

    float m = -1e30f;
    for (int j = tid; j < n; j += 256) m = fmaxf(m, row[j]);
    red[tid] = m; __syncthreads();
    for (int s = 128; s > 0; s >>= 1) {
        if (tid < s) red[tid] = fmaxf(red[tid], red[tid + s]);
        __syncthreads();
    }
    m = red[0]; __syncthreads();

    float sum = 0.0f;
    for (int j = tid; j < n; j += 256) {
        float e = __expf(row[j] - m);
        row[j] = e;
        sum += e;
    }
    red[tid] = sum; __syncthreads();
    for (int s = 128; s > 0; s >>= 1) {
        if (tid < s) red[tid] += red[tid + s];
        __syncthreads();
    }
    const float inv = 1.0f / red[0];

    for (int j = tid; j < n; j += 256) {
        float p = row[j] * inv;
        bf16 h = __float2bfloat16_rn(p);
        ph[j] = h;
        pl[j] = __float2bfloat16_rn(p - __bfloat162float(h));
    }
    const bf16 z = __float2bfloat16_rn(0.0f);
    for (int j = n + tid; j < nend; j += 256) { ph[j] = z; pl[j] = z; }
}

// ---------------------------------------------------------------------------
// Kernel: O = P V (K truncated causally; V [s][n] via trans-B). grid (8,16,4)
// ---------------------------------------------------------------------------
__global__ __launch_bounds__(256) void pv_gemm(float* __restrict__ out)
{
    const int b = blockIdx.z;
    const int row0 = blockIdx.y * 128;     // query tile
    const int col0 = blockIdx.x * 128;     // channel tile
    const size_t po = (size_t)b * TT * TT;
    const size_t vo = (size_t)b * TT * CC;
    float acc[64];
    #pragma unroll
    for (int i = 0; i < 64; i++) acc[i] = 0.0f;
    run_gemm<true>(g_Phi + po, g_Plo + po, TT, g_Vhi + vo, g_Vlo + vo, CC,
                   row0 + 128, row0, col0, acc);
    const int wid = threadIdx.x >> 5, lane = threadIdx.x & 31;
    const int rbase = row0 + (wid >> 2) * 64 + (lane >> 2);
    const int cbase = col0 + (wid & 3) * 32 + 2 * (lane & 3);
    float* O = out + (size_t)b * TT * CC;
    #pragma unroll
    for (int mt = 0; mt < 4; mt++)
        #pragma unroll
        for (int nt = 0; nt < 4; nt++) {
            const float* c = acc + (mt * 4 + nt) * 4;
            size_t r = rbase + mt * 16, cc = cbase + nt * 8;
            *(float2*)(O + r * CC + cc) = make_float2(c[0], c[1]);
            *(float2*)(O + (r + 8) * CC + cc) = make_float2(c[2], c[3]);
        }
}

// ---------------------------------------------------------------------------
// Kernel: fp32 -> bf16 hi/lo split for x and the 3 weight matrices.
// ---------------------------------------------------------------------------
__global__ __launch_bounds__(256) void convert_all(
    const float* __restrict__ x, const float* __restrict__ wq,
    const float* __restrict__ wk, const float* __restrict__ wv)
{
    const long i = (long)blockIdx.x * 256 + threadIdx.x;
    const float* src; bf16* hi; bf16* lo; size_t off;
    if (i < 2097152) {
        src = x; hi = g_Xhi; lo = g_Xlo; off = (size_t)i;
    } else {
        long j = i - 2097152;
        int w = (int)(j / 262144);
        off = (size_t)(j - (long)w * 262144);
        src = (w == 0) ? wq : (w == 1) ? wk : wv;
        hi = g_Whi + (size_t)w * CC * CC;
        lo = g_Wlo + (size_t)w * CC * CC;
    }
    float4 v = ((const float4*)src)[off];
    bf16 h0 = __float2bfloat16_rn(v.x), h1 = __float2bfloat16_rn(v.y);
    bf16 h2 = __float2bfloat16_rn(v.z), h3 = __float2bfloat16_rn(v.w);
    uint2 hw, lw;
    hw.x = bfpack(v.x, v.y); hw.y = bfpack(v.z, v.w);
    lw.x = bfpack(v.x - __bfloat162float(h0), v.y - __bfloat162float(h1));
    lw.y = bfpack(v.z - __bfloat162float(h2), v.w - __bfloat162float(h3));
    ((uint2*)hi)[off] = hw;
    ((uint2*)lo)[off] = lw;
}

// ---------------------------------------------------------------------------
extern "C" void kernel_launch(void* const* d_in, const int* in_sizes, int n_in,
                              void* d_out, int out_size)
{
    const float* x  = (const float*)d_in[0];
    const float* Wq = (const float*)d_in[1];
    const float* Wk = (const float*)d_in[2];
    const float* Wv = (const float*)d_in[3];
    float* out = (float*)d_out;

    cudaFuncSetAttribute(qkv_gemm, cudaFuncAttributeMaxDynamicSharedMemorySize, SMEM_BYTES);
    cudaFuncSetAttribute(qk_gemm,  cudaFuncAttributeMaxDynamicSharedMemorySize, SMEM_BYTES);
    cudaFuncSetAttribute(pv_gemm,  cudaFuncAttributeMaxDynamicSharedMemorySize, SMEM_BYTES);

    convert_all<<<11264, 256>>>(x, Wq, Wk, Wv);
    qkv_gemm<<<dim3(8, 64, 3), 256, SMEM_BYTES>>>();
    qk_gemm<<<dim3(16, 16, BB), 256, SMEM_BYTES>>>();
    softmax_split<<<dim3(TT, BB), 256>>>();
    pv_gemm<<<dim3(8, 16, BB), 256, SMEM_BYTES>>>(out);
}

// round 4
// speedup vs baseline: 2.4827x; 1.0116x over previous
#include <cuda_runtime.h>
#include <cuda_bf16.h>
#include <stdint.h>
#include <math.h>

#define BB 4
#define TT 2048
#define CC 1024
#define NTOK 8192   // BB*TT

typedef __nv_bfloat16 bf16;

// ---------------- scratch (__device__ globals; allocation-free rule) -------
__device__ __align__(256) bf16 g_Xhi[NTOK * CC];
__device__ __align__(256) bf16 g_Xlo[NTOK * CC];
__device__ __align__(256) bf16 g_Whi[3 * CC * CC];
__device__ __align__(256) bf16 g_Wlo[3 * CC * CC];
__device__ __align__(256) bf16 g_Qhi[NTOK * CC];
__device__ __align__(256) bf16 g_Qlo[NTOK * CC];
__device__ __align__(256) bf16 g_Khi[NTOK * CC];
__device__ __align__(256) bf16 g_Klo[NTOK * CC];
__device__ __align__(256) bf16 g_Vhi[NTOK * CC];     // natural [token][channel]
__device__ __align__(256) bf16 g_Vlo[NTOK * CC];
__device__ __align__(256) float g_S[(size_t)BB * TT * TT];
__device__ __align__(256) bf16 g_Phi[(size_t)BB * TT * TT];
__device__ __align__(256) bf16 g_Plo[(size_t)BB * TT * TT];

// ---------------- helpers ---------------------------------------------------
__device__ __forceinline__ uint32_t smem_u32(const void* p) {
    uint32_t a;
    asm("{ .reg .u64 t; cvta.to.shared.u64 t, %1; cvt.u32.u64 %0, t; }" : "=r"(a) : "l"(p));
    return a;
}
__device__ __forceinline__ void cp16(uint32_t s, const void* g) {
    asm volatile("cp.async.cg.shared.global [%0], [%1], 16;" :: "r"(s), "l"(g));
}
#define CP_COMMIT() asm volatile("cp.async.commit_group;" ::: "memory")
#define CP_WAIT1()  asm volatile("cp.async.wait_group 1;" ::: "memory")

__device__ __forceinline__ void ldsm4(uint32_t a, uint32_t& r0, uint32_t& r1,
                                      uint32_t& r2, uint32_t& r3) {
    asm volatile("ldmatrix.sync.aligned.m8n8.x4.shared.b16 {%0,%1,%2,%3}, [%4];"
                 : "=r"(r0), "=r"(r1), "=r"(r2), "=r"(r3) : "r"(a));
}
__device__ __forceinline__ void ldsm4t(uint32_t a, uint32_t& r0, uint32_t& r1,
                                       uint32_t& r2, uint32_t& r3) {
    asm volatile("ldmatrix.sync.aligned.m8n8.x4.trans.shared.b16 {%0,%1,%2,%3}, [%4];"
                 : "=r"(r0), "=r"(r1), "=r"(r2), "=r"(r3) : "r"(a));
}
__device__ __forceinline__ void mma16816(float* c, const uint32_t* a, uint32_t b0, uint32_t b1) {
    asm volatile(
        "mma.sync.aligned.m16n8k16.row.col.f32.bf16.bf16.f32 "
        "{%0,%1,%2,%3}, {%4,%5,%6,%7}, {%8,%9}, {%0,%1,%2,%3};"
        : "+f"(c[0]), "+f"(c[1]), "+f"(c[2]), "+f"(c[3])
        : "r"(a[0]), "r"(a[1]), "r"(a[2]), "r"(a[3]), "r"(b0), "r"(b1));
}

__device__ __forceinline__ uint32_t bfpack(float a, float b) {
    __nv_bfloat162 h = __floats2bfloat162_rn(a, b);
    return *reinterpret_cast<uint32_t*>(&h);
}
__device__ __forceinline__ void store_split(bf16* hi, bf16* lo, size_t idx, float a, float b) {
    bf16 h0 = __float2bfloat16_rn(a), h1 = __float2bfloat16_rn(b);
    *(uint32_t*)(hi + idx) = bfpack(a, b);
    *(uint32_t*)(lo + idx) = bfpack(a - __bfloat162float(h0), b - __bfloat162float(h1));
}

// smem: 3 stages x 4 tiles (Ahi, Alo, Bhi, Blo) x 18432B
#define TILE_B  18432
#define STAGE_B (4 * TILE_B)
#define SMEM_BYTES (3 * STAGE_B)
#define PAD_NT 144   // bytes per 64-elem k-row (128B + 16 pad)
#define PAD_TR 272   // bytes per 128-elem n-row (256B + 16 pad)

extern __shared__ char dsm[];

// ---------------------------------------------------------------------------
// 128x128 tile, 3-term split-bf16 GEMM, term-fused K stages:
// per K-chunk load Ahi/Alo/Bhi/Blo, compute hi*hi + hi*lo + lo*hi.
// ---------------------------------------------------------------------------
template <bool TRANSB>
__device__ __forceinline__ void run_gemm(
    const bf16* __restrict__ Ahi, const bf16* __restrict__ Alo, int lda,
    const bf16* __restrict__ Bhi, const bf16* __restrict__ Blo, int ldb,
    int Ktot, int row0, int col0, float* acc)
{
    const int tid = threadIdx.x;
    const int wid = tid >> 5, lane = tid & 31;
    const int wm = (wid >> 2) * 64, wn = (wid & 3) * 32;
    const uint32_t smem = smem_u32(dsm);
    const int nk = Ktot >> 6;

    auto load_stage = [&](int s, int buf) {
        const int kk0 = s << 6;
        const uint32_t base = smem + buf * STAGE_B;
        #pragma unroll
        for (int i = 0; i < 4; i++) {
            int c = tid + i * 256;                 // 0..1023
            int r = c >> 3, kc = c & 7;
            uint32_t aoff = (uint32_t)r * PAD_NT + kc * 16;
            const bf16* pah = Ahi + (size_t)(row0 + r) * lda + kk0 + kc * 8;
            const bf16* pal = Alo + (size_t)(row0 + r) * lda + kk0 + kc * 8;
            cp16(base + aoff, pah);
            cp16(base + TILE_B + aoff, pal);
            if (!TRANSB) {
                const bf16* pbh = Bhi + (size_t)(col0 + r) * ldb + kk0 + kc * 8;
                const bf16* pbl = Blo + (size_t)(col0 + r) * ldb + kk0 + kc * 8;
                cp16(base + 2 * TILE_B + aoff, pbh);
                cp16(base + 3 * TILE_B + aoff, pbl);
            } else {
                int rt = c >> 4, nc = c & 15;
                uint32_t boff = (uint32_t)rt * PAD_TR + nc * 16;
                const bf16* pbh = Bhi + (size_t)(kk0 + rt) * ldb + col0 + nc * 8;
                const bf16* pbl = Blo + (size_t)(kk0 + rt) * ldb + col0 + nc * 8;
                cp16(base + 2 * TILE_B + boff, pbh);
                cp16(base + 3 * TILE_B + boff, pbl);
            }
        }
    };

    load_stage(0, 0); CP_COMMIT();
    if (nk > 1) load_stage(1, 1);
    CP_COMMIT();

    for (int s = 0; s < nk; s++) {
        const int buf = s % 3;
        const uint32_t base = smem + buf * STAGE_B;
        CP_WAIT1();
        __syncthreads();
        if (s + 2 < nk) load_stage(s + 2, (s + 2) % 3);
        CP_COMMIT();

        #pragma unroll
        for (int kk = 0; kk < 4; kk++) {
            // A-hi fragments (reused for 2 of 3 term-MMAs)
            uint32_t aH[4][4];
            #pragma unroll
            for (int mt = 0; mt < 4; mt++) {
                uint32_t a = base + (uint32_t)(wm + mt * 16 + (lane & 7) + ((lane >> 3) & 1) * 8) * PAD_NT
                           + kk * 32 + ((lane >> 4) & 1) * 16;
                ldsm4(a, aH[mt][0], aH[mt][1], aH[mt][2], aH[mt][3]);
            }
            // B fragments (hi and lo)
            uint32_t bH[4][2], bL[4][2];
            #pragma unroll
            for (int pr = 0; pr < 2; pr++) {
                uint32_t h0, h1, h2, h3, l0, l1, l2, l3;
                if (!TRANSB) {
                    uint32_t a = (uint32_t)(wn + pr * 16 + (lane & 7) + ((lane >> 3) & 1) * 8) * PAD_NT
                               + kk * 32 + ((lane >> 4) & 1) * 16;
                    ldsm4(base + 2 * TILE_B + a, h0, h1, h2, h3);
                    ldsm4(base + 3 * TILE_B + a, l0, l1, l2, l3);
                } else {
                    uint32_t a = (uint32_t)(kk * 16 + (lane & 7) + ((lane >> 4) & 1) * 8) * PAD_TR
                               + (wn + pr * 16) * 2 + ((lane >> 3) & 1) * 16;
                    ldsm4t(base + 2 * TILE_B + a, h0, h1, h2, h3);
                    ldsm4t(base + 3 * TILE_B + a, l0, l1, l2, l3);
                }
                bH[pr * 2 + 0][0] = h0; bH[pr * 2 + 0][1] = h2;
                bH[pr * 2 + 1][0] = h1; bH[pr * 2 + 1][1] = h3;
                bL[pr * 2 + 0][0] = l0; bL[pr * 2 + 0][1] = l2;
                bL[pr * 2 + 1][0] = l1; bL[pr * 2 + 1][1] = l3;
            }
            // term 1: hi*hi, term 2: hi*lo
            #pragma unroll
            for (int mt = 0; mt < 4; mt++)
                #pragma unroll
                for (int nt = 0; nt < 4; nt++) {
                    mma16816(acc + (mt * 4 + nt) * 4, aH[mt], bH[nt][0], bH[nt][1]);
                    mma16816(acc + (mt * 4 + nt) * 4, aH[mt], bL[nt][0], bL[nt][1]);
                }
            // A-lo fragments; term 3: lo*hi
            uint32_t aL[4][4];
            #pragma unroll
            for (int mt = 0; mt < 4; mt++) {
                uint32_t a = base + TILE_B
                           + (uint32_t)(wm + mt * 16 + (lane & 7) + ((lane >> 3) & 1) * 8) * PAD_NT
                           + kk * 32 + ((lane >> 4) & 1) * 16;
                ldsm4(a, aL[mt][0], aL[mt][1], aL[mt][2], aL[mt][3]);
            }
            #pragma unroll
            for (int mt = 0; mt < 4; mt++)
                #pragma unroll
                for (int nt = 0; nt < 4; nt++)
                    mma16816(acc + (mt * 4 + nt) * 4, aL[mt], bH[nt][0], bH[nt][1]);
        }
        __syncthreads();
    }
}

// ---------------------------------------------------------------------------
// Kernel: QKV projection. grid (8, 64, 3). out z=0:Q z=1:K z=2:V, split hi/lo.
// ---------------------------------------------------------------------------
__global__ __launch_bounds__(256) void qkv_gemm()
{
    const int z = blockIdx.z;
    const int row0 = blockIdx.y * 128;       // token
    const int col0 = blockIdx.x * 128;       // out channel
    float acc[64];
    #pragma unroll
    for (int i = 0; i < 64; i++) acc[i] = 0.0f;
    run_gemm<false>(g_Xhi, g_Xlo, CC,
                    g_Whi + (size_t)z * CC * CC, g_Wlo + (size_t)z * CC * CC, CC,
                    CC, row0, col0, acc);
    bf16* ohi = (z == 0) ? g_Qhi : (z == 1) ? g_Khi : g_Vhi;
    bf16* olo = (z == 0) ? g_Qlo : (z == 1) ? g_Klo : g_Vlo;
    const int wid = threadIdx.x >> 5, lane = threadIdx.x & 31;
    const int rbase = row0 + (wid >> 2) * 64 + (lane >> 2);
    const int cbase = col0 + (wid & 3) * 32 + 2 * (lane & 3);
    #pragma unroll
    for (int mt = 0; mt < 4; mt++)
        #pragma unroll
        for (int nt = 0; nt < 4; nt++) {
            const float* c = acc + (mt * 4 + nt) * 4;
            size_t r = rbase + mt * 16, cc = cbase + nt * 8;
            store_split(ohi, olo, r * CC + cc, c[0], c[1]);
            store_split(ohi, olo, (r + 8) * CC + cc, c[2], c[3]);
        }
}

// ---------------------------------------------------------------------------
// Kernel: S = scale * Q K^T, causal tile skip. grid (16, 16, 4)
// ---------------------------------------------------------------------------
__global__ __launch_bounds__(256) void qk_gemm()
{
    const int row0 = blockIdx.y * 128;
    const int col0 = blockIdx.x * 128;
    if (col0 > row0 + 127) return;
    const int b = blockIdx.z;
    const size_t qo = (size_t)b * TT * CC;
    float acc[64];
    #pragma unroll
    for (int i = 0; i < 64; i++) acc[i] = 0.0f;
    run_gemm<false>(g_Qhi + qo, g_Qlo + qo, CC, g_Khi + qo, g_Klo + qo, CC,
                    CC, row0, col0, acc);
    const int wid = threadIdx.x >> 5, lane = threadIdx.x & 31;
    const int rbase = row0 + (wid >> 2) * 64 + (lane >> 2);
    const int cbase = col0 + (wid & 3) * 32 + 2 * (lane & 3);
    float* S = g_S + (size_t)b * TT * TT;
    #pragma unroll
    for (int mt = 0; mt < 4; mt++)
        #pragma unroll
        for (int nt = 0; nt < 4; nt++) {
            const float* c = acc + (mt * 4 + nt) * 4;
            size_t r = rbase + mt * 16, cc = cbase + nt * 8;
            *(float2*)(S + r * TT + cc) = make_float2(c[0] * 0.03125f, c[1] * 0.03125f);
            *(float2*)(S + (r + 8) * TT + cc) = make_float2(c[2] * 0.03125f, c[3] * 0.03125f);
        }
}

// ---------------------------------------------------------------------------
// Kernel: causal softmax + split P to bf16 hi/lo. grid (2048, 4)
// ---------------------------------------------------------------------------
__global__ __launch_bounds__(256) void softmax_split()
{
    const int b = blockIdx.y, t = blockIdx.x;
    float* row = g_S + ((size_t)b * TT + t) * TT;
    bf16* ph = g_Phi + ((size_t)b * TT + t) * TT;
    bf16* pl = g_Plo + ((size_t)b * TT + t) * TT;
    const int n = t + 1;
    const int nend = ((t >> 7) + 1) << 7;
    const int tid = threadIdx.x;
    __shared__ float red[256];

    float m = -1e30f;
    for (int j = tid; j < n; j += 256) m = fmaxf(m, row[j]);
    red[tid] = m; __syncthreads();
    for (int s = 128; s > 0; s >>= 1) {
        if (tid < s) red[tid] = fmaxf(red[tid], red[tid + s]);
        __syncthreads();
    }
    m = red[0]; __syncthreads();

    float sum = 0.0f;
    for (int j = tid; j < n; j += 256) {
        float e = __expf(row[j] - m);
        row[j] = e;
        sum += e;
    }
    red[tid] = sum; __syncthreads();
    for (int s = 128; s > 0; s >>= 1) {
        if (tid < s) red[tid] += red[tid + s];
        __syncthreads();
    }
    const float inv = 1.0f / red[0];

    for (int j = tid; j < n; j += 256) {
        float p = row[j] * inv;
        bf16 h = __float2bfloat16_rn(p);
        ph[j] = h;
        pl[j] = __float2bfloat16_rn(p - __bfloat162float(h));
    }
    const bf16 z = __float2bfloat16_rn(0.0f);
    for (int j = n + tid; j < nend; j += 256) { ph[j] = z; pl[j] = z; }
}

// ---------------------------------------------------------------------------
// Kernel: O = P V (K truncated causally; V [s][n] via trans-B). grid (8,16,4)
// ---------------------------------------------------------------------------
__global__ __launch_bounds__(256) void pv_gemm(float* __restrict__ out)
{
    const int b = blockIdx.z;
    const int row0 = blockIdx.y * 128;     // query tile
    const int col0 = blockIdx.x * 128;     // channel tile
    const size_t po = (size_t)b * TT * TT;
    const size_t vo = (size_t)b * TT * CC;
    float acc[64];
    #pragma unroll
    for (int i = 0; i < 64; i++) acc[i] = 0.0f;
    run_gemm<true>(g_Phi + po, g_Plo + po, TT, g_Vhi + vo, g_Vlo + vo, CC,
                   row0 + 128, row0, col0, acc);
    const int wid = threadIdx.x >> 5, lane = threadIdx.x & 31;
    const int rbase = row0 + (wid >> 2) * 64 + (lane >> 2);
    const int cbase = col0 + (wid & 3) * 32 + 2 * (lane & 3);
    float* O = out + (size_t)b * TT * CC;
    #pragma unroll
    for (int mt = 0; mt < 4; mt++)
        #pragma unroll
        for (int nt = 0; nt < 4; nt++) {
            const float* c = acc + (mt * 4 + nt) * 4;
            size_t r = rbase + mt * 16, cc = cbase + nt * 8;
            *(float2*)(O + r * CC + cc) = make_float2(c[0], c[1]);
            *(float2*)(O + (r + 8) * CC + cc) = make_float2(c[2], c[3]);
        }
}

// ---------------------------------------------------------------------------
// Kernel: fp32 -> bf16 hi/lo split for x and the 3 weight matrices.
// ---------------------------------------------------------------------------
__global__ __launch_bounds__(256) void convert_all(
    const float* __restrict__ x, const float* __restrict__ wq,
    const float* __restrict__ wk, const float* __restrict__ wv)
{
    const long i = (long)blockIdx.x * 256 + threadIdx.x;
    const float* src; bf16* hi; bf16* lo; size_t off;
    if (i < 2097152) {
        src = x; hi = g_Xhi; lo = g_Xlo; off = (size_t)i;
    } else {
        long j = i - 2097152;
        int w = (int)(j / 262144);
        off = (size_t)(j - (long)w * 262144);
        src = (w == 0) ? wq : (w == 1) ? wk : wv;
        hi = g_Whi + (size_t)w * CC * CC;
        lo = g_Wlo + (size_t)w * CC * CC;
    }
    float4 v = ((const float4*)src)[off];
    bf16 h0 = __float2bfloat16_rn(v.x), h1 = __float2bfloat16_rn(v.y);
    bf16 h2 = __float2bfloat16_rn(v.z), h3 = __float2bfloat16_rn(v.w);
    uint2 hw, lw;
    hw.x = bfpack(v.x, v.y); hw.y = bfpack(v.z, v.w);
    lw.x = bfpack(v.x - __bfloat162float(h0), v.y - __bfloat162float(h1));
    lw.y = bfpack(v.z - __bfloat162float(h2), v.w - __bfloat162float(h3));
    ((uint2*)hi)[off] = hw;
    ((uint2*)lo)[off] = lw;
}

// ---------------------------------------------------------------------------
extern "C" void kernel_launch(void* const* d_in, const int* in_sizes, int n_in,
                              void* d_out, int out_size)
{
    const float* x  = (const float*)d_in[0];
    const float* Wq = (const float*)d_in[1];
    const float* Wk = (const float*)d_in[2];
    const float* Wv = (const float*)d_in[3];
    float* out = (float*)d_out;

    cudaFuncSetAttribute(qkv_gemm, cudaFuncAttributeMaxDynamicSharedMemorySize, SMEM_BYTES);
    cudaFuncSetAttribute(qk_gemm,  cudaFuncAttributeMaxDynamicSharedMemorySize, SMEM_BYTES);
    cudaFuncSetAttribute(pv_gemm,  cudaFuncAttributeMaxDynamicSharedMemorySize, SMEM_BYTES);

    convert_all<<<11264, 256>>>(x, Wq, Wk, Wv);
    qkv_gemm<<<dim3(8, 64, 3), 256, SMEM_BYTES>>>();
    qk_gemm<<<dim3(16, 16, BB), 256, SMEM_BYTES>>>();
    softmax_split<<<dim3(TT, BB), 256>>>();
    pv_gemm<<<dim3(8, 16, BB), 256, SMEM_BYTES>>>(out);
}

// round 5
// speedup vs baseline: 3.4579x; 1.3928x over previous
#include <cuda_runtime.h>
#include <cuda_fp16.h>
#include <stdint.h>
#include <math.h>

#define BB 4
#define TT 2048
#define CC 1024
#define NTOK 8192   // BB*TT

typedef __half fp16;

// ---------------- scratch (__device__ globals; allocation-free rule) -------
__device__ __align__(256) fp16 g_Xhi[NTOK * CC];
__device__ __align__(256) fp16 g_Xlo[NTOK * CC];
__device__ __align__(256) fp16 g_Wh [3 * CC * CC];             // single limb
__device__ __align__(256) fp16 g_Qhi[NTOK * CC];
__device__ __align__(256) fp16 g_Qlo[NTOK * CC];
__device__ __align__(256) fp16 g_Kh [NTOK * CC];               // single limb
__device__ __align__(256) fp16 g_Vh [NTOK * CC];               // single limb, [token][ch]
__device__ __align__(256) float g_S[(size_t)BB * TT * TT];
__device__ __align__(256) fp16 g_Phi[(size_t)BB * TT * TT];
__device__ __align__(256) fp16 g_Plo[(size_t)BB * TT * TT];

// ---------------- helpers ---------------------------------------------------
__device__ __forceinline__ uint32_t smem_u32(const void* p) {
    uint32_t a;
    asm("{ .reg .u64 t; cvta.to.shared.u64 t, %1; cvt.u32.u64 %0, t; }" : "=r"(a) : "l"(p));
    return a;
}
__device__ __forceinline__ void cp16(uint32_t s, const void* g) {
    asm volatile("cp.async.cg.shared.global [%0], [%1], 16;" :: "r"(s), "l"(g));
}
#define CP_COMMIT() asm volatile("cp.async.commit_group;" ::: "memory")
#define CP_WAIT2()  asm volatile("cp.async.wait_group 2;" ::: "memory")

__device__ __forceinline__ void ldsm4(uint32_t a, uint32_t& r0, uint32_t& r1,
                                      uint32_t& r2, uint32_t& r3) {
    asm volatile("ldmatrix.sync.aligned.m8n8.x4.shared.b16 {%0,%1,%2,%3}, [%4];"
                 : "=r"(r0), "=r"(r1), "=r"(r2), "=r"(r3) : "r"(a));
}
__device__ __forceinline__ void ldsm4t(uint32_t a, uint32_t& r0, uint32_t& r1,
                                       uint32_t& r2, uint32_t& r3) {
    asm volatile("ldmatrix.sync.aligned.m8n8.x4.trans.shared.b16 {%0,%1,%2,%3}, [%4];"
                 : "=r"(r0), "=r"(r1), "=r"(r2), "=r"(r3) : "r"(a));
}
__device__ __forceinline__ void mma16816(float* c, const uint32_t* a, uint32_t b0, uint32_t b1) {
    asm volatile(
        "mma.sync.aligned.m16n8k16.row.col.f32.f16.f16.f32 "
        "{%0,%1,%2,%3}, {%4,%5,%6,%7}, {%8,%9}, {%0,%1,%2,%3};"
        : "+f"(c[0]), "+f"(c[1]), "+f"(c[2]), "+f"(c[3])
        : "r"(a[0]), "r"(a[1]), "r"(a[2]), "r"(a[3]), "r"(b0), "r"(b1));
}

__device__ __forceinline__ uint32_t h2pack(float a, float b) {
    __half2 h = __floats2half2_rn(a, b);
    return *reinterpret_cast<uint32_t*>(&h);
}
__device__ __forceinline__ void store_split(fp16* hi, fp16* lo, size_t idx, float a, float b) {
    fp16 h0 = __float2half_rn(a), h1 = __float2half_rn(b);
    *(uint32_t*)(hi + idx) = h2pack(a, b);
    *(uint32_t*)(lo + idx) = h2pack(a - __half2float(h0), b - __half2float(h1));
}

// smem: 4 stages x 3 tiles (Ahi, Alo, B) x 18432B = 221184B
#define TILE_B  18432
#define STAGE_B (3 * TILE_B)
#define NSTAGE  4
#define SMEM_BYTES (NSTAGE * STAGE_B)
#define PAD_NT 144   // bytes per 64-elem k-row (128B + 16 pad)
#define PAD_TR 272   // bytes per 128-elem n-row (256B + 16 pad)

extern __shared__ char dsm[];

// ---------------------------------------------------------------------------
// 128x128 tile, 2-term split-fp16 GEMM: C = (Ahi + Alo) * B, B single fp16.
// NT: B stored [n][k] (k contig).  TRANSB: B stored [k][n] (n contig).
// ---------------------------------------------------------------------------
template <bool TRANSB>
__device__ __forceinline__ void run_gemm(
    const fp16* __restrict__ Ahi, const fp16* __restrict__ Alo, int lda,
    const fp16* __restrict__ B, int ldb,
    int Ktot, int row0, int col0, float* acc)
{
    const int tid = threadIdx.x;
    const int wid = tid >> 5, lane = tid & 31;
    const int wm = (wid >> 2) * 64, wn = (wid & 3) * 32;
    const uint32_t smem = smem_u32(dsm);
    const int nk = Ktot >> 6;

    auto load_stage = [&](int s, int buf) {
        const int kk0 = s << 6;
        const uint32_t base = smem + buf * STAGE_B;
        #pragma unroll
        for (int i = 0; i < 4; i++) {
            int c = tid + i * 256;                 // 0..1023
            int r = c >> 3, kc = c & 7;
            uint32_t aoff = (uint32_t)r * PAD_NT + kc * 16;
            cp16(base + aoff,          Ahi + (size_t)(row0 + r) * lda + kk0 + kc * 8);
            cp16(base + TILE_B + aoff, Alo + (size_t)(row0 + r) * lda + kk0 + kc * 8);
            if (!TRANSB) {
                cp16(base + 2 * TILE_B + aoff,
                     B + (size_t)(col0 + r) * ldb + kk0 + kc * 8);
            } else {
                int rt = c >> 4, nc = c & 15;
                cp16(base + 2 * TILE_B + (uint32_t)rt * PAD_TR + nc * 16,
                     B + (size_t)(kk0 + rt) * ldb + col0 + nc * 8);
            }
        }
    };

    load_stage(0, 0); CP_COMMIT();
    if (nk > 1) load_stage(1, 1);
    CP_COMMIT();
    if (nk > 2) load_stage(2, 2);
    CP_COMMIT();

    for (int s = 0; s < nk; s++) {
        const int buf = s & 3;
        const uint32_t base = smem + buf * STAGE_B;
        CP_WAIT2();
        __syncthreads();
        if (s + 3 < nk) load_stage(s + 3, (s + 3) & 3);
        CP_COMMIT();

        #pragma unroll
        for (int kk = 0; kk < 4; kk++) {
            uint32_t aH[4][4];
            #pragma unroll
            for (int mt = 0; mt < 4; mt++) {
                uint32_t a = base + (uint32_t)(wm + mt * 16 + (lane & 7) + ((lane >> 3) & 1) * 8) * PAD_NT
                           + kk * 32 + ((lane >> 4) & 1) * 16;
                ldsm4(a, aH[mt][0], aH[mt][1], aH[mt][2], aH[mt][3]);
            }
            uint32_t bF[4][2];
            #pragma unroll
            for (int pr = 0; pr < 2; pr++) {
                uint32_t r0, r1, r2, r3;
                if (!TRANSB) {
                    uint32_t a = base + 2 * TILE_B
                               + (uint32_t)(wn + pr * 16 + (lane & 7) + ((lane >> 3) & 1) * 8) * PAD_NT
                               + kk * 32 + ((lane >> 4) & 1) * 16;
                    ldsm4(a, r0, r1, r2, r3);
                } else {
                    uint32_t a = base + 2 * TILE_B
                               + (uint32_t)(kk * 16 + (lane & 7) + ((lane >> 4) & 1) * 8) * PAD_TR
                               + (wn + pr * 16) * 2 + ((lane >> 3) & 1) * 16;
                    ldsm4t(a, r0, r1, r2, r3);
                }
                bF[pr * 2 + 0][0] = r0; bF[pr * 2 + 0][1] = r2;
                bF[pr * 2 + 1][0] = r1; bF[pr * 2 + 1][1] = r3;
            }
            uint32_t aL[4][4];
            #pragma unroll
            for (int mt = 0; mt < 4; mt++) {
                uint32_t a = base + TILE_B
                           + (uint32_t)(wm + mt * 16 + (lane & 7) + ((lane >> 3) & 1) * 8) * PAD_NT
                           + kk * 32 + ((lane >> 4) & 1) * 16;
                ldsm4(a, aL[mt][0], aL[mt][1], aL[mt][2], aL[mt][3]);
            }
            #pragma unroll
            for (int mt = 0; mt < 4; mt++)
                #pragma unroll
                for (int nt = 0; nt < 4; nt++) {
                    mma16816(acc + (mt * 4 + nt) * 4, aH[mt], bF[nt][0], bF[nt][1]);
                    mma16816(acc + (mt * 4 + nt) * 4, aL[mt], bF[nt][0], bF[nt][1]);
                }
        }
    }
}

// ---------------------------------------------------------------------------
// Kernel: QKV projection. grid (8, 64, 3). z=0: Q split; z=1: K; z=2: V.
// ---------------------------------------------------------------------------
__global__ __launch_bounds__(256) void qkv_gemm()
{
    const int z = blockIdx.z;
    const int row0 = blockIdx.y * 128;       // token
    const int col0 = blockIdx.x * 128;       // out channel
    float acc[64];
    #pragma unroll
    for (int i = 0; i < 64; i++) acc[i] = 0.0f;
    run_gemm<false>(g_Xhi, g_Xlo, CC, g_Wh + (size_t)z * CC * CC, CC,
                    CC, row0, col0, acc);
    const int wid = threadIdx.x >> 5, lane = threadIdx.x & 31;
    const int rbase = row0 + (wid >> 2) * 64 + (lane >> 2);
    const int cbase = col0 + (wid & 3) * 32 + 2 * (lane & 3);
    if (z == 0) {
        #pragma unroll
        for (int mt = 0; mt < 4; mt++)
            #pragma unroll
            for (int nt = 0; nt < 4; nt++) {
                const float* c = acc + (mt * 4 + nt) * 4;
                size_t r = rbase + mt * 16, cc = cbase + nt * 8;
                store_split(g_Qhi, g_Qlo, r * CC + cc, c[0], c[1]);
                store_split(g_Qhi, g_Qlo, (r + 8) * CC + cc, c[2], c[3]);
            }
    } else {
        fp16* o = (z == 1) ? g_Kh : g_Vh;
        #pragma unroll
        for (int mt = 0; mt < 4; mt++)
            #pragma unroll
            for (int nt = 0; nt < 4; nt++) {
                const float* c = acc + (mt * 4 + nt) * 4;
                size_t r = rbase + mt * 16, cc = cbase + nt * 8;
                *(uint32_t*)(o + r * CC + cc) = h2pack(c[0], c[1]);
                *(uint32_t*)(o + (r + 8) * CC + cc) = h2pack(c[2], c[3]);
            }
    }
}

// ---------------------------------------------------------------------------
// Kernel: S = scale * Q K^T, causal tile skip. grid (16, 16, 4)
// ---------------------------------------------------------------------------
__global__ __launch_bounds__(256) void qk_gemm()
{
    const int row0 = blockIdx.y * 128;
    const int col0 = blockIdx.x * 128;
    if (col0 > row0 + 127) return;
    const int b = blockIdx.z;
    const size_t qo = (size_t)b * TT * CC;
    float acc[64];
    #pragma unroll
    for (int i = 0; i < 64; i++) acc[i] = 0.0f;
    run_gemm<false>(g_Qhi + qo, g_Qlo + qo, CC, g_Kh + qo, CC,
                    CC, row0, col0, acc);
    const int wid = threadIdx.x >> 5, lane = threadIdx.x & 31;
    const int rbase = row0 + (wid >> 2) * 64 + (lane >> 2);
    const int cbase = col0 + (wid & 3) * 32 + 2 * (lane & 3);
    float* S = g_S + (size_t)b * TT * TT;
    #pragma unroll
    for (int mt = 0; mt < 4; mt++)
        #pragma unroll
        for (int nt = 0; nt < 4; nt++) {
            const float* c = acc + (mt * 4 + nt) * 4;
            size_t r = rbase + mt * 16, cc = cbase + nt * 8;
            *(float2*)(S + r * TT + cc) = make_float2(c[0] * 0.03125f, c[1] * 0.03125f);
            *(float2*)(S + (r + 8) * TT + cc) = make_float2(c[2] * 0.03125f, c[3] * 0.03125f);
        }
}

// ---------------------------------------------------------------------------
// Kernel: causal softmax + split P to fp16 hi/lo. grid (2048, 4)
// ---------------------------------------------------------------------------
__global__ __launch_bounds__(256) void softmax_split()
{
    const int b = blockIdx.y, t = blockIdx.x;
    float* row = g_S + ((size_t)b * TT + t) * TT;
    fp16* ph = g_Phi + ((size_t)b * TT + t) * TT;
    fp16* pl = g_Plo + ((size_t)b * TT + t) * TT;
    const int n = t + 1;
    const int nend = ((t >> 7) + 1) << 7;
    const int tid = threadIdx.x;
    __shared__ float red[256];

    float m = -1e30f;
    for (int j = tid; j < n; j += 256) m = fmaxf(m, row[j]);
    red[tid] = m; __syncthreads();
    for (int s = 128; s > 0; s >>= 1) {
        if (tid < s) red[tid] = fmaxf(red[tid], red[tid + s]);
        __syncthreads();
    }
    m = red[0]; __syncthreads();

    float sum = 0.0f;
    for (int j = tid; j < n; j += 256) {
        float e = __expf(row[j] - m);
        row[j] = e;
        sum += e;
    }
    red[tid] = sum; __syncthreads();
    for (int s = 128; s > 0; s >>= 1) {
        if (tid < s) red[tid] += red[tid + s];
        __syncthreads();
    }
    const float inv = 1.0f / red[0];

    for (int j = tid; j < n; j += 256) {
        float p = row[j] * inv;
        fp16 h = __float2half_rn(p);
        ph[j] = h;
        pl[j] = __float2half_rn(p - __half2float(h));
    }
    const fp16 z = __float2half_rn(0.0f);
    for (int j = n + tid; j < nend; j += 256) { ph[j] = z; pl[j] = z; }
}

// ---------------------------------------------------------------------------
// Kernel: O = P V (K truncated causally; V [s][n] via trans-B). grid (8,16,4)
// ---------------------------------------------------------------------------
__global__ __launch_bounds__(256) void pv_gemm(float* __restrict__ out)
{
    const int b = blockIdx.z;
    const int row0 = blockIdx.y * 128;     // query tile
    const int col0 = blockIdx.x * 128;     // channel tile
    const size_t po = (size_t)b * TT * TT;
    const size_t vo = (size_t)b * TT * CC;
    float acc[64];
    #pragma unroll
    for (int i = 0; i < 64; i++) acc[i] = 0.0f;
    run_gemm<true>(g_Phi + po, g_Plo + po, TT, g_Vh + vo, CC,
                   row0 + 128, row0, col0, acc);
    const int wid = threadIdx.x >> 5, lane = threadIdx.x & 31;
    const int rbase = row0 + (wid >> 2) * 64 + (lane >> 2);
    const int cbase = col0 + (wid & 3) * 32 + 2 * (lane & 3);
    float* O = out + (size_t)b * TT * CC;
    #pragma unroll
    for (int mt = 0; mt < 4; mt++)
        #pragma unroll
        for (int nt = 0; nt < 4; nt++) {
            const float* c = acc + (mt * 4 + nt) * 4;
            size_t r = rbase + mt * 16, cc = cbase + nt * 8;
            *(float2*)(O + r * CC + cc) = make_float2(c[0], c[1]);
            *(float2*)(O + (r + 8) * CC + cc) = make_float2(c[2], c[3]);
        }
}

// ---------------------------------------------------------------------------
// Kernel: fp32 -> fp16 splits: x -> hi/lo, W -> single limb.
// ---------------------------------------------------------------------------
__global__ __launch_bounds__(256) void convert_all(
    const float* __restrict__ x, const float* __restrict__ wq,
    const float* __restrict__ wk, const float* __restrict__ wv)
{
    const long i = (long)blockIdx.x * 256 + threadIdx.x;
    if (i < 2097152) {
        float4 v = ((const float4*)x)[i];
        fp16 h0 = __float2half_rn(v.x), h1 = __float2half_rn(v.y);
        fp16 h2 = __float2half_rn(v.z), h3 = __float2half_rn(v.w);
        uint2 hw, lw;
        hw.x = h2pack(v.x, v.y); hw.y = h2pack(v.z, v.w);
        lw.x = h2pack(v.x - __half2float(h0), v.y - __half2float(h1));
        lw.y = h2pack(v.z - __half2float(h2), v.w - __half2float(h3));
        ((uint2*)g_Xhi)[i] = hw;
        ((uint2*)g_Xlo)[i] = lw;
    } else {
        long j = i - 2097152;
        int w = (int)(j / 262144);
        size_t off = (size_t)(j - (long)w * 262144);
        const float* src = (w == 0) ? wq : (w == 1) ? wk : wv;
        float4 v = ((const float4*)src)[off];
        uint2 hw;
        hw.x = h2pack(v.x, v.y); hw.y = h2pack(v.z, v.w);
        ((uint2*)(g_Wh + (size_t)w * CC * CC))[off] = hw;
    }
}

// ---------------------------------------------------------------------------
extern "C" void kernel_launch(void* const* d_in, const int* in_sizes, int n_in,
                              void* d_out, int out_size)
{
    const float* x  = (const float*)d_in[0];
    const float* Wq = (const float*)d_in[1];
    const float* Wk = (const float*)d_in[2];
    const float* Wv = (const float*)d_in[3];
    float* out = (float*)d_out;

    cudaFuncSetAttribute(qkv_gemm, cudaFuncAttributeMaxDynamicSharedMemorySize, SMEM_BYTES);
    cudaFuncSetAttribute(qk_gemm,  cudaFuncAttributeMaxDynamicSharedMemorySize, SMEM_BYTES);
    cudaFuncSetAttribute(pv_gemm,  cudaFuncAttributeMaxDynamicSharedMemorySize, SMEM_BYTES);

    convert_all<<<11264, 256>>>(x, Wq, Wk, Wv);
    qkv_gemm<<<dim3(8, 64, 3), 256, SMEM_BYTES>>>();
    qk_gemm<<<dim3(16, 16, BB), 256, SMEM_BYTES>>>();
    softmax_split<<<dim3(TT, BB), 256>>>();
    pv_gemm<<<dim3(8, 16, BB), 256, SMEM_BYTES>>>(out);
}

// round 6
// speedup vs baseline: 5.8540x; 1.6929x over previous
#include <cuda_runtime.h>
#include <cuda_fp16.h>
#include <stdint.h>
#include <math.h>

#define BB 4
#define TT 2048
#define CC 1024
#define NTOK 8192   // BB*TT

typedef __half fp16;

// ---------------- scratch (__device__ globals; allocation-free rule) -------
__device__ __align__(256) fp16 g_Xh[NTOK * CC];
__device__ __align__(256) fp16 g_Wh[3 * CC * CC];
__device__ __align__(256) fp16 g_Qh[NTOK * CC];
__device__ __align__(256) fp16 g_Kh[NTOK * CC];
__device__ __align__(256) fp16 g_Vh[NTOK * CC];      // [token][channel]
__device__ __align__(256) float g_S[(size_t)BB * TT * TT];
__device__ __align__(256) fp16 g_Ph[(size_t)BB * TT * TT];

// ---------------- helpers ---------------------------------------------------
__device__ __forceinline__ uint32_t smem_u32(const void* p) {
    uint32_t a;
    asm("{ .reg .u64 t; cvta.to.shared.u64 t, %1; cvt.u32.u64 %0, t; }" : "=r"(a) : "l"(p));
    return a;
}
__device__ __forceinline__ void cp16(uint32_t s, const void* g) {
    asm volatile("cp.async.cg.shared.global [%0], [%1], 16;" :: "r"(s), "l"(g));
}
#define CP_COMMIT() asm volatile("cp.async.commit_group;" ::: "memory")
#define CP_WAIT2()  asm volatile("cp.async.wait_group 2;" ::: "memory")

__device__ __forceinline__ void ldsm4(uint32_t a, uint32_t& r0, uint32_t& r1,
                                      uint32_t& r2, uint32_t& r3) {
    asm volatile("ldmatrix.sync.aligned.m8n8.x4.shared.b16 {%0,%1,%2,%3}, [%4];"
                 : "=r"(r0), "=r"(r1), "=r"(r2), "=r"(r3) : "r"(a));
}
__device__ __forceinline__ void ldsm4t(uint32_t a, uint32_t& r0, uint32_t& r1,
                                       uint32_t& r2, uint32_t& r3) {
    asm volatile("ldmatrix.sync.aligned.m8n8.x4.trans.shared.b16 {%0,%1,%2,%3}, [%4];"
                 : "=r"(r0), "=r"(r1), "=r"(r2), "=r"(r3) : "r"(a));
}
__device__ __forceinline__ void mma16816(float* c, const uint32_t* a, uint32_t b0, uint32_t b1) {
    asm volatile(
        "mma.sync.aligned.m16n8k16.row.col.f32.f16.f16.f32 "
        "{%0,%1,%2,%3}, {%4,%5,%6,%7}, {%8,%9}, {%0,%1,%2,%3};"
        : "+f"(c[0]), "+f"(c[1]), "+f"(c[2]), "+f"(c[3])
        : "r"(a[0]), "r"(a[1]), "r"(a[2]), "r"(a[3]), "r"(b0), "r"(b1));
}
__device__ __forceinline__ uint32_t h2pack(float a, float b) {
    __half2 h = __floats2half2_rn(a, b);
    return *reinterpret_cast<uint32_t*>(&h);
}

// smem: 4 stages x 2 tiles (A, B) x 18432B = 147456B
#define TILE_B  18432
#define STAGE_B (2 * TILE_B)
#define NSTAGE  4
#define SMEM_BYTES (NSTAGE * STAGE_B)
#define PAD_NT 144   // bytes per 64-elem k-row (128B + 16 pad)
#define PAD_TR 272   // bytes per 128-elem n-row (256B + 16 pad)

extern __shared__ char dsm[];

// ---------------------------------------------------------------------------
// 128x128 tile fp16 GEMM: C = A * B^T(NT) or A * B(TRANSB layout [k][n]).
// ---------------------------------------------------------------------------
template <bool TRANSB>
__device__ __forceinline__ void run_gemm(
    const fp16* __restrict__ A, int lda,
    const fp16* __restrict__ B, int ldb,
    int Ktot, int row0, int col0, float* acc)
{
    const int tid = threadIdx.x;
    const int wid = tid >> 5, lane = tid & 31;
    const int wm = (wid >> 2) * 64, wn = (wid & 3) * 32;
    const uint32_t smem = smem_u32(dsm);
    const int nk = Ktot >> 6;

    auto load_stage = [&](int s, int buf) {
        const int kk0 = s << 6;
        const uint32_t base = smem + buf * STAGE_B;
        #pragma unroll
        for (int i = 0; i < 4; i++) {
            int c = tid + i * 256;                 // 0..1023
            int r = c >> 3, kc = c & 7;
            cp16(base + (uint32_t)r * PAD_NT + kc * 16,
                 A + (size_t)(row0 + r) * lda + kk0 + kc * 8);
            if (!TRANSB) {
                cp16(base + TILE_B + (uint32_t)r * PAD_NT + kc * 16,
                     B + (size_t)(col0 + r) * ldb + kk0 + kc * 8);
            } else {
                int rt = c >> 4, nc = c & 15;
                cp16(base + TILE_B + (uint32_t)rt * PAD_TR + nc * 16,
                     B + (size_t)(kk0 + rt) * ldb + col0 + nc * 8);
            }
        }
    };

    load_stage(0, 0); CP_COMMIT();
    if (nk > 1) load_stage(1, 1);
    CP_COMMIT();
    if (nk > 2) load_stage(2, 2);
    CP_COMMIT();

    for (int s = 0; s < nk; s++) {
        const int buf = s & 3;
        const uint32_t base = smem + buf * STAGE_B;
        CP_WAIT2();
        __syncthreads();
        if (s + 3 < nk) load_stage(s + 3, (s + 3) & 3);
        CP_COMMIT();

        #pragma unroll
        for (int kk = 0; kk < 4; kk++) {
            uint32_t aF[4][4];
            #pragma unroll
            for (int mt = 0; mt < 4; mt++) {
                uint32_t a = base + (uint32_t)(wm + mt * 16 + (lane & 7) + ((lane >> 3) & 1) * 8) * PAD_NT
                           + kk * 32 + ((lane >> 4) & 1) * 16;
                ldsm4(a, aF[mt][0], aF[mt][1], aF[mt][2], aF[mt][3]);
            }
            uint32_t bF[4][2];
            #pragma unroll
            for (int pr = 0; pr < 2; pr++) {
                uint32_t r0, r1, r2, r3;
                if (!TRANSB) {
                    uint32_t a = base + TILE_B
                               + (uint32_t)(wn + pr * 16 + (lane & 7) + ((lane >> 3) & 1) * 8) * PAD_NT
                               + kk * 32 + ((lane >> 4) & 1) * 16;
                    ldsm4(a, r0, r1, r2, r3);
                } else {
                    uint32_t a = base + TILE_B
                               + (uint32_t)(kk * 16 + (lane & 7) + ((lane >> 4) & 1) * 8) * PAD_TR
                               + (wn + pr * 16) * 2 + ((lane >> 3) & 1) * 16;
                    ldsm4t(a, r0, r1, r2, r3);
                }
                bF[pr * 2 + 0][0] = r0; bF[pr * 2 + 0][1] = r2;
                bF[pr * 2 + 1][0] = r1; bF[pr * 2 + 1][1] = r3;
            }
            #pragma unroll
            for (int mt = 0; mt < 4; mt++)
                #pragma unroll
                for (int nt = 0; nt < 4; nt++)
                    mma16816(acc + (mt * 4 + nt) * 4, aF[mt], bF[nt][0], bF[nt][1]);
        }
    }
}

// ---------------------------------------------------------------------------
// Kernel: QKV projection. grid (8, 64, 3). z=0: Q, z=1: K, z=2: V.
// ---------------------------------------------------------------------------
__global__ __launch_bounds__(256) void qkv_gemm()
{
    const int z = blockIdx.z;
    const int row0 = blockIdx.y * 128;       // token
    const int col0 = blockIdx.x * 128;       // out channel
    float acc[64];
    #pragma unroll
    for (int i = 0; i < 64; i++) acc[i] = 0.0f;
    run_gemm<false>(g_Xh, CC, g_Wh + (size_t)z * CC * CC, CC,
                    CC, row0, col0, acc);
    fp16* o = (z == 0) ? g_Qh : (z == 1) ? g_Kh : g_Vh;
    const int wid = threadIdx.x >> 5, lane = threadIdx.x & 31;
    const int rbase = row0 + (wid >> 2) * 64 + (lane >> 2);
    const int cbase = col0 + (wid & 3) * 32 + 2 * (lane & 3);
    #pragma unroll
    for (int mt = 0; mt < 4; mt++)
        #pragma unroll
        for (int nt = 0; nt < 4; nt++) {
            const float* c = acc + (mt * 4 + nt) * 4;
            size_t r = rbase + mt * 16, cc = cbase + nt * 8;
            *(uint32_t*)(o + r * CC + cc) = h2pack(c[0], c[1]);
            *(uint32_t*)(o + (r + 8) * CC + cc) = h2pack(c[2], c[3]);
        }
}

// ---------------------------------------------------------------------------
// Kernel: S = scale * Q K^T, causal tile skip. grid (16, 16, 4)
// ---------------------------------------------------------------------------
__global__ __launch_bounds__(256) void qk_gemm()
{
    const int row0 = blockIdx.y * 128;
    const int col0 = blockIdx.x * 128;
    if (col0 > row0 + 127) return;
    const int b = blockIdx.z;
    const size_t qo = (size_t)b * TT * CC;
    float acc[64];
    #pragma unroll
    for (int i = 0; i < 64; i++) acc[i] = 0.0f;
    run_gemm<false>(g_Qh + qo, CC, g_Kh + qo, CC, CC, row0, col0, acc);
    const int wid = threadIdx.x >> 5, lane = threadIdx.x & 31;
    const int rbase = row0 + (wid >> 2) * 64 + (lane >> 2);
    const int cbase = col0 + (wid & 3) * 32 + 2 * (lane & 3);
    float* S = g_S + (size_t)b * TT * TT;
    #pragma unroll
    for (int mt = 0; mt < 4; mt++)
        #pragma unroll
        for (int nt = 0; nt < 4; nt++) {
            const float* c = acc + (mt * 4 + nt) * 4;
            size_t r = rbase + mt * 16, cc = cbase + nt * 8;
            *(float2*)(S + r * TT + cc) = make_float2(c[0] * 0.03125f, c[1] * 0.03125f);
            *(float2*)(S + (r + 8) * TT + cc) = make_float2(c[2] * 0.03125f, c[3] * 0.03125f);
        }
}

// ---------------------------------------------------------------------------
// Kernel: causal softmax -> fp16 P. grid (2048, 4)
// ---------------------------------------------------------------------------
__global__ __launch_bounds__(256) void softmax_k()
{
    const int b = blockIdx.y, t = blockIdx.x;
    float* row = g_S + ((size_t)b * TT + t) * TT;
    fp16* ph = g_Ph + ((size_t)b * TT + t) * TT;
    const int n = t + 1;
    const int nend = ((t >> 7) + 1) << 7;
    const int tid = threadIdx.x;
    __shared__ float red[256];

    float m = -1e30f;
    for (int j = tid; j < n; j += 256) m = fmaxf(m, row[j]);
    red[tid] = m; __syncthreads();
    for (int s = 128; s > 0; s >>= 1) {
        if (tid < s) red[tid] = fmaxf(red[tid], red[tid + s]);
        __syncthreads();
    }
    m = red[0]; __syncthreads();

    float sum = 0.0f;
    for (int j = tid; j < n; j += 256) {
        float e = __expf(row[j] - m);
        row[j] = e;
        sum += e;
    }
    red[tid] = sum; __syncthreads();
    for (int s = 128; s > 0; s >>= 1) {
        if (tid < s) red[tid] += red[tid + s];
        __syncthreads();
    }
    const float inv = 1.0f / red[0];

    for (int j = tid; j < n; j += 256)
        ph[j] = __float2half_rn(row[j] * inv);
    const fp16 z = __float2half_rn(0.0f);
    for (int j = n + tid; j < nend; j += 256) ph[j] = z;
}

// ---------------------------------------------------------------------------
// Kernel: O = P V (K truncated causally; V [s][n] via trans-B). grid (8,16,4)
// ---------------------------------------------------------------------------
__global__ __launch_bounds__(256) void pv_gemm(float* __restrict__ out)
{
    const int b = blockIdx.z;
    const int row0 = blockIdx.y * 128;     // query tile
    const int col0 = blockIdx.x * 128;     // channel tile
    const size_t po = (size_t)b * TT * TT;
    const size_t vo = (size_t)b * TT * CC;
    float acc[64];
    #pragma unroll
    for (int i = 0; i < 64; i++) acc[i] = 0.0f;
    run_gemm<true>(g_Ph + po, TT, g_Vh + vo, CC, row0 + 128, row0, col0, acc);
    const int wid = threadIdx.x >> 5, lane = threadIdx.x & 31;
    const int rbase = row0 + (wid >> 2) * 64 + (lane >> 2);
    const int cbase = col0 + (wid & 3) * 32 + 2 * (lane & 3);
    float* O = out + (size_t)b * TT * CC;
    #pragma unroll
    for (int mt = 0; mt < 4; mt++)
        #pragma unroll
        for (int nt = 0; nt < 4; nt++) {
            const float* c = acc + (mt * 4 + nt) * 4;
            size_t r = rbase + mt * 16, cc = cbase + nt * 8;
            *(float2*)(O + r * CC + cc) = make_float2(c[0], c[1]);
            *(float2*)(O + (r + 8) * CC + cc) = make_float2(c[2], c[3]);
        }
}

// ---------------------------------------------------------------------------
// Kernel: fp32 -> fp16 for x and the 3 weight matrices.
// ---------------------------------------------------------------------------
__global__ __launch_bounds__(256) void convert_all(
    const float* __restrict__ x, const float* __restrict__ wq,
    const float* __restrict__ wk, const float* __restrict__ wv)
{
    const long i = (long)blockIdx.x * 256 + threadIdx.x;
    const float* src; fp16* dst; size_t off;
    if (i < 2097152) {
        src = x; dst = g_Xh; off = (size_t)i;
    } else {
        long j = i - 2097152;
        int w = (int)(j / 262144);
        off = (size_t)(j - (long)w * 262144);
        src = (w == 0) ? wq : (w == 1) ? wk : wv;
        dst = g_Wh + (size_t)w * CC * CC;
    }
    float4 v = ((const float4*)src)[off];
    uint2 hw;
    hw.x = h2pack(v.x, v.y); hw.y = h2pack(v.z, v.w);
    ((uint2*)dst)[off] = hw;
}

// ---------------------------------------------------------------------------
extern "C" void kernel_launch(void* const* d_in, const int* in_sizes, int n_in,
                              void* d_out, int out_size)
{
    const float* x  = (const float*)d_in[0];
    const float* Wq = (const float*)d_in[1];
    const float* Wk = (const float*)d_in[2];
    const float* Wv = (const float*)d_in[3];
    float* out = (float*)d_out;

    cudaFuncSetAttribute(qkv_gemm, cudaFuncAttributeMaxDynamicSharedMemorySize, SMEM_BYTES);
    cudaFuncSetAttribute(qk_gemm,  cudaFuncAttributeMaxDynamicSharedMemorySize, SMEM_BYTES);
    cudaFuncSetAttribute(pv_gemm,  cudaFuncAttributeMaxDynamicSharedMemorySize, SMEM_BYTES);

    convert_all<<<11264, 256>>>(x, Wq, Wk, Wv);
    qkv_gemm<<<dim3(8, 64, 3), 256, SMEM_BYTES>>>();
    qk_gemm<<<dim3(16, 16, BB), 256, SMEM_BYTES>>>();
    softmax_k<<<dim3(TT, BB), 256>>>();
    pv_gemm<<<dim3(8, 16, BB), 256, SMEM_BYTES>>>(out);
}

// round 7
// speedup vs baseline: 6.3177x; 1.0792x over previous
#include <cuda_runtime.h>
#include <cuda_fp16.h>
#include <stdint.h>
#include <math.h>

#define BB 4
#define TT 2048
#define CC 1024
#define NTOK 8192   // BB*TT

typedef __half fp16;

// ---------------- scratch (__device__ globals; allocation-free rule) -------
__device__ __align__(256) fp16 g_Xh [NTOK * CC];
__device__ __align__(256) fp16 g_Wk [CC * CC];
__device__ __align__(256) fp16 g_Wv [CC * CC];
__device__ __align__(256) fp16 g_WqT[CC * CC];       // Wq transposed [c][d]
__device__ __align__(256) fp16 g_M  [CC * CC];       // Wq^T Wk, [c][c']
__device__ __align__(256) fp16 g_Gh [NTOK * CC];     // X M
__device__ __align__(256) fp16 g_Vh [NTOK * CC];     // [token][channel]
__device__ __align__(256) float g_S[(size_t)BB * TT * TT];
__device__ __align__(256) fp16 g_Ph[(size_t)BB * TT * TT];

// ---------------- helpers ---------------------------------------------------
__device__ __forceinline__ uint32_t smem_u32(const void* p) {
    uint32_t a;
    asm("{ .reg .u64 t; cvta.to.shared.u64 t, %1; cvt.u32.u64 %0, t; }" : "=r"(a) : "l"(p));
    return a;
}
__device__ __forceinline__ void cp16(uint32_t s, const void* g) {
    asm volatile("cp.async.cg.shared.global [%0], [%1], 16;" :: "r"(s), "l"(g));
}
#define CP_COMMIT() asm volatile("cp.async.commit_group;" ::: "memory")
#define CP_WAIT2()  asm volatile("cp.async.wait_group 2;" ::: "memory")

__device__ __forceinline__ void ldsm4(uint32_t a, uint32_t& r0, uint32_t& r1,
                                      uint32_t& r2, uint32_t& r3) {
    asm volatile("ldmatrix.sync.aligned.m8n8.x4.shared.b16 {%0,%1,%2,%3}, [%4];"
                 : "=r"(r0), "=r"(r1), "=r"(r2), "=r"(r3) : "r"(a));
}
__device__ __forceinline__ void ldsm4t(uint32_t a, uint32_t& r0, uint32_t& r1,
                                       uint32_t& r2, uint32_t& r3) {
    asm volatile("ldmatrix.sync.aligned.m8n8.x4.trans.shared.b16 {%0,%1,%2,%3}, [%4];"
                 : "=r"(r0), "=r"(r1), "=r"(r2), "=r"(r3) : "r"(a));
}
__device__ __forceinline__ void mma16816(float* c, const uint32_t* a, uint32_t b0, uint32_t b1) {
    asm volatile(
        "mma.sync.aligned.m16n8k16.row.col.f32.f16.f16.f32 "
        "{%0,%1,%2,%3}, {%4,%5,%6,%7}, {%8,%9}, {%0,%1,%2,%3};"
        : "+f"(c[0]), "+f"(c[1]), "+f"(c[2]), "+f"(c[3])
        : "r"(a[0]), "r"(a[1]), "r"(a[2]), "r"(a[3]), "r"(b0), "r"(b1));
}
__device__ __forceinline__ uint32_t h2pack(float a, float b) {
    __half2 h = __floats2half2_rn(a, b);
    return *reinterpret_cast<uint32_t*>(&h);
}

// smem: 4 stages x 2 tiles (A, B) x 18432B = 147456B
#define TILE_B  18432
#define STAGE_B (2 * TILE_B)
#define NSTAGE  4
#define SMEM_BYTES (NSTAGE * STAGE_B)
#define PAD_NT 144   // bytes per 64-elem k-row (128B + 16 pad)
#define PAD_TR 272   // bytes per 128-elem n-row (256B + 16 pad)

extern __shared__ char dsm[];

// ---------------------------------------------------------------------------
// 128x128 tile fp16 GEMM: C = A * B^T(NT, B [n][k]) or A * B(TRANSB, B [k][n]).
// ---------------------------------------------------------------------------
template <bool TRANSB>
__device__ __forceinline__ void run_gemm(
    const fp16* __restrict__ A, int lda,
    const fp16* __restrict__ B, int ldb,
    int Ktot, int row0, int col0, float* acc)
{
    const int tid = threadIdx.x;
    const int wid = tid >> 5, lane = tid & 31;
    const int wm = (wid >> 2) * 64, wn = (wid & 3) * 32;
    const uint32_t smem = smem_u32(dsm);
    const int nk = Ktot >> 6;

    auto load_stage = [&](int s, int buf) {
        const int kk0 = s << 6;
        const uint32_t base = smem + buf * STAGE_B;
        #pragma unroll
        for (int i = 0; i < 4; i++) {
            int c = tid + i * 256;                 // 0..1023
            int r = c >> 3, kc = c & 7;
            cp16(base + (uint32_t)r * PAD_NT + kc * 16,
                 A + (size_t)(row0 + r) * lda + kk0 + kc * 8);
            if (!TRANSB) {
                cp16(base + TILE_B + (uint32_t)r * PAD_NT + kc * 16,
                     B + (size_t)(col0 + r) * ldb + kk0 + kc * 8);
            } else {
                int rt = c >> 4, nc = c & 15;
                cp16(base + TILE_B + (uint32_t)rt * PAD_TR + nc * 16,
                     B + (size_t)(kk0 + rt) * ldb + col0 + nc * 8);
            }
        }
    };

    load_stage(0, 0); CP_COMMIT();
    if (nk > 1) load_stage(1, 1);
    CP_COMMIT();
    if (nk > 2) load_stage(2, 2);
    CP_COMMIT();

    for (int s = 0; s < nk; s++) {
        const int buf = s & 3;
        const uint32_t base = smem + buf * STAGE_B;
        CP_WAIT2();
        __syncthreads();
        if (s + 3 < nk) load_stage(s + 3, (s + 3) & 3);
        CP_COMMIT();

        #pragma unroll
        for (int kk = 0; kk < 4; kk++) {
            uint32_t aF[4][4];
            #pragma unroll
            for (int mt = 0; mt < 4; mt++) {
                uint32_t a = base + (uint32_t)(wm + mt * 16 + (lane & 7) + ((lane >> 3) & 1) * 8) * PAD_NT
                           + kk * 32 + ((lane >> 4) & 1) * 16;
                ldsm4(a, aF[mt][0], aF[mt][1], aF[mt][2], aF[mt][3]);
            }
            uint32_t bF[4][2];
            #pragma unroll
            for (int pr = 0; pr < 2; pr++) {
                uint32_t r0, r1, r2, r3;
                if (!TRANSB) {
                    uint32_t a = base + TILE_B
                               + (uint32_t)(wn + pr * 16 + (lane & 7) + ((lane >> 3) & 1) * 8) * PAD_NT
                               + kk * 32 + ((lane >> 4) & 1) * 16;
                    ldsm4(a, r0, r1, r2, r3);
                } else {
                    uint32_t a = base + TILE_B
                               + (uint32_t)(kk * 16 + (lane & 7) + ((lane >> 4) & 1) * 8) * PAD_TR
                               + (wn + pr * 16) * 2 + ((lane >> 3) & 1) * 16;
                    ldsm4t(a, r0, r1, r2, r3);
                }
                bF[pr * 2 + 0][0] = r0; bF[pr * 2 + 0][1] = r2;
                bF[pr * 2 + 1][0] = r1; bF[pr * 2 + 1][1] = r3;
            }
            #pragma unroll
            for (int mt = 0; mt < 4; mt++)
                #pragma unroll
                for (int nt = 0; nt < 4; nt++)
                    mma16816(acc + (mt * 4 + nt) * 4, aF[mt], bF[nt][0], bF[nt][1]);
        }
    }
}

// Common fp16 epilogue: write 128x128 tile of acc to o[r][c], ld=CC.
__device__ __forceinline__ void epilogue_h(fp16* o, int row0, int col0, const float* acc)
{
    const int wid = threadIdx.x >> 5, lane = threadIdx.x & 31;
    const int rbase = row0 + (wid >> 2) * 64 + (lane >> 2);
    const int cbase = col0 + (wid & 3) * 32 + 2 * (lane & 3);
    #pragma unroll
    for (int mt = 0; mt < 4; mt++)
        #pragma unroll
        for (int nt = 0; nt < 4; nt++) {
            const float* c = acc + (mt * 4 + nt) * 4;
            size_t r = rbase + mt * 16, cc = cbase + nt * 8;
            *(uint32_t*)(o + r * CC + cc) = h2pack(c[0], c[1]);
            *(uint32_t*)(o + (r + 8) * CC + cc) = h2pack(c[2], c[3]);
        }
}

// ---------------------------------------------------------------------------
// Kernel: M = Wq^T Wk. grid (8, 8). A = WqT [c][d] (NT), B = Wk [d][c'] (TRANSB)
// ---------------------------------------------------------------------------
__global__ __launch_bounds__(256) void m_gemm()
{
    const int row0 = blockIdx.y * 128;   // c
    const int col0 = blockIdx.x * 128;   // c'
    float acc[64];
    #pragma unroll
    for (int i = 0; i < 64; i++) acc[i] = 0.0f;
    run_gemm<true>(g_WqT, CC, g_Wk, CC, CC, row0, col0, acc);
    epilogue_h(g_M, row0, col0, acc);
}

// ---------------------------------------------------------------------------
// Kernel: G = X M. grid (8, 64). A = X (NT-A), B = M [c][c'] (TRANSB)
// ---------------------------------------------------------------------------
__global__ __launch_bounds__(256) void g_gemm()
{
    const int row0 = blockIdx.y * 128;   // token
    const int col0 = blockIdx.x * 128;   // c'
    float acc[64];
    #pragma unroll
    for (int i = 0; i < 64; i++) acc[i] = 0.0f;
    run_gemm<true>(g_Xh, CC, g_M, CC, CC, row0, col0, acc);
    epilogue_h(g_Gh, row0, col0, acc);
}

// ---------------------------------------------------------------------------
// Kernel: V = X Wv^T. grid (8, 64). NT.
// ---------------------------------------------------------------------------
__global__ __launch_bounds__(256) void v_gemm()
{
    const int row0 = blockIdx.y * 128;
    const int col0 = blockIdx.x * 128;
    float acc[64];
    #pragma unroll
    for (int i = 0; i < 64; i++) acc[i] = 0.0f;
    run_gemm<false>(g_Xh, CC, g_Wv, CC, CC, row0, col0, acc);
    epilogue_h(g_Vh, row0, col0, acc);
}

// ---------------------------------------------------------------------------
// Kernel: S = scale * G X^T, causal tile skip. grid (16, 16, 4). NT.
// ---------------------------------------------------------------------------
__global__ __launch_bounds__(256) void qk_gemm()
{
    const int row0 = blockIdx.y * 128;
    const int col0 = blockIdx.x * 128;
    if (col0 > row0 + 127) return;
    const int b = blockIdx.z;
    const size_t xo = (size_t)b * TT * CC;
    float acc[64];
    #pragma unroll
    for (int i = 0; i < 64; i++) acc[i] = 0.0f;
    run_gemm<false>(g_Gh + xo, CC, g_Xh + xo, CC, CC, row0, col0, acc);
    const int wid = threadIdx.x >> 5, lane = threadIdx.x & 31;
    const int rbase = row0 + (wid >> 2) * 64 + (lane >> 2);
    const int cbase = col0 + (wid & 3) * 32 + 2 * (lane & 3);
    float* S = g_S + (size_t)b * TT * TT;
    #pragma unroll
    for (int mt = 0; mt < 4; mt++)
        #pragma unroll
        for (int nt = 0; nt < 4; nt++) {
            const float* c = acc + (mt * 4 + nt) * 4;
            size_t r = rbase + mt * 16, cc = cbase + nt * 8;
            *(float2*)(S + r * TT + cc) = make_float2(c[0] * 0.03125f, c[1] * 0.03125f);
            *(float2*)(S + (r + 8) * TT + cc) = make_float2(c[2] * 0.03125f, c[3] * 0.03125f);
        }
}

// ---------------------------------------------------------------------------
// Kernel: causal softmax -> fp16 P. grid (2048, 4). Single global read,
// row cached in registers (<= 8 elems/thread).
// ---------------------------------------------------------------------------
__global__ __launch_bounds__(256) void softmax_k()
{
    const int b = blockIdx.y, t = blockIdx.x;
    const float* row = g_S + ((size_t)b * TT + t) * TT;
    fp16* ph = g_Ph + ((size_t)b * TT + t) * TT;
    const int n = t + 1;
    const int nend = ((t >> 7) + 1) << 7;
    const int tid = threadIdx.x;
    const int lane = tid & 31, wrp = tid >> 5;
    __shared__ float red[8];

    float v[8];
    int cnt = 0;
    float m = -1e30f;
    for (int j = tid; j < n; j += 256) {
        float x = row[j];
        v[cnt++] = x;
        m = fmaxf(m, x);
    }
    #pragma unroll
    for (int o = 16; o > 0; o >>= 1)
        m = fmaxf(m, __shfl_xor_sync(0xffffffffu, m, o));
    if (lane == 0) red[wrp] = m;
    __syncthreads();
    m = red[0];
    #pragma unroll
    for (int w = 1; w < 8; w++) m = fmaxf(m, red[w]);
    __syncthreads();

    float sum = 0.0f;
    #pragma unroll
    for (int c = 0; c < 8; c++)
        if (c < cnt) {
            float e = __expf(v[c] - m);
            v[c] = e;
            sum += e;
        }
    #pragma unroll
    for (int o = 16; o > 0; o >>= 1)
        sum += __shfl_xor_sync(0xffffffffu, sum, o);
    if (lane == 0) red[wrp] = sum;
    __syncthreads();
    sum = red[0];
    #pragma unroll
    for (int w = 1; w < 8; w++) sum += red[w];
    const float inv = 1.0f / sum;

    int c = 0;
    for (int j = tid; j < n; j += 256)
        ph[j] = __float2half_rn(v[c++] * inv);
    const fp16 z = __float2half_rn(0.0f);
    for (int j = n + tid; j < nend; j += 256) ph[j] = z;
}

// ---------------------------------------------------------------------------
// Kernel: O = P V (K truncated causally; V [s][n] via trans-B). grid (8,16,4)
// ---------------------------------------------------------------------------
__global__ __launch_bounds__(256) void pv_gemm(float* __restrict__ out)
{
    const int b = blockIdx.z;
    const int row0 = blockIdx.y * 128;     // query tile
    const int col0 = blockIdx.x * 128;     // channel tile
    const size_t po = (size_t)b * TT * TT;
    const size_t vo = (size_t)b * TT * CC;
    float acc[64];
    #pragma unroll
    for (int i = 0; i < 64; i++) acc[i] = 0.0f;
    run_gemm<true>(g_Ph + po, TT, g_Vh + vo, CC, row0 + 128, row0, col0, acc);
    const int wid = threadIdx.x >> 5, lane = threadIdx.x & 31;
    const int rbase = row0 + (wid >> 2) * 64 + (lane >> 2);
    const int cbase = col0 + (wid & 3) * 32 + 2 * (lane & 3);
    float* O = out + (size_t)b * TT * CC;
    #pragma unroll
    for (int mt = 0; mt < 4; mt++)
        #pragma unroll
        for (int nt = 0; nt < 4; nt++) {
            const float* c = acc + (mt * 4 + nt) * 4;
            size_t r = rbase + mt * 16, cc = cbase + nt * 8;
            *(float2*)(O + r * CC + cc) = make_float2(c[0], c[1]);
            *(float2*)(O + (r + 8) * CC + cc) = make_float2(c[2], c[3]);
        }
}

// ---------------------------------------------------------------------------
// Kernel: fp32 -> fp16 for x, Wk, Wv. (float4 granularity)
// ---------------------------------------------------------------------------
__global__ __launch_bounds__(256) void convert_all(
    const float* __restrict__ x, const float* __restrict__ wk,
    const float* __restrict__ wv)
{
    const long i = (long)blockIdx.x * 256 + threadIdx.x;
    const float* src; fp16* dst; size_t off;
    if (i < 2097152) {
        src = x; dst = g_Xh; off = (size_t)i;
    } else {
        long j = i - 2097152;
        int w = (int)(j / 262144);
        off = (size_t)(j - (long)w * 262144);
        src = (w == 0) ? wk : wv;
        dst = (w == 0) ? g_Wk : g_Wv;
    }
    float4 v = ((const float4*)src)[off];
    uint2 hw;
    hw.x = h2pack(v.x, v.y); hw.y = h2pack(v.z, v.w);
    ((uint2*)dst)[off] = hw;
}

// ---------------------------------------------------------------------------
// Kernel: WqT[c][d] = fp16(Wq[d][c]). grid (32, 32), 256 thr (32x8), smem tile.
// ---------------------------------------------------------------------------
__global__ __launch_bounds__(256) void transpose_wq(const float* __restrict__ wq)
{
    __shared__ float tbuf[32][33];
    const int tx = threadIdx.x & 31, ty = threadIdx.x >> 5;
    const int d0 = blockIdx.y * 32, c0 = blockIdx.x * 32;
    #pragma unroll
    for (int i = 0; i < 4; i++)
        tbuf[ty + i * 8][tx] = wq[(size_t)(d0 + ty + i * 8) * CC + c0 + tx];
    __syncthreads();
    #pragma unroll
    for (int i = 0; i < 4; i++)
        g_WqT[(size_t)(c0 + ty + i * 8) * CC + d0 + tx] =
            __float2half_rn(tbuf[tx][ty + i * 8]);
}

// ---------------------------------------------------------------------------
extern "C" void kernel_launch(void* const* d_in, const int* in_sizes, int n_in,
                              void* d_out, int out_size)
{
    const float* x  = (const float*)d_in[0];
    const float* Wq = (const float*)d_in[1];
    const float* Wk = (const float*)d_in[2];
    const float* Wv = (const float*)d_in[3];
    float* out = (float*)d_out;

    cudaFuncSetAttribute(m_gemm,  cudaFuncAttributeMaxDynamicSharedMemorySize, SMEM_BYTES);
    cudaFuncSetAttribute(g_gemm,  cudaFuncAttributeMaxDynamicSharedMemorySize, SMEM_BYTES);
    cudaFuncSetAttribute(v_gemm,  cudaFuncAttributeMaxDynamicSharedMemorySize, SMEM_BYTES);
    cudaFuncSetAttribute(qk_gemm, cudaFuncAttributeMaxDynamicSharedMemorySize, SMEM_BYTES);
    cudaFuncSetAttribute(pv_gemm, cudaFuncAttributeMaxDynamicSharedMemorySize, SMEM_BYTES);

    convert_all<<<10240, 256>>>(x, Wk, Wv);
    transpose_wq<<<dim3(32, 32), 256>>>(Wq);
    m_gemm<<<dim3(8, 8), 256, SMEM_BYTES>>>();
    g_gemm<<<dim3(8, 64), 256, SMEM_BYTES>>>();
    v_gemm<<<dim3(8, 64), 256, SMEM_BYTES>>>();
    qk_gemm<<<dim3(16, 16, BB), 256, SMEM_BYTES>>>();
    softmax_k<<<dim3(TT, BB), 256>>>();
    pv_gemm<<<dim3(8, 16, BB), 256, SMEM_BYTES>>>(out);
}

// round 8
// speedup vs baseline: 6.9351x; 1.0977x over previous
#include <cuda_runtime.h>
#include <cuda_fp16.h>
#include <stdint.h>
#include <math.h>

#define BB 4
#define TT 2048
#define CC 1024
#define NTOK 8192   // BB*TT

typedef __half fp16;

// ---------------- scratch (__device__ globals; allocation-free rule) -------
__device__ __align__(256) fp16 g_Xh [NTOK * CC];
__device__ __align__(256) fp16 g_Wk [CC * CC];
__device__ __align__(256) fp16 g_Wv [CC * CC];
__device__ __align__(256) fp16 g_WqT[CC * CC];       // Wq transposed [c][d]
__device__ __align__(256) fp16 g_M  [CC * CC];       // Wq^T Wk, [c][c']
__device__ __align__(256) fp16 g_Gh [NTOK * CC];     // X M
__device__ __align__(256) fp16 g_Vh [NTOK * CC];     // [token][channel]
__device__ __align__(256) float g_S[(size_t)BB * TT * TT];
__device__ __align__(256) fp16 g_Ph[(size_t)BB * TT * TT];

// ---------------- helpers ---------------------------------------------------
__device__ __forceinline__ uint32_t smem_u32(const void* p) {
    uint32_t a;
    asm("{ .reg .u64 t; cvta.to.shared.u64 t, %1; cvt.u32.u64 %0, t; }" : "=r"(a) : "l"(p));
    return a;
}
__device__ __forceinline__ void cp16(uint32_t s, const void* g) {
    asm volatile("cp.async.cg.shared.global [%0], [%1], 16;" :: "r"(s), "l"(g));
}
#define CP_COMMIT() asm volatile("cp.async.commit_group;" ::: "memory")
#define CP_WAIT1()  asm volatile("cp.async.wait_group 1;" ::: "memory")

__device__ __forceinline__ void ldsm4(uint32_t a, uint32_t& r0, uint32_t& r1,
                                      uint32_t& r2, uint32_t& r3) {
    asm volatile("ldmatrix.sync.aligned.m8n8.x4.shared.b16 {%0,%1,%2,%3}, [%4];"
                 : "=r"(r0), "=r"(r1), "=r"(r2), "=r"(r3) : "r"(a));
}
__device__ __forceinline__ void ldsm4t(uint32_t a, uint32_t& r0, uint32_t& r1,
                                       uint32_t& r2, uint32_t& r3) {
    asm volatile("ldmatrix.sync.aligned.m8n8.x4.trans.shared.b16 {%0,%1,%2,%3}, [%4];"
                 : "=r"(r0), "=r"(r1), "=r"(r2), "=r"(r3) : "r"(a));
}
__device__ __forceinline__ void mma16816(float* c, const uint32_t* a, uint32_t b0, uint32_t b1) {
    asm volatile(
        "mma.sync.aligned.m16n8k16.row.col.f32.f16.f16.f32 "
        "{%0,%1,%2,%3}, {%4,%5,%6,%7}, {%8,%9}, {%0,%1,%2,%3};"
        : "+f"(c[0]), "+f"(c[1]), "+f"(c[2]), "+f"(c[3])
        : "r"(a[0]), "r"(a[1]), "r"(a[2]), "r"(a[3]), "r"(b0), "r"(b1));
}
__device__ __forceinline__ uint32_t h2pack(float a, float b) {
    __half2 h = __floats2half2_rn(a, b);
    return *reinterpret_cast<uint32_t*>(&h);
}

// smem: 3 stages x 2 tiles (A, B) x 18432B = 110592B  -> 2 CTAs/SM
#define TILE_B  18432
#define STAGE_B (2 * TILE_B)
#define NSTAGE  3
#define SMEM_BYTES (NSTAGE * STAGE_B)
#define PAD_NT 144   // bytes per 64-elem k-row (128B + 16 pad)
#define PAD_TR 272   // bytes per 128-elem n-row (256B + 16 pad)

extern __shared__ char dsm[];

// ---------------------------------------------------------------------------
// 128x128 tile fp16 GEMM: C = A * B^T(NT, B [n][k]) or A * B(TRANSB, B [k][n]).
// 3-stage cp.async pipeline, 2 CTAs/SM.
// ---------------------------------------------------------------------------
template <bool TRANSB>
__device__ __forceinline__ void run_gemm(
    const fp16* __restrict__ A, int lda,
    const fp16* __restrict__ B, int ldb,
    int Ktot, int row0, int col0, float* acc)
{
    const int tid = threadIdx.x;
    const int wid = tid >> 5, lane = tid & 31;
    const int wm = (wid >> 2) * 64, wn = (wid & 3) * 32;
    const uint32_t smem = smem_u32(dsm);
    const int nk = Ktot >> 6;

    auto load_stage = [&](int s, int buf) {
        const int kk0 = s << 6;
        const uint32_t base = smem + buf * STAGE_B;
        #pragma unroll
        for (int i = 0; i < 4; i++) {
            int c = tid + i * 256;                 // 0..1023
            int r = c >> 3, kc = c & 7;
            cp16(base + (uint32_t)r * PAD_NT + kc * 16,
                 A + (size_t)(row0 + r) * lda + kk0 + kc * 8);
            if (!TRANSB) {
                cp16(base + TILE_B + (uint32_t)r * PAD_NT + kc * 16,
                     B + (size_t)(col0 + r) * ldb + kk0 + kc * 8);
            } else {
                int rt = c >> 4, nc = c & 15;
                cp16(base + TILE_B + (uint32_t)rt * PAD_TR + nc * 16,
                     B + (size_t)(kk0 + rt) * ldb + col0 + nc * 8);
            }
        }
    };

    load_stage(0, 0); CP_COMMIT();
    if (nk > 1) load_stage(1, 1);
    CP_COMMIT();

    for (int s = 0; s < nk; s++) {
        const int buf = s % 3;
        const uint32_t base = smem + buf * STAGE_B;
        CP_WAIT1();
        __syncthreads();
        if (s + 2 < nk) load_stage(s + 2, (s + 2) % 3);
        CP_COMMIT();

        #pragma unroll
        for (int kk = 0; kk < 4; kk++) {
            uint32_t aF[4][4];
            #pragma unroll
            for (int mt = 0; mt < 4; mt++) {
                uint32_t a = base + (uint32_t)(wm + mt * 16 + (lane & 7) + ((lane >> 3) & 1) * 8) * PAD_NT
                           + kk * 32 + ((lane >> 4) & 1) * 16;
                ldsm4(a, aF[mt][0], aF[mt][1], aF[mt][2], aF[mt][3]);
            }
            uint32_t bF[4][2];
            #pragma unroll
            for (int pr = 0; pr < 2; pr++) {
                uint32_t r0, r1, r2, r3;
                if (!TRANSB) {
                    uint32_t a = base + TILE_B
                               + (uint32_t)(wn + pr * 16 + (lane & 7) + ((lane >> 3) & 1) * 8) * PAD_NT
                               + kk * 32 + ((lane >> 4) & 1) * 16;
                    ldsm4(a, r0, r1, r2, r3);
                } else {
                    uint32_t a = base + TILE_B
                               + (uint32_t)(kk * 16 + (lane & 7) + ((lane >> 4) & 1) * 8) * PAD_TR
                               + (wn + pr * 16) * 2 + ((lane >> 3) & 1) * 16;
                    ldsm4t(a, r0, r1, r2, r3);
                }
                bF[pr * 2 + 0][0] = r0; bF[pr * 2 + 0][1] = r2;
                bF[pr * 2 + 1][0] = r1; bF[pr * 2 + 1][1] = r3;
            }
            #pragma unroll
            for (int mt = 0; mt < 4; mt++)
                #pragma unroll
                for (int nt = 0; nt < 4; nt++)
                    mma16816(acc + (mt * 4 + nt) * 4, aF[mt], bF[nt][0], bF[nt][1]);
        }
        __syncthreads();
    }
}

// Common fp16 epilogue: write 128x128 tile of acc to o[r][c], ld=CC.
__device__ __forceinline__ void epilogue_h(fp16* o, int row0, int col0, const float* acc)
{
    const int wid = threadIdx.x >> 5, lane = threadIdx.x & 31;
    const int rbase = row0 + (wid >> 2) * 64 + (lane >> 2);
    const int cbase = col0 + (wid & 3) * 32 + 2 * (lane & 3);
    #pragma unroll
    for (int mt = 0; mt < 4; mt++)
        #pragma unroll
        for (int nt = 0; nt < 4; nt++) {
            const float* c = acc + (mt * 4 + nt) * 4;
            size_t r = rbase + mt * 16, cc = cbase + nt * 8;
            *(uint32_t*)(o + r * CC + cc) = h2pack(c[0], c[1]);
            *(uint32_t*)(o + (r + 8) * CC + cc) = h2pack(c[2], c[3]);
        }
}

// ---------------------------------------------------------------------------
// Kernel: M = Wq^T Wk. grid (8, 8). A = WqT [c][d] (NT), B = Wk [d][c'] (TRANSB)
// ---------------------------------------------------------------------------
__global__ __launch_bounds__(256, 2) void m_gemm()
{
    const int row0 = blockIdx.y * 128;   // c
    const int col0 = blockIdx.x * 128;   // c'
    float acc[64];
    #pragma unroll
    for (int i = 0; i < 64; i++) acc[i] = 0.0f;
    run_gemm<true>(g_WqT, CC, g_Wk, CC, CC, row0, col0, acc);
    epilogue_h(g_M, row0, col0, acc);
}

// ---------------------------------------------------------------------------
// Kernel: G = X M. grid (8, 64). A = X (NT-A), B = M [c][c'] (TRANSB)
// ---------------------------------------------------------------------------
__global__ __launch_bounds__(256, 2) void g_gemm()
{
    const int row0 = blockIdx.y * 128;   // token
    const int col0 = blockIdx.x * 128;   // c'
    float acc[64];
    #pragma unroll
    for (int i = 0; i < 64; i++) acc[i] = 0.0f;
    run_gemm<true>(g_Xh, CC, g_M, CC, CC, row0, col0, acc);
    epilogue_h(g_Gh, row0, col0, acc);
}

// ---------------------------------------------------------------------------
// Kernel: V = X Wv^T. grid (8, 64). NT.
// ---------------------------------------------------------------------------
__global__ __launch_bounds__(256, 2) void v_gemm()
{
    const int row0 = blockIdx.y * 128;
    const int col0 = blockIdx.x * 128;
    float acc[64];
    #pragma unroll
    for (int i = 0; i < 64; i++) acc[i] = 0.0f;
    run_gemm<false>(g_Xh, CC, g_Wv, CC, CC, row0, col0, acc);
    epilogue_h(g_Vh, row0, col0, acc);
}

// ---------------------------------------------------------------------------
// Kernel: S = scale * G X^T, causal tile skip. grid (16, 16, 4). NT.
// ---------------------------------------------------------------------------
__global__ __launch_bounds__(256, 2) void qk_gemm()
{
    const int row0 = blockIdx.y * 128;
    const int col0 = blockIdx.x * 128;
    if (col0 > row0 + 127) return;
    const int b = blockIdx.z;
    const size_t xo = (size_t)b * TT * CC;
    float acc[64];
    #pragma unroll
    for (int i = 0; i < 64; i++) acc[i] = 0.0f;
    run_gemm<false>(g_Gh + xo, CC, g_Xh + xo, CC, CC, row0, col0, acc);
    const int wid = threadIdx.x >> 5, lane = threadIdx.x & 31;
    const int rbase = row0 + (wid >> 2) * 64 + (lane >> 2);
    const int cbase = col0 + (wid & 3) * 32 + 2 * (lane & 3);
    float* S = g_S + (size_t)b * TT * TT;
    #pragma unroll
    for (int mt = 0; mt < 4; mt++)
        #pragma unroll
        for (int nt = 0; nt < 4; nt++) {
            const float* c = acc + (mt * 4 + nt) * 4;
            size_t r = rbase + mt * 16, cc = cbase + nt * 8;
            *(float2*)(S + r * TT + cc) = make_float2(c[0] * 0.03125f, c[1] * 0.03125f);
            *(float2*)(S + (r + 8) * TT + cc) = make_float2(c[2] * 0.03125f, c[3] * 0.03125f);
        }
}

// ---------------------------------------------------------------------------
// Kernel: causal softmax -> fp16 P. grid (2048, 4). Row in registers.
// ---------------------------------------------------------------------------
__global__ __launch_bounds__(256) void softmax_k()
{
    const int b = blockIdx.y, t = blockIdx.x;
    const float* row = g_S + ((size_t)b * TT + t) * TT;
    fp16* ph = g_Ph + ((size_t)b * TT + t) * TT;
    const int n = t + 1;
    const int nend = ((t >> 7) + 1) << 7;
    const int tid = threadIdx.x;
    const int lane = tid & 31, wrp = tid >> 5;
    __shared__ float red[8];

    float v[8];
    int cnt = 0;
    float m = -1e30f;
    for (int j = tid; j < n; j += 256) {
        float x = row[j];
        v[cnt++] = x;
        m = fmaxf(m, x);
    }
    #pragma unroll
    for (int o = 16; o > 0; o >>= 1)
        m = fmaxf(m, __shfl_xor_sync(0xffffffffu, m, o));
    if (lane == 0) red[wrp] = m;
    __syncthreads();
    m = red[0];
    #pragma unroll
    for (int w = 1; w < 8; w++) m = fmaxf(m, red[w]);
    __syncthreads();

    float sum = 0.0f;
    #pragma unroll
    for (int c = 0; c < 8; c++)
        if (c < cnt) {
            float e = __expf(v[c] - m);
            v[c] = e;
            sum += e;
        }
    #pragma unroll
    for (int o = 16; o > 0; o >>= 1)
        sum += __shfl_xor_sync(0xffffffffu, sum, o);
    if (lane == 0) red[wrp] = sum;
    __syncthreads();
    sum = red[0];
    #pragma unroll
    for (int w = 1; w < 8; w++) sum += red[w];
    const float inv = 1.0f / sum;

    int c = 0;
    for (int j = tid; j < n; j += 256)
        ph[j] = __float2half_rn(v[c++] * inv);
    const fp16 z = __float2half_rn(0.0f);
    for (int j = n + tid; j < nend; j += 256) ph[j] = z;
}

// ---------------------------------------------------------------------------
// Kernel: O = P V (K truncated causally; V [s][n] via trans-B). grid (8,16,4)
// ---------------------------------------------------------------------------
__global__ __launch_bounds__(256, 2) void pv_gemm(float* __restrict__ out)
{
    const int b = blockIdx.z;
    const int row0 = blockIdx.y * 128;     // query tile
    const int col0 = blockIdx.x * 128;     // channel tile
    const size_t po = (size_t)b * TT * TT;
    const size_t vo = (size_t)b * TT * CC;
    float acc[64];
    #pragma unroll
    for (int i = 0; i < 64; i++) acc[i] = 0.0f;
    run_gemm<true>(g_Ph + po, TT, g_Vh + vo, CC, row0 + 128, row0, col0, acc);
    const int wid = threadIdx.x >> 5, lane = threadIdx.x & 31;
    const int rbase = row0 + (wid >> 2) * 64 + (lane >> 2);
    const int cbase = col0 + (wid & 3) * 32 + 2 * (lane & 3);
    float* O = out + (size_t)b * TT * CC;
    #pragma unroll
    for (int mt = 0; mt < 4; mt++)
        #pragma unroll
        for (int nt = 0; nt < 4; nt++) {
            const float* c = acc + (mt * 4 + nt) * 4;
            size_t r = rbase + mt * 16, cc = cbase + nt * 8;
            *(float2*)(O + r * CC + cc) = make_float2(c[0], c[1]);
            *(float2*)(O + (r + 8) * CC + cc) = make_float2(c[2], c[3]);
        }
}

// ---------------------------------------------------------------------------
// Kernel: fp32 -> fp16 for x, Wk, Wv. (float4 granularity)
// ---------------------------------------------------------------------------
__global__ __launch_bounds__(256) void convert_all(
    const float* __restrict__ x, const float* __restrict__ wk,
    const float* __restrict__ wv)
{
    const long i = (long)blockIdx.x * 256 + threadIdx.x;
    const float* src; fp16* dst; size_t off;
    if (i < 2097152) {
        src = x; dst = g_Xh; off = (size_t)i;
    } else {
        long j = i - 2097152;
        int w = (int)(j / 262144);
        off = (size_t)(j - (long)w * 262144);
        src = (w == 0) ? wk : wv;
        dst = (w == 0) ? g_Wk : g_Wv;
    }
    float4 v = ((const float4*)src)[off];
    uint2 hw;
    hw.x = h2pack(v.x, v.y); hw.y = h2pack(v.z, v.w);
    ((uint2*)dst)[off] = hw;
}

// ---------------------------------------------------------------------------
// Kernel: WqT[c][d] = fp16(Wq[d][c]). grid (32, 32), 256 thr (32x8), smem tile.
// ---------------------------------------------------------------------------
__global__ __launch_bounds__(256) void transpose_wq(const float* __restrict__ wq)
{
    __shared__ float tbuf[32][33];
    const int tx = threadIdx.x & 31, ty = threadIdx.x >> 5;
    const int d0 = blockIdx.y * 32, c0 = blockIdx.x * 32;
    #pragma unroll
    for (int i = 0; i < 4; i++)
        tbuf[ty + i * 8][tx] = wq[(size_t)(d0 + ty + i * 8) * CC + c0 + tx];
    __syncthreads();
    #pragma unroll
    for (int i = 0; i < 4; i++)
        g_WqT[(size_t)(c0 + ty + i * 8) * CC + d0 + tx] =
            __float2half_rn(tbuf[tx][ty + i * 8]);
}

// ---------------------------------------------------------------------------
extern "C" void kernel_launch(void* const* d_in, const int* in_sizes, int n_in,
                              void* d_out, int out_size)
{
    const float* x  = (const float*)d_in[0];
    const float* Wq = (const float*)d_in[1];
    const float* Wk = (const float*)d_in[2];
    const float* Wv = (const float*)d_in[3];
    float* out = (float*)d_out;

    cudaFuncSetAttribute(m_gemm,  cudaFuncAttributeMaxDynamicSharedMemorySize, SMEM_BYTES);
    cudaFuncSetAttribute(g_gemm,  cudaFuncAttributeMaxDynamicSharedMemorySize, SMEM_BYTES);
    cudaFuncSetAttribute(v_gemm,  cudaFuncAttributeMaxDynamicSharedMemorySize, SMEM_BYTES);
    cudaFuncSetAttribute(qk_gemm, cudaFuncAttributeMaxDynamicSharedMemorySize, SMEM_BYTES);
    cudaFuncSetAttribute(pv_gemm, cudaFuncAttributeMaxDynamicSharedMemorySize, SMEM_BYTES);

    convert_all<<<10240, 256>>>(x, Wk, Wv);
    transpose_wq<<<dim3(32, 32), 256>>>(Wq);
    m_gemm<<<dim3(8, 8), 256, SMEM_BYTES>>>();
    g_gemm<<<dim3(8, 64), 256, SMEM_BYTES>>>();
    v_gemm<<<dim3(8, 64), 256, SMEM_BYTES>>>();
    qk_gemm<<<dim3(16, 16, BB), 256, SMEM_BYTES>>>();
    softmax_k<<<dim3(TT, BB), 256>>>();
    pv_gemm<<<dim3(8, 16, BB), 256, SMEM_BYTES>>>(out);
}

// round 9
// speedup vs baseline: 7.5069x; 1.0824x over previous
#include <cuda_runtime.h>
#include <cuda_fp16.h>
#include <stdint.h>
#include <math.h>

#define BB 4
#define TT 2048
#define CC 1024
#define NTOK 8192   // BB*TT

typedef __half fp16;

// ---------------- scratch (__device__ globals; allocation-free rule) -------
__device__ __align__(256) fp16 g_Xh [NTOK * CC];
__device__ __align__(256) fp16 g_Wk [CC * CC];
__device__ __align__(256) fp16 g_Wv [CC * CC];
__device__ __align__(256) fp16 g_WqT[CC * CC];       // Wq transposed [c][d]
__device__ __align__(256) float g_Mp[4 * CC * CC];   // split-K partials (fp32)
__device__ __align__(256) fp16 g_M  [CC * CC];       // Wq^T Wk, [c][c']
__device__ __align__(256) fp16 g_Gh [NTOK * CC];     // X M
__device__ __align__(256) fp16 g_Vh [NTOK * CC];     // [token][channel]
__device__ __align__(256) float g_S[(size_t)BB * TT * TT];
__device__ __align__(256) fp16 g_Ph[(size_t)BB * TT * TT];

// ---------------- helpers ---------------------------------------------------
__device__ __forceinline__ uint32_t smem_u32(const void* p) {
    uint32_t a;
    asm("{ .reg .u64 t; cvta.to.shared.u64 t, %1; cvt.u32.u64 %0, t; }" : "=r"(a) : "l"(p));
    return a;
}
__device__ __forceinline__ void cp16(uint32_t s, const void* g) {
    asm volatile("cp.async.cg.shared.global [%0], [%1], 16;" :: "r"(s), "l"(g));
}
#define CP_COMMIT() asm volatile("cp.async.commit_group;" ::: "memory")
#define CP_WAIT1()  asm volatile("cp.async.wait_group 1;" ::: "memory")

__device__ __forceinline__ void ldsm4(uint32_t a, uint32_t& r0, uint32_t& r1,
                                      uint32_t& r2, uint32_t& r3) {
    asm volatile("ldmatrix.sync.aligned.m8n8.x4.shared.b16 {%0,%1,%2,%3}, [%4];"
                 : "=r"(r0), "=r"(r1), "=r"(r2), "=r"(r3) : "r"(a));
}
__device__ __forceinline__ void ldsm4t(uint32_t a, uint32_t& r0, uint32_t& r1,
                                       uint32_t& r2, uint32_t& r3) {
    asm volatile("ldmatrix.sync.aligned.m8n8.x4.trans.shared.b16 {%0,%1,%2,%3}, [%4];"
                 : "=r"(r0), "=r"(r1), "=r"(r2), "=r"(r3) : "r"(a));
}
__device__ __forceinline__ void mma16816(float* c, const uint32_t* a, uint32_t b0, uint32_t b1) {
    asm volatile(
        "mma.sync.aligned.m16n8k16.row.col.f32.f16.f16.f32 "
        "{%0,%1,%2,%3}, {%4,%5,%6,%7}, {%8,%9}, {%0,%1,%2,%3};"
        : "+f"(c[0]), "+f"(c[1]), "+f"(c[2]), "+f"(c[3])
        : "r"(a[0]), "r"(a[1]), "r"(a[2]), "r"(a[3]), "r"(b0), "r"(b1));
}
__device__ __forceinline__ uint32_t h2pack(float a, float b) {
    __half2 h = __floats2half2_rn(a, b);
    return *reinterpret_cast<uint32_t*>(&h);
}

// smem: 3 stages x 2 tiles (A, B) x 18432B = 110592B  -> 2 CTAs/SM
#define TILE_B  18432
#define STAGE_B (2 * TILE_B)
#define NSTAGE  3
#define SMEM_BYTES (NSTAGE * STAGE_B)
#define PAD_NT 144   // bytes per 64-elem k-row (128B + 16 pad)
#define PAD_TR 272   // bytes per 128-elem n-row (256B + 16 pad)

extern __shared__ char dsm[];

// ---------------------------------------------------------------------------
// 128x128 tile fp16 GEMM: C = A * B^T(NT, B [n][k]) or A * B(TRANSB, B [k][n]).
// 3-stage cp.async pipeline, single barrier per stage (top barrier of iter s
// orders all consumption of buf (s-1)%3 before its refill issued at iter s).
// ---------------------------------------------------------------------------
template <bool TRANSB>
__device__ __forceinline__ void run_gemm(
    const fp16* __restrict__ A, int lda,
    const fp16* __restrict__ B, int ldb,
    int Ktot, int row0, int col0, float* acc)
{
    const int tid = threadIdx.x;
    const int wid = tid >> 5, lane = tid & 31;
    const int wm = (wid >> 2) * 64, wn = (wid & 3) * 32;
    const uint32_t smem = smem_u32(dsm);
    const int nk = Ktot >> 6;

    auto load_stage = [&](int s, int buf) {
        const int kk0 = s << 6;
        const uint32_t base = smem + buf * STAGE_B;
        #pragma unroll
        for (int i = 0; i < 4; i++) {
            int c = tid + i * 256;                 // 0..1023
            int r = c >> 3, kc = c & 7;
            cp16(base + (uint32_t)r * PAD_NT + kc * 16,
                 A + (size_t)(row0 + r) * lda + kk0 + kc * 8);
            if (!TRANSB) {
                cp16(base + TILE_B + (uint32_t)r * PAD_NT + kc * 16,
                     B + (size_t)(col0 + r) * ldb + kk0 + kc * 8);
            } else {
                int rt = c >> 4, nc = c & 15;
                cp16(base + TILE_B + (uint32_t)rt * PAD_TR + nc * 16,
                     B + (size_t)(kk0 + rt) * ldb + col0 + nc * 8);
            }
        }
    };

    load_stage(0, 0); CP_COMMIT();
    if (nk > 1) load_stage(1, 1);
    CP_COMMIT();

    for (int s = 0; s < nk; s++) {
        const int buf = s % 3;
        const uint32_t base = smem + buf * STAGE_B;
        CP_WAIT1();
        __syncthreads();
        if (s + 2 < nk) load_stage(s + 2, (s + 2) % 3);
        CP_COMMIT();

        #pragma unroll
        for (int kk = 0; kk < 4; kk++) {
            uint32_t aF[4][4];
            #pragma unroll
            for (int mt = 0; mt < 4; mt++) {
                uint32_t a = base + (uint32_t)(wm + mt * 16 + (lane & 7) + ((lane >> 3) & 1) * 8) * PAD_NT
                           + kk * 32 + ((lane >> 4) & 1) * 16;
                ldsm4(a, aF[mt][0], aF[mt][1], aF[mt][2], aF[mt][3]);
            }
            uint32_t bF[4][2];
            #pragma unroll
            for (int pr = 0; pr < 2; pr++) {
                uint32_t r0, r1, r2, r3;
                if (!TRANSB) {
                    uint32_t a = base + TILE_B
                               + (uint32_t)(wn + pr * 16 + (lane & 7) + ((lane >> 3) & 1) * 8) * PAD_NT
                               + kk * 32 + ((lane >> 4) & 1) * 16;
                    ldsm4(a, r0, r1, r2, r3);
                } else {
                    uint32_t a = base + TILE_B
                               + (uint32_t)(kk * 16 + (lane & 7) + ((lane >> 4) & 1) * 8) * PAD_TR
                               + (wn + pr * 16) * 2 + ((lane >> 3) & 1) * 16;
                    ldsm4t(a, r0, r1, r2, r3);
                }
                bF[pr * 2 + 0][0] = r0; bF[pr * 2 + 0][1] = r2;
                bF[pr * 2 + 1][0] = r1; bF[pr * 2 + 1][1] = r3;
            }
            #pragma unroll
            for (int mt = 0; mt < 4; mt++)
                #pragma unroll
                for (int nt = 0; nt < 4; nt++)
                    mma16816(acc + (mt * 4 + nt) * 4, aF[mt], bF[nt][0], bF[nt][1]);
        }
    }
}

// Common fp16 epilogue: write 128x128 tile of acc to o[r][c], ld=CC.
__device__ __forceinline__ void epilogue_h(fp16* o, int row0, int col0, const float* acc)
{
    const int wid = threadIdx.x >> 5, lane = threadIdx.x & 31;
    const int rbase = row0 + (wid >> 2) * 64 + (lane >> 2);
    const int cbase = col0 + (wid & 3) * 32 + 2 * (lane & 3);
    #pragma unroll
    for (int mt = 0; mt < 4; mt++)
        #pragma unroll
        for (int nt = 0; nt < 4; nt++) {
            const float* c = acc + (mt * 4 + nt) * 4;
            size_t r = rbase + mt * 16, cc = cbase + nt * 8;
            *(uint32_t*)(o + r * CC + cc) = h2pack(c[0], c[1]);
            *(uint32_t*)(o + (r + 8) * CC + cc) = h2pack(c[2], c[3]);
        }
}

// ---------------------------------------------------------------------------
// Kernel: split-K M partials. grid (8, 8, 4): z = K-slice of 256.
// A = WqT [c][d] (NT-A side), B = Wk [d][c'] (TRANSB). fp32 out.
// ---------------------------------------------------------------------------
__global__ __launch_bounds__(256, 2) void m_gemm_split()
{
    const int row0 = blockIdx.y * 128;   // c
    const int col0 = blockIdx.x * 128;   // c'
    const int z = blockIdx.z;
    float acc[64];
    #pragma unroll
    for (int i = 0; i < 64; i++) acc[i] = 0.0f;
    run_gemm<true>(g_WqT + z * 256, CC, g_Wk + (size_t)(z * 256) * CC, CC,
                   256, row0, col0, acc);
    float* o = g_Mp + (size_t)z * CC * CC;
    const int wid = threadIdx.x >> 5, lane = threadIdx.x & 31;
    const int rbase = row0 + (wid >> 2) * 64 + (lane >> 2);
    const int cbase = col0 + (wid & 3) * 32 + 2 * (lane & 3);
    #pragma unroll
    for (int mt = 0; mt < 4; mt++)
        #pragma unroll
        for (int nt = 0; nt < 4; nt++) {
            const float* c = acc + (mt * 4 + nt) * 4;
            size_t r = rbase + mt * 16, cc = cbase + nt * 8;
            *(float2*)(o + r * CC + cc) = make_float2(c[0], c[1]);
            *(float2*)(o + (r + 8) * CC + cc) = make_float2(c[2], c[3]);
        }
}

// ---------------------------------------------------------------------------
// Kernel: reduce 4 fp32 partials -> fp16 M. grid (1024), 256 thr, float4.
// ---------------------------------------------------------------------------
__global__ __launch_bounds__(256) void m_reduce()
{
    const size_t i = (size_t)blockIdx.x * 256 + threadIdx.x;   // float4 index
    float4 a = ((const float4*)g_Mp)[i];
    float4 b = ((const float4*)(g_Mp + CC * CC))[i];
    float4 c = ((const float4*)(g_Mp + 2 * CC * CC))[i];
    float4 d = ((const float4*)(g_Mp + 3 * CC * CC))[i];
    float x0 = a.x + b.x + c.x + d.x;
    float x1 = a.y + b.y + c.y + d.y;
    float x2 = a.z + b.z + c.z + d.z;
    float x3 = a.w + b.w + c.w + d.w;
    uint2 hw;
    hw.x = h2pack(x0, x1); hw.y = h2pack(x2, x3);
    ((uint2*)g_M)[i] = hw;
}

// ---------------------------------------------------------------------------
// Kernel: merged G = X M (z=0, TRANSB) and V = X Wv^T (z=1, NT). grid (8,64,2)
// ---------------------------------------------------------------------------
__global__ __launch_bounds__(256, 2) void gv_gemm()
{
    const int row0 = blockIdx.y * 128;   // token
    const int col0 = blockIdx.x * 128;   // channel
    float acc[64];
    #pragma unroll
    for (int i = 0; i < 64; i++) acc[i] = 0.0f;
    if (blockIdx.z == 0) {
        run_gemm<true>(g_Xh, CC, g_M, CC, CC, row0, col0, acc);
        epilogue_h(g_Gh, row0, col0, acc);
    } else {
        run_gemm<false>(g_Xh, CC, g_Wv, CC, CC, row0, col0, acc);
        epilogue_h(g_Vh, row0, col0, acc);
    }
}

// ---------------------------------------------------------------------------
// Kernel: S = scale * G X^T, causal tile skip. grid (16, 16, 4). NT.
// ---------------------------------------------------------------------------
__global__ __launch_bounds__(256, 2) void qk_gemm()
{
    const int row0 = blockIdx.y * 128;
    const int col0 = blockIdx.x * 128;
    if (col0 > row0 + 127) return;
    const int b = blockIdx.z;
    const size_t xo = (size_t)b * TT * CC;
    float acc[64];
    #pragma unroll
    for (int i = 0; i < 64; i++) acc[i] = 0.0f;
    run_gemm<false>(g_Gh + xo, CC, g_Xh + xo, CC, CC, row0, col0, acc);
    const int wid = threadIdx.x >> 5, lane = threadIdx.x & 31;
    const int rbase = row0 + (wid >> 2) * 64 + (lane >> 2);
    const int cbase = col0 + (wid & 3) * 32 + 2 * (lane & 3);
    float* S = g_S + (size_t)b * TT * TT;
    #pragma unroll
    for (int mt = 0; mt < 4; mt++)
        #pragma unroll
        for (int nt = 0; nt < 4; nt++) {
            const float* c = acc + (mt * 4 + nt) * 4;
            size_t r = rbase + mt * 16, cc = cbase + nt * 8;
            *(float2*)(S + r * TT + cc) = make_float2(c[0] * 0.03125f, c[1] * 0.03125f);
            *(float2*)(S + (r + 8) * TT + cc) = make_float2(c[2] * 0.03125f, c[3] * 0.03125f);
        }
}

// ---------------------------------------------------------------------------
// Kernel: causal softmax -> fp16 P. grid (2048, 4). Row in registers.
// ---------------------------------------------------------------------------
__global__ __launch_bounds__(256) void softmax_k()
{
    const int b = blockIdx.y, t = blockIdx.x;
    const float* row = g_S + ((size_t)b * TT + t) * TT;
    fp16* ph = g_Ph + ((size_t)b * TT + t) * TT;
    const int n = t + 1;
    const int nend = ((t >> 7) + 1) << 7;
    const int tid = threadIdx.x;
    const int lane = tid & 31, wrp = tid >> 5;
    __shared__ float red[8];

    float v[8];
    int cnt = 0;
    float m = -1e30f;
    for (int j = tid; j < n; j += 256) {
        float x = row[j];
        v[cnt++] = x;
        m = fmaxf(m, x);
    }
    #pragma unroll
    for (int o = 16; o > 0; o >>= 1)
        m = fmaxf(m, __shfl_xor_sync(0xffffffffu, m, o));
    if (lane == 0) red[wrp] = m;
    __syncthreads();
    m = red[0];
    #pragma unroll
    for (int w = 1; w < 8; w++) m = fmaxf(m, red[w]);
    __syncthreads();

    float sum = 0.0f;
    #pragma unroll
    for (int c = 0; c < 8; c++)
        if (c < cnt) {
            float e = __expf(v[c] - m);
            v[c] = e;
            sum += e;
        }
    #pragma unroll
    for (int o = 16; o > 0; o >>= 1)
        sum += __shfl_xor_sync(0xffffffffu, sum, o);
    if (lane == 0) red[wrp] = sum;
    __syncthreads();
    sum = red[0];
    #pragma unroll
    for (int w = 1; w < 8; w++) sum += red[w];
    const float inv = 1.0f / sum;

    int c = 0;
    for (int j = tid; j < n; j += 256)
        ph[j] = __float2half_rn(v[c++] * inv);
    const fp16 z = __float2half_rn(0.0f);
    for (int j = n + tid; j < nend; j += 256) ph[j] = z;
}

// ---------------------------------------------------------------------------
// Kernel: O = P V (K truncated causally; V [s][n] via trans-B). grid (8,16,4)
// ---------------------------------------------------------------------------
__global__ __launch_bounds__(256, 2) void pv_gemm(float* __restrict__ out)
{
    const int b = blockIdx.z;
    const int row0 = blockIdx.y * 128;     // query tile
    const int col0 = blockIdx.x * 128;     // channel tile
    const size_t po = (size_t)b * TT * TT;
    const size_t vo = (size_t)b * TT * CC;
    float acc[64];
    #pragma unroll
    for (int i = 0; i < 64; i++) acc[i] = 0.0f;
    run_gemm<true>(g_Ph + po, TT, g_Vh + vo, CC, row0 + 128, row0, col0, acc);
    const int wid = threadIdx.x >> 5, lane = threadIdx.x & 31;
    const int rbase = row0 + (wid >> 2) * 64 + (lane >> 2);
    const int cbase = col0 + (wid & 3) * 32 + 2 * (lane & 3);
    float* O = out + (size_t)b * TT * CC;
    #pragma unroll
    for (int mt = 0; mt < 4; mt++)
        #pragma unroll
        for (int nt = 0; nt < 4; nt++) {
            const float* c = acc + (mt * 4 + nt) * 4;
            size_t r = rbase + mt * 16, cc = cbase + nt * 8;
            *(float2*)(O + r * CC + cc) = make_float2(c[0], c[1]);
            *(float2*)(O + (r + 8) * CC + cc) = make_float2(c[2], c[3]);
        }
}

// ---------------------------------------------------------------------------
// Kernel: fp32 -> fp16 for x, Wk, Wv. (float4 granularity)
// ---------------------------------------------------------------------------
__global__ __launch_bounds__(256) void convert_all(
    const float* __restrict__ x, const float* __restrict__ wk,
    const float* __restrict__ wv)
{
    const long i = (long)blockIdx.x * 256 + threadIdx.x;
    const float* src; fp16* dst; size_t off;
    if (i < 2097152) {
        src = x; dst = g_Xh; off = (size_t)i;
    } else {
        long j = i - 2097152;
        int w = (int)(j / 262144);
        off = (size_t)(j - (long)w * 262144);
        src = (w == 0) ? wk : wv;
        dst = (w == 0) ? g_Wk : g_Wv;
    }
    float4 v = ((const float4*)src)[off];
    uint2 hw;
    hw.x = h2pack(v.x, v.y); hw.y = h2pack(v.z, v.w);
    ((uint2*)dst)[off] = hw;
}

// ---------------------------------------------------------------------------
// Kernel: WqT[c][d] = fp16(Wq[d][c]). grid (32, 32), 256 thr (32x8), smem tile.
// ---------------------------------------------------------------------------
__global__ __launch_bounds__(256) void transpose_wq(const float* __restrict__ wq)
{
    __shared__ float tbuf[32][33];
    const int tx = threadIdx.x & 31, ty = threadIdx.x >> 5;
    const int d0 = blockIdx.y * 32, c0 = blockIdx.x * 32;
    #pragma unroll
    for (int i = 0; i < 4; i++)
        tbuf[ty + i * 8][tx] = wq[(size_t)(d0 + ty + i * 8) * CC + c0 + tx];
    __syncthreads();
    #pragma unroll
    for (int i = 0; i < 4; i++)
        g_WqT[(size_t)(c0 + ty + i * 8) * CC + d0 + tx] =
            __float2half_rn(tbuf[tx][ty + i * 8]);
}

// ---------------------------------------------------------------------------
extern "C" void kernel_launch(void* const* d_in, const int* in_sizes, int n_in,
                              void* d_out, int out_size)
{
    const float* x  = (const float*)d_in[0];
    const float* Wq = (const float*)d_in[1];
    const float* Wk = (const float*)d_in[2];
    const float* Wv = (const float*)d_in[3];
    float* out = (float*)d_out;

    cudaFuncSetAttribute(m_gemm_split, cudaFuncAttributeMaxDynamicSharedMemorySize, SMEM_BYTES);
    cudaFuncSetAttribute(gv_gemm, cudaFuncAttributeMaxDynamicSharedMemorySize, SMEM_BYTES);
    cudaFuncSetAttribute(qk_gemm, cudaFuncAttributeMaxDynamicSharedMemorySize, SMEM_BYTES);
    cudaFuncSetAttribute(pv_gemm, cudaFuncAttributeMaxDynamicSharedMemorySize, SMEM_BYTES);

    convert_all<<<10240, 256>>>(x, Wk, Wv);
    transpose_wq<<<dim3(32, 32), 256>>>(Wq);
    m_gemm_split<<<dim3(8, 8, 4), 256, SMEM_BYTES>>>();
    m_reduce<<<1024, 256>>>();
    gv_gemm<<<dim3(8, 64, 2), 256, SMEM_BYTES>>>();
    qk_gemm<<<dim3(16, 16, BB), 256, SMEM_BYTES>>>();
    softmax_k<<<dim3(TT, BB), 256>>>();
    pv_gemm<<<dim3(8, 16, BB), 256, SMEM_BYTES>>>(out);
}

// round 10
// speedup vs baseline: 7.6346x; 1.0170x over previous
#include <cuda_runtime.h>
#include <cuda_fp16.h>
#include <stdint.h>
#include <math.h>

#define BB 4
#define TT 2048
#define CC 1024
#define NTOK 8192   // BB*TT

typedef __half fp16;

// ---------------- scratch (__device__ globals; allocation-free rule) -------
__device__ __align__(256) fp16 g_Xh [NTOK * CC];
__device__ __align__(256) fp16 g_Wk [CC * CC];
__device__ __align__(256) fp16 g_Wv [CC * CC];
__device__ __align__(256) fp16 g_WqT[CC * CC];       // Wq transposed [c][d]
__device__ __align__(256) float g_Mp[4 * CC * CC];   // split-K partials (fp32)
__device__ __align__(256) fp16 g_M  [CC * CC];       // Wq^T Wk, [c][c']
__device__ __align__(256) fp16 g_Gh [NTOK * CC];     // X M
__device__ __align__(256) fp16 g_Vh [NTOK * CC];     // [token][channel]
__device__ __align__(256) float g_S[(size_t)BB * TT * TT];
__device__ __align__(256) fp16 g_Ph[(size_t)BB * TT * TT];

// ---------------- helpers ---------------------------------------------------
__device__ __forceinline__ uint32_t smem_u32(const void* p) {
    uint32_t a;
    asm("{ .reg .u64 t; cvta.to.shared.u64 t, %1; cvt.u32.u64 %0, t; }" : "=r"(a) : "l"(p));
    return a;
}
__device__ __forceinline__ void cp16(uint32_t s, const void* g) {
    asm volatile("cp.async.cg.shared.global [%0], [%1], 16;" :: "r"(s), "l"(g));
}
#define CP_COMMIT() asm volatile("cp.async.commit_group;" ::: "memory")
#define CP_WAIT1()  asm volatile("cp.async.wait_group 1;" ::: "memory")

__device__ __forceinline__ void ldsm4(uint32_t a, uint32_t& r0, uint32_t& r1,
                                      uint32_t& r2, uint32_t& r3) {
    asm volatile("ldmatrix.sync.aligned.m8n8.x4.shared.b16 {%0,%1,%2,%3}, [%4];"
                 : "=r"(r0), "=r"(r1), "=r"(r2), "=r"(r3) : "r"(a));
}
__device__ __forceinline__ void ldsm4t(uint32_t a, uint32_t& r0, uint32_t& r1,
                                       uint32_t& r2, uint32_t& r3) {
    asm volatile("ldmatrix.sync.aligned.m8n8.x4.trans.shared.b16 {%0,%1,%2,%3}, [%4];"
                 : "=r"(r0), "=r"(r1), "=r"(r2), "=r"(r3) : "r"(a));
}
__device__ __forceinline__ void mma16816(float* c, const uint32_t* a, uint32_t b0, uint32_t b1) {
    asm volatile(
        "mma.sync.aligned.m16n8k16.row.col.f32.f16.f16.f32 "
        "{%0,%1,%2,%3}, {%4,%5,%6,%7}, {%8,%9}, {%0,%1,%2,%3};"
        : "+f"(c[0]), "+f"(c[1]), "+f"(c[2]), "+f"(c[3])
        : "r"(a[0]), "r"(a[1]), "r"(a[2]), "r"(a[3]), "r"(b0), "r"(b1));
}
__device__ __forceinline__ uint32_t h2pack(float a, float b) {
    __half2 h = __floats2half2_rn(a, b);
    return *reinterpret_cast<uint32_t*>(&h);
}

// smem: 3 stages x 2 tiles (A, B) x 18432B = 110592B  -> 2 CTAs/SM
#define TILE_B  18432
#define STAGE_B (2 * TILE_B)
#define NSTAGE  3
#define SMEM_BYTES (NSTAGE * STAGE_B)
#define PAD_NT 144   // bytes per 64-elem k-row (128B + 16 pad)
#define PAD_TR 272   // bytes per 128-elem n-row (256B + 16 pad)

extern __shared__ char dsm[];

// ---------------------------------------------------------------------------
// 128x128 tile fp16 GEMM: C = A * B^T(NT, B [n][k]) or A * B(TRANSB, B [k][n]).
// 3-stage cp.async pipeline, single barrier per stage.
// ---------------------------------------------------------------------------
template <bool TRANSB>
__device__ __forceinline__ void run_gemm(
    const fp16* __restrict__ A, int lda,
    const fp16* __restrict__ B, int ldb,
    int Ktot, int row0, int col0, float* acc)
{
    const int tid = threadIdx.x;
    const int wid = tid >> 5, lane = tid & 31;
    const int wm = (wid >> 2) * 64, wn = (wid & 3) * 32;
    const uint32_t smem = smem_u32(dsm);
    const int nk = Ktot >> 6;

    auto load_stage = [&](int s, int buf) {
        const int kk0 = s << 6;
        const uint32_t base = smem + buf * STAGE_B;
        #pragma unroll
        for (int i = 0; i < 4; i++) {
            int c = tid + i * 256;                 // 0..1023
            int r = c >> 3, kc = c & 7;
            cp16(base + (uint32_t)r * PAD_NT + kc * 16,
                 A + (size_t)(row0 + r) * lda + kk0 + kc * 8);
            if (!TRANSB) {
                cp16(base + TILE_B + (uint32_t)r * PAD_NT + kc * 16,
                     B + (size_t)(col0 + r) * ldb + kk0 + kc * 8);
            } else {
                int rt = c >> 4, nc = c & 15;
                cp16(base + TILE_B + (uint32_t)rt * PAD_TR + nc * 16,
                     B + (size_t)(kk0 + rt) * ldb + col0 + nc * 8);
            }
        }
    };

    load_stage(0, 0); CP_COMMIT();
    if (nk > 1) load_stage(1, 1);
    CP_COMMIT();

    for (int s = 0; s < nk; s++) {
        const int buf = s % 3;
        const uint32_t base = smem + buf * STAGE_B;
        CP_WAIT1();
        __syncthreads();
        if (s + 2 < nk) load_stage(s + 2, (s + 2) % 3);
        CP_COMMIT();

        #pragma unroll
        for (int kk = 0; kk < 4; kk++) {
            uint32_t aF[4][4];
            #pragma unroll
            for (int mt = 0; mt < 4; mt++) {
                uint32_t a = base + (uint32_t)(wm + mt * 16 + (lane & 7) + ((lane >> 3) & 1) * 8) * PAD_NT
                           + kk * 32 + ((lane >> 4) & 1) * 16;
                ldsm4(a, aF[mt][0], aF[mt][1], aF[mt][2], aF[mt][3]);
            }
            uint32_t bF[4][2];
            #pragma unroll
            for (int pr = 0; pr < 2; pr++) {
                uint32_t r0, r1, r2, r3;
                if (!TRANSB) {
                    uint32_t a = base + TILE_B
                               + (uint32_t)(wn + pr * 16 + (lane & 7) + ((lane >> 3) & 1) * 8) * PAD_NT
                               + kk * 32 + ((lane >> 4) & 1) * 16;
                    ldsm4(a, r0, r1, r2, r3);
                } else {
                    uint32_t a = base + TILE_B
                               + (uint32_t)(kk * 16 + (lane & 7) + ((lane >> 4) & 1) * 8) * PAD_TR
                               + (wn + pr * 16) * 2 + ((lane >> 3) & 1) * 16;
                    ldsm4t(a, r0, r1, r2, r3);
                }
                bF[pr * 2 + 0][0] = r0; bF[pr * 2 + 0][1] = r2;
                bF[pr * 2 + 1][0] = r1; bF[pr * 2 + 1][1] = r3;
            }
            #pragma unroll
            for (int mt = 0; mt < 4; mt++)
                #pragma unroll
                for (int nt = 0; nt < 4; nt++)
                    mma16816(acc + (mt * 4 + nt) * 4, aF[mt], bF[nt][0], bF[nt][1]);
        }
    }
}

// Common fp16 epilogue: write 128x128 tile of acc to o[r][c], ld=CC.
__device__ __forceinline__ void epilogue_h(fp16* o, int row0, int col0, const float* acc)
{
    const int wid = threadIdx.x >> 5, lane = threadIdx.x & 31;
    const int rbase = row0 + (wid >> 2) * 64 + (lane >> 2);
    const int cbase = col0 + (wid & 3) * 32 + 2 * (lane & 3);
    #pragma unroll
    for (int mt = 0; mt < 4; mt++)
        #pragma unroll
        for (int nt = 0; nt < 4; nt++) {
            const float* c = acc + (mt * 4 + nt) * 4;
            size_t r = rbase + mt * 16, cc = cbase + nt * 8;
            *(uint32_t*)(o + r * CC + cc) = h2pack(c[0], c[1]);
            *(uint32_t*)(o + (r + 8) * CC + cc) = h2pack(c[2], c[3]);
        }
}

// ---------------------------------------------------------------------------
// Kernel: split-K M partials. grid (8, 8, 4): z = K-slice of 256.
// ---------------------------------------------------------------------------
__global__ __launch_bounds__(256, 2) void m_gemm_split()
{
    const int row0 = blockIdx.y * 128;   // c
    const int col0 = blockIdx.x * 128;   // c'
    const int z = blockIdx.z;
    float acc[64];
    #pragma unroll
    for (int i = 0; i < 64; i++) acc[i] = 0.0f;
    run_gemm<true>(g_WqT + z * 256, CC, g_Wk + (size_t)(z * 256) * CC, CC,
                   256, row0, col0, acc);
    float* o = g_Mp + (size_t)z * CC * CC;
    const int wid = threadIdx.x >> 5, lane = threadIdx.x & 31;
    const int rbase = row0 + (wid >> 2) * 64 + (lane >> 2);
    const int cbase = col0 + (wid & 3) * 32 + 2 * (lane & 3);
    #pragma unroll
    for (int mt = 0; mt < 4; mt++)
        #pragma unroll
        for (int nt = 0; nt < 4; nt++) {
            const float* c = acc + (mt * 4 + nt) * 4;
            size_t r = rbase + mt * 16, cc = cbase + nt * 8;
            *(float2*)(o + r * CC + cc) = make_float2(c[0], c[1]);
            *(float2*)(o + (r + 8) * CC + cc) = make_float2(c[2], c[3]);
        }
}

// ---------------------------------------------------------------------------
// Kernel: reduce 4 fp32 partials -> fp16 M. grid (1024), 256 thr, float4.
// ---------------------------------------------------------------------------
__global__ __launch_bounds__(256) void m_reduce()
{
    const size_t i = (size_t)blockIdx.x * 256 + threadIdx.x;   // float4 index
    float4 a = ((const float4*)g_Mp)[i];
    float4 b = ((const float4*)(g_Mp + CC * CC))[i];
    float4 c = ((const float4*)(g_Mp + 2 * CC * CC))[i];
    float4 d = ((const float4*)(g_Mp + 3 * CC * CC))[i];
    float x0 = a.x + b.x + c.x + d.x;
    float x1 = a.y + b.y + c.y + d.y;
    float x2 = a.z + b.z + c.z + d.z;
    float x3 = a.w + b.w + c.w + d.w;
    uint2 hw;
    hw.x = h2pack(x0, x1); hw.y = h2pack(x2, x3);
    ((uint2*)g_M)[i] = hw;
}

// ---------------------------------------------------------------------------
// Kernel: G = X M. grid (8, 64). TRANSB (M [c][c']).
// ---------------------------------------------------------------------------
__global__ __launch_bounds__(256, 2) void g_gemm()
{
    const int row0 = blockIdx.y * 128;
    const int col0 = blockIdx.x * 128;
    float acc[64];
    #pragma unroll
    for (int i = 0; i < 64; i++) acc[i] = 0.0f;
    run_gemm<true>(g_Xh, CC, g_M, CC, CC, row0, col0, acc);
    epilogue_h(g_Gh, row0, col0, acc);
}

// ---------------------------------------------------------------------------
// Kernel: V = X Wv^T. grid (8, 64). NT.
// ---------------------------------------------------------------------------
__global__ __launch_bounds__(256, 2) void v_gemm()
{
    const int row0 = blockIdx.y * 128;
    const int col0 = blockIdx.x * 128;
    float acc[64];
    #pragma unroll
    for (int i = 0; i < 64; i++) acc[i] = 0.0f;
    run_gemm<false>(g_Xh, CC, g_Wv, CC, CC, row0, col0, acc);
    epilogue_h(g_Vh, row0, col0, acc);
}

// ---------------------------------------------------------------------------
// Kernel: S_b = scale * G_b X_b^T, causal tile skip. grid (16, 16). NT.
// ---------------------------------------------------------------------------
__global__ __launch_bounds__(256, 2) void qk_gemm(int b)
{
    const int row0 = blockIdx.y * 128;
    const int col0 = blockIdx.x * 128;
    if (col0 > row0 + 127) return;
    const size_t xo = (size_t)b * TT * CC;
    float acc[64];
    #pragma unroll
    for (int i = 0; i < 64; i++) acc[i] = 0.0f;
    run_gemm<false>(g_Gh + xo, CC, g_Xh + xo, CC, CC, row0, col0, acc);
    const int wid = threadIdx.x >> 5, lane = threadIdx.x & 31;
    const int rbase = row0 + (wid >> 2) * 64 + (lane >> 2);
    const int cbase = col0 + (wid & 3) * 32 + 2 * (lane & 3);
    float* S = g_S + (size_t)b * TT * TT;
    #pragma unroll
    for (int mt = 0; mt < 4; mt++)
        #pragma unroll
        for (int nt = 0; nt < 4; nt++) {
            const float* c = acc + (mt * 4 + nt) * 4;
            size_t r = rbase + mt * 16, cc = cbase + nt * 8;
            *(float2*)(S + r * TT + cc) = make_float2(c[0] * 0.03125f, c[1] * 0.03125f);
            *(float2*)(S + (r + 8) * TT + cc) = make_float2(c[2] * 0.03125f, c[3] * 0.03125f);
        }
}

// ---------------------------------------------------------------------------
// Kernel: causal softmax -> fp16 P, batch b. grid (2048). Row in registers.
// ---------------------------------------------------------------------------
__global__ __launch_bounds__(256) void softmax_k(int b)
{
    const int t = blockIdx.x;
    const float* row = g_S + ((size_t)b * TT + t) * TT;
    fp16* ph = g_Ph + ((size_t)b * TT + t) * TT;
    const int n = t + 1;
    const int nend = ((t >> 7) + 1) << 7;
    const int tid = threadIdx.x;
    const int lane = tid & 31, wrp = tid >> 5;
    __shared__ float red[8];

    float v[8];
    int cnt = 0;
    float m = -1e30f;
    for (int j = tid; j < n; j += 256) {
        float x = row[j];
        v[cnt++] = x;
        m = fmaxf(m, x);
    }
    #pragma unroll
    for (int o = 16; o > 0; o >>= 1)
        m = fmaxf(m, __shfl_xor_sync(0xffffffffu, m, o));
    if (lane == 0) red[wrp] = m;
    __syncthreads();
    m = red[0];
    #pragma unroll
    for (int w = 1; w < 8; w++) m = fmaxf(m, red[w]);
    __syncthreads();

    float sum = 0.0f;
    #pragma unroll
    for (int c = 0; c < 8; c++)
        if (c < cnt) {
            float e = __expf(v[c] - m);
            v[c] = e;
            sum += e;
        }
    #pragma unroll
    for (int o = 16; o > 0; o >>= 1)
        sum += __shfl_xor_sync(0xffffffffu, sum, o);
    if (lane == 0) red[wrp] = sum;
    __syncthreads();
    sum = red[0];
    #pragma unroll
    for (int w = 1; w < 8; w++) sum += red[w];
    const float inv = 1.0f / sum;

    int c = 0;
    for (int j = tid; j < n; j += 256)
        ph[j] = __float2half_rn(v[c++] * inv);
    const fp16 z = __float2half_rn(0.0f);
    for (int j = n + tid; j < nend; j += 256) ph[j] = z;
}

// ---------------------------------------------------------------------------
// Kernel: O_b = P_b V_b (K truncated causally). grid (8, 16).
// ---------------------------------------------------------------------------
__global__ __launch_bounds__(256, 2) void pv_gemm(float* __restrict__ out, int b)
{
    const int row0 = blockIdx.y * 128;     // query tile
    const int col0 = blockIdx.x * 128;     // channel tile
    const size_t po = (size_t)b * TT * TT;
    const size_t vo = (size_t)b * TT * CC;
    float acc[64];
    #pragma unroll
    for (int i = 0; i < 64; i++) acc[i] = 0.0f;
    run_gemm<true>(g_Ph + po, TT, g_Vh + vo, CC, row0 + 128, row0, col0, acc);
    const int wid = threadIdx.x >> 5, lane = threadIdx.x & 31;
    const int rbase = row0 + (wid >> 2) * 64 + (lane >> 2);
    const int cbase = col0 + (wid & 3) * 32 + 2 * (lane & 3);
    float* O = out + (size_t)b * TT * CC;
    #pragma unroll
    for (int mt = 0; mt < 4; mt++)
        #pragma unroll
        for (int nt = 0; nt < 4; nt++) {
            const float* c = acc + (mt * 4 + nt) * 4;
            size_t r = rbase + mt * 16, cc = cbase + nt * 8;
            *(float2*)(O + r * CC + cc) = make_float2(c[0], c[1]);
            *(float2*)(O + (r + 8) * CC + cc) = make_float2(c[2], c[3]);
        }
}

// ---------------------------------------------------------------------------
// Kernel: fp32 -> fp16 for x, Wk, Wv. (float4 granularity)
// ---------------------------------------------------------------------------
__global__ __launch_bounds__(256) void convert_all(
    const float* __restrict__ x, const float* __restrict__ wk,
    const float* __restrict__ wv)
{
    const long i = (long)blockIdx.x * 256 + threadIdx.x;
    const float* src; fp16* dst; size_t off;
    if (i < 2097152) {
        src = x; dst = g_Xh; off = (size_t)i;
    } else {
        long j = i - 2097152;
        int w = (int)(j / 262144);
        off = (size_t)(j - (long)w * 262144);
        src = (w == 0) ? wk : wv;
        dst = (w == 0) ? g_Wk : g_Wv;
    }
    float4 v = ((const float4*)src)[off];
    uint2 hw;
    hw.x = h2pack(v.x, v.y); hw.y = h2pack(v.z, v.w);
    ((uint2*)dst)[off] = hw;
}

// ---------------------------------------------------------------------------
// Kernel: WqT[c][d] = fp16(Wq[d][c]). grid (32, 32), 256 thr, smem tile.
// ---------------------------------------------------------------------------
__global__ __launch_bounds__(256) void transpose_wq(const float* __restrict__ wq)
{
    __shared__ float tbuf[32][33];
    const int tx = threadIdx.x & 31, ty = threadIdx.x >> 5;
    const int d0 = blockIdx.y * 32, c0 = blockIdx.x * 32;
    #pragma unroll
    for (int i = 0; i < 4; i++)
        tbuf[ty + i * 8][tx] = wq[(size_t)(d0 + ty + i * 8) * CC + c0 + tx];
    __syncthreads();
    #pragma unroll
    for (int i = 0; i < 4; i++)
        g_WqT[(size_t)(c0 + ty + i * 8) * CC + d0 + tx] =
            __float2half_rn(tbuf[tx][ty + i * 8]);
}

// ---------------------------------------------------------------------------
extern "C" void kernel_launch(void* const* d_in, const int* in_sizes, int n_in,
                              void* d_out, int out_size)
{
    const float* x  = (const float*)d_in[0];
    const float* Wq = (const float*)d_in[1];
    const float* Wk = (const float*)d_in[2];
    const float* Wv = (const float*)d_in[3];
    float* out = (float*)d_out;

    // One-time resource setup (first call is the uncaptured correctness run).
    static cudaStream_t st[3];
    static cudaEvent_t  ev[7];
    static bool inited = false;
    if (!inited) {
        for (int i = 0; i < 3; i++)
            cudaStreamCreateWithFlags(&st[i], cudaStreamNonBlocking);
        for (int i = 0; i < 7; i++)
            cudaEventCreateWithFlags(&ev[i], cudaEventDisableTiming);
        cudaFuncSetAttribute(m_gemm_split, cudaFuncAttributeMaxDynamicSharedMemorySize, SMEM_BYTES);
        cudaFuncSetAttribute(g_gemm,  cudaFuncAttributeMaxDynamicSharedMemorySize, SMEM_BYTES);
        cudaFuncSetAttribute(v_gemm,  cudaFuncAttributeMaxDynamicSharedMemorySize, SMEM_BYTES);
        cudaFuncSetAttribute(qk_gemm, cudaFuncAttributeMaxDynamicSharedMemorySize, SMEM_BYTES);
        cudaFuncSetAttribute(pv_gemm, cudaFuncAttributeMaxDynamicSharedMemorySize, SMEM_BYTES);
        inited = true;
    }

    // main (legacy) stream: conversions
    convert_all<<<10240, 256>>>(x, Wk, Wv);
    transpose_wq<<<dim3(32, 32), 256>>>(Wq);
    cudaEventRecord(ev[0], 0);

    // side stream: M = WqT*Wk chain (overlaps v_gemm on main)
    cudaStreamWaitEvent(st[0], ev[0], 0);
    m_gemm_split<<<dim3(8, 8, 4), 256, SMEM_BYTES, st[0]>>>();
    m_reduce<<<1024, 256, 0, st[0]>>>();
    cudaEventRecord(ev[1], st[0]);                 // e_m

    // main: V projection (independent of M)
    v_gemm<<<dim3(8, 64), 256, SMEM_BYTES>>>();
    cudaEventRecord(ev[2], 0);                     // e_v

    // main: G = X M (needs M)
    cudaStreamWaitEvent(0, ev[1], 0);
    g_gemm<<<dim3(8, 64), 256, SMEM_BYTES>>>();
    cudaEventRecord(ev[3], 0);                     // e_g

    // batch 0 chain on main (already ordered after v and g)
    qk_gemm<<<dim3(16, 16), 256, SMEM_BYTES>>>(0);
    softmax_k<<<2048, 256>>>(0);
    pv_gemm<<<dim3(8, 16), 256, SMEM_BYTES>>>(out, 0);

    // batch 1..3 chains on side streams
    for (int i = 0; i < 3; i++) {
        const int b = i + 1;
        cudaStreamWaitEvent(st[i], ev[3], 0);      // wait G
        cudaStreamWaitEvent(st[i], ev[2], 0);      // wait V
        qk_gemm<<<dim3(16, 16), 256, SMEM_BYTES, st[i]>>>(b);
        softmax_k<<<2048, 256, 0, st[i]>>>(b);
        pv_gemm<<<dim3(8, 16), 256, SMEM_BYTES, st[i]>>>(out, b);
        cudaEventRecord(ev[4 + i], st[i]);
    }
    // join all chains back into the main stream
    for (int i = 0; i < 3; i++)
        cudaStreamWaitEvent(0, ev[4 + i], 0);
}

// round 13
// speedup vs baseline: 7.6482x; 1.0018x over previous
#include <cuda_runtime.h>
#include <cuda_fp16.h>
#include <stdint.h>
#include <math.h>

#define BB 4
#define TT 2048
#define CC 1024
#define NTOK 8192   // BB*TT

typedef __half fp16;

// ---------------- scratch (__device__ globals; allocation-free rule) -------
__device__ __align__(256) fp16 g_Xh [NTOK * CC];
__device__ __align__(256) fp16 g_Wk [CC * CC];
__device__ __align__(256) fp16 g_Wv [CC * CC];
__device__ __align__(256) fp16 g_WqT[CC * CC];       // Wq transposed [c][d]
__device__ __align__(256) float g_Mp[4 * CC * CC];   // split-K partials (fp32)
__device__ __align__(256) fp16 g_M  [CC * CC];       // Wq^T Wk, [c][c']
__device__ __align__(256) fp16 g_Gh [NTOK * CC];     // X M
__device__ __align__(256) fp16 g_Vh [NTOK * CC];     // [token][channel]
__device__ __align__(256) float g_S[(size_t)BB * TT * TT];
__device__ __align__(256) fp16 g_Ph[(size_t)BB * TT * TT];

// ---------------- helpers ---------------------------------------------------
__device__ __forceinline__ uint32_t smem_u32(const void* p) {
    uint32_t a;
    asm("{ .reg .u64 t; cvta.to.shared.u64 t, %1; cvt.u32.u64 %0, t; }" : "=r"(a) : "l"(p));
    return a;
}
__device__ __forceinline__ void cp16(uint32_t s, const void* g) {
    asm volatile("cp.async.cg.shared.global [%0], [%1], 16;" :: "r"(s), "l"(g));
}
#define CP_COMMIT() asm volatile("cp.async.commit_group;" ::: "memory")
#define CP_WAIT1()  asm volatile("cp.async.wait_group 1;" ::: "memory")

__device__ __forceinline__ void ldsm4(uint32_t a, uint32_t& r0, uint32_t& r1,
                                      uint32_t& r2, uint32_t& r3) {
    asm volatile("ldmatrix.sync.aligned.m8n8.x4.shared.b16 {%0,%1,%2,%3}, [%4];"
                 : "=r"(r0), "=r"(r1), "=r"(r2), "=r"(r3) : "r"(a));
}
__device__ __forceinline__ void ldsm4t(uint32_t a, uint32_t& r0, uint32_t& r1,
                                       uint32_t& r2, uint32_t& r3) {
    asm volatile("ldmatrix.sync.aligned.m8n8.x4.trans.shared.b16 {%0,%1,%2,%3}, [%4];"
                 : "=r"(r0), "=r"(r1), "=r"(r2), "=r"(r3) : "r"(a));
}
__device__ __forceinline__ void mma16816(float* c, const uint32_t* a, uint32_t b0, uint32_t b1) {
    asm volatile(
        "mma.sync.aligned.m16n8k16.row.col.f32.f16.f16.f32 "
        "{%0,%1,%2,%3}, {%4,%5,%6,%7}, {%8,%9}, {%0,%1,%2,%3};"
        : "+f"(c[0]), "+f"(c[1]), "+f"(c[2]), "+f"(c[3])
        : "r"(a[0]), "r"(a[1]), "r"(a[2]), "r"(a[3]), "r"(b0), "r"(b1));
}
__device__ __forceinline__ uint32_t h2pack(float a, float b) {
    __half2 h = __floats2half2_rn(a, b);
    return *reinterpret_cast<uint32_t*>(&h);
}

// smem: 3 stages x 2 tiles (A, B) x 18432B = 110592B  -> 2 CTAs/SM
#define TILE_B  18432
#define STAGE_B (2 * TILE_B)
#define NSTAGE  3
#define SMEM_BYTES (NSTAGE * STAGE_B)
#define PAD_NT 144   // bytes per 64-elem k-row (128B + 16 pad)
#define PAD_TR 272   // bytes per 128-elem n-row (256B + 16 pad)

extern __shared__ char dsm[];

// ---------------------------------------------------------------------------
// 128x128 tile fp16 GEMM: C = A * B^T(NT, B [n][k]) or A * B(TRANSB, B [k][n]).
// 3-stage cp.async pipeline, single barrier per stage.
// ---------------------------------------------------------------------------
template <bool TRANSB>
__device__ __forceinline__ void run_gemm(
    const fp16* __restrict__ A, int lda,
    const fp16* __restrict__ B, int ldb,
    int Ktot, int row0, int col0, float* acc)
{
    const int tid = threadIdx.x;
    const int wid = tid >> 5, lane = tid & 31;
    const int wm = (wid >> 2) * 64, wn = (wid & 3) * 32;
    const uint32_t smem = smem_u32(dsm);
    const int nk = Ktot >> 6;

    auto load_stage = [&](int s, int buf) {
        const int kk0 = s << 6;
        const uint32_t base = smem + buf * STAGE_B;
        #pragma unroll
        for (int i = 0; i < 4; i++) {
            int c = tid + i * 256;                 // 0..1023
            int r = c >> 3, kc = c & 7;
            cp16(base + (uint32_t)r * PAD_NT + kc * 16,
                 A + (size_t)(row0 + r) * lda + kk0 + kc * 8);
            if (!TRANSB) {
                cp16(base + TILE_B + (uint32_t)r * PAD_NT + kc * 16,
                     B + (size_t)(col0 + r) * ldb + kk0 + kc * 8);
            } else {
                int rt = c >> 4, nc = c & 15;
                cp16(base + TILE_B + (uint32_t)rt * PAD_TR + nc * 16,
                     B + (size_t)(kk0 + rt) * ldb + col0 + nc * 8);
            }
        }
    };

    load_stage(0, 0); CP_COMMIT();
    if (nk > 1) load_stage(1, 1);
    CP_COMMIT();

    for (int s = 0; s < nk; s++) {
        const int buf = s % 3;
        const uint32_t base = smem + buf * STAGE_B;
        CP_WAIT1();
        __syncthreads();
        if (s + 2 < nk) load_stage(s + 2, (s + 2) % 3);
        CP_COMMIT();

        #pragma unroll
        for (int kk = 0; kk < 4; kk++) {
            uint32_t aF[4][4];
            #pragma unroll
            for (int mt = 0; mt < 4; mt++) {
                uint32_t a = base + (uint32_t)(wm + mt * 16 + (lane & 7) + ((lane >> 3) & 1) * 8) * PAD_NT
                           + kk * 32 + ((lane >> 4) & 1) * 16;
                ldsm4(a, aF[mt][0], aF[mt][1], aF[mt][2], aF[mt][3]);
            }
            uint32_t bF[4][2];
            #pragma unroll
            for (int pr = 0; pr < 2; pr++) {
                uint32_t r0, r1, r2, r3;
                if (!TRANSB) {
                    uint32_t a = base + TILE_B
                               + (uint32_t)(wn + pr * 16 + (lane & 7) + ((lane >> 3) & 1) * 8) * PAD_NT
                               + kk * 32 + ((lane >> 4) & 1) * 16;
                    ldsm4(a, r0, r1, r2, r3);
                } else {
                    uint32_t a = base + TILE_B
                               + (uint32_t)(kk * 16 + (lane & 7) + ((lane >> 4) & 1) * 8) * PAD_TR
                               + (wn + pr * 16) * 2 + ((lane >> 3) & 1) * 16;
                    ldsm4t(a, r0, r1, r2, r3);
                }
                bF[pr * 2 + 0][0] = r0; bF[pr * 2 + 0][1] = r2;
                bF[pr * 2 + 1][0] = r1; bF[pr * 2 + 1][1] = r3;
            }
            #pragma unroll
            for (int mt = 0; mt < 4; mt++)
                #pragma unroll
                for (int nt = 0; nt < 4; nt++)
                    mma16816(acc + (mt * 4 + nt) * 4, aF[mt], bF[nt][0], bF[nt][1]);
        }
    }
}

// Common fp16 epilogue: write 128x128 tile of acc to o[r][c], ld=CC.
__device__ __forceinline__ void epilogue_h(fp16* o, int row0, int col0, const float* acc)
{
    const int wid = threadIdx.x >> 5, lane = threadIdx.x & 31;
    const int rbase = row0 + (wid >> 2) * 64 + (lane >> 2);
    const int cbase = col0 + (wid & 3) * 32 + 2 * (lane & 3);
    #pragma unroll
    for (int mt = 0; mt < 4; mt++)
        #pragma unroll
        for (int nt = 0; nt < 4; nt++) {
            const float* c = acc + (mt * 4 + nt) * 4;
            size_t r = rbase + mt * 16, cc = cbase + nt * 8;
            *(uint32_t*)(o + r * CC + cc) = h2pack(c[0], c[1]);
            *(uint32_t*)(o + (r + 8) * CC + cc) = h2pack(c[2], c[3]);
        }
}

// ---------------------------------------------------------------------------
// Kernel: split-K M partials. grid (8, 8, 4): z = K-slice of 256.
// ---------------------------------------------------------------------------
__global__ __launch_bounds__(256, 2) void m_gemm_split()
{
    const int row0 = blockIdx.y * 128;   // c
    const int col0 = blockIdx.x * 128;   // c'
    const int z = blockIdx.z;
    float acc[64];
    #pragma unroll
    for (int i = 0; i < 64; i++) acc[i] = 0.0f;
    run_gemm<true>(g_WqT + z * 256, CC, g_Wk + (size_t)(z * 256) * CC, CC,
                   256, row0, col0, acc);
    float* o = g_Mp + (size_t)z * CC * CC;
    const int wid = threadIdx.x >> 5, lane = threadIdx.x & 31;
    const int rbase = row0 + (wid >> 2) * 64 + (lane >> 2);
    const int cbase = col0 + (wid & 3) * 32 + 2 * (lane & 3);
    #pragma unroll
    for (int mt = 0; mt < 4; mt++)
        #pragma unroll
        for (int nt = 0; nt < 4; nt++) {
            const float* c = acc + (mt * 4 + nt) * 4;
            size_t r = rbase + mt * 16, cc = cbase + nt * 8;
            *(float2*)(o + r * CC + cc) = make_float2(c[0], c[1]);
            *(float2*)(o + (r + 8) * CC + cc) = make_float2(c[2], c[3]);
        }
}

// ---------------------------------------------------------------------------
// Kernel: reduce 4 fp32 partials -> fp16 M. grid (1024), 256 thr, float4.
// ---------------------------------------------------------------------------
__global__ __launch_bounds__(256) void m_reduce()
{
    const size_t i = (size_t)blockIdx.x * 256 + threadIdx.x;   // float4 index
    float4 a = ((const float4*)g_Mp)[i];
    float4 b = ((const float4*)(g_Mp + CC * CC))[i];
    float4 c = ((const float4*)(g_Mp + 2 * CC * CC))[i];
    float4 d = ((const float4*)(g_Mp + 3 * CC * CC))[i];
    float x0 = a.x + b.x + c.x + d.x;
    float x1 = a.y + b.y + c.y + d.y;
    float x2 = a.z + b.z + c.z + d.z;
    float x3 = a.w + b.w + c.w + d.w;
    uint2 hw;
    hw.x = h2pack(x0, x1); hw.y = h2pack(x2, x3);
    ((uint2*)g_M)[i] = hw;
}

// ---------------------------------------------------------------------------
// Kernel: G = X M. grid (8, 64). TRANSB (M [c][c']).
// ---------------------------------------------------------------------------
__global__ __launch_bounds__(256, 2) void g_gemm()
{
    const int row0 = blockIdx.y * 128;
    const int col0 = blockIdx.x * 128;
    float acc[64];
    #pragma unroll
    for (int i = 0; i < 64; i++) acc[i] = 0.0f;
    run_gemm<true>(g_Xh, CC, g_M, CC, CC, row0, col0, acc);
    epilogue_h(g_Gh, row0, col0, acc);
}

// ---------------------------------------------------------------------------
// Kernel: V = X Wv^T. grid (8, 64). NT.
// ---------------------------------------------------------------------------
__global__ __launch_bounds__(256, 2) void v_gemm()
{
    const int row0 = blockIdx.y * 128;
    const int col0 = blockIdx.x * 128;
    float acc[64];
    #pragma unroll
    for (int i = 0; i < 64; i++) acc[i] = 0.0f;
    run_gemm<false>(g_Xh, CC, g_Wv, CC, CC, row0, col0, acc);
    epilogue_h(g_Vh, row0, col0, acc);
}

// ---------------------------------------------------------------------------
// Kernel: S_b = scale * G_b X_b^T, causal tile skip. grid (16, 16). NT.
// ---------------------------------------------------------------------------
__global__ __launch_bounds__(256, 2) void qk_gemm(int b)
{
    const int row0 = blockIdx.y * 128;
    const int col0 = blockIdx.x * 128;
    if (col0 > row0 + 127) return;
    const size_t xo = (size_t)b * TT * CC;
    float acc[64];
    #pragma unroll
    for (int i = 0; i < 64; i++) acc[i] = 0.0f;
    run_gemm<false>(g_Gh + xo, CC, g_Xh + xo, CC, CC, row0, col0, acc);
    const int wid = threadIdx.x >> 5, lane = threadIdx.x & 31;
    const int rbase = row0 + (wid >> 2) * 64 + (lane >> 2);
    const int cbase = col0 + (wid & 3) * 32 + 2 * (lane & 3);
    float* S = g_S + (size_t)b * TT * TT;
    #pragma unroll
    for (int mt = 0; mt < 4; mt++)
        #pragma unroll
        for (int nt = 0; nt < 4; nt++) {
            const float* c = acc + (mt * 4 + nt) * 4;
            size_t r = rbase + mt * 16, cc = cbase + nt * 8;
            *(float2*)(S + r * TT + cc) = make_float2(c[0] * 0.03125f, c[1] * 0.03125f);
            *(float2*)(S + (r + 8) * TT + cc) = make_float2(c[2] * 0.03125f, c[3] * 0.03125f);
        }
}

// ---------------------------------------------------------------------------
// Kernel: causal softmax -> fp16 P, batch b. grid (2048). Row in registers.
// ---------------------------------------------------------------------------
__global__ __launch_bounds__(256) void softmax_k(int b)
{
    const int t = blockIdx.x;
    const float* row = g_S + ((size_t)b * TT + t) * TT;
    fp16* ph = g_Ph + ((size_t)b * TT + t) * TT;
    const int n = t + 1;
    const int nend = ((t >> 7) + 1) << 7;
    const int tid = threadIdx.x;
    const int lane = tid & 31, wrp = tid >> 5;
    __shared__ float red[8];

    float v[8];
    int cnt = 0;
    float m = -1e30f;
    for (int j = tid; j < n; j += 256) {
        float x = row[j];
        v[cnt++] = x;
        m = fmaxf(m, x);
    }
    #pragma unroll
    for (int o = 16; o > 0; o >>= 1)
        m = fmaxf(m, __shfl_xor_sync(0xffffffffu, m, o));
    if (lane == 0) red[wrp] = m;
    __syncthreads();
    m = red[0];
    #pragma unroll
    for (int w = 1; w < 8; w++) m = fmaxf(m, red[w]);
    __syncthreads();

    float sum = 0.0f;
    #pragma unroll
    for (int c = 0; c < 8; c++)
        if (c < cnt) {
            float e = __expf(v[c] - m);
            v[c] = e;
            sum += e;
        }
    #pragma unroll
    for (int o = 16; o > 0; o >>= 1)
        sum += __shfl_xor_sync(0xffffffffu, sum, o);
    if (lane == 0) red[wrp] = sum;
    __syncthreads();
    sum = red[0];
    #pragma unroll
    for (int w = 1; w < 8; w++) sum += red[w];
    const float inv = 1.0f / sum;

    int c = 0;
    for (int j = tid; j < n; j += 256)
        ph[j] = __float2half_rn(v[c++] * inv);
    const fp16 z = __float2half_rn(0.0f);
    for (int j = n + tid; j < nend; j += 256) ph[j] = z;
}

// ---------------------------------------------------------------------------
// Kernel: O_b = P_b V_b (K truncated causally). grid (8, 16).
// ---------------------------------------------------------------------------
__global__ __launch_bounds__(256, 2) void pv_gemm(float* __restrict__ out, int b)
{
    const int row0 = blockIdx.y * 128;     // query tile
    const int col0 = blockIdx.x * 128;     // channel tile
    const size_t po = (size_t)b * TT * TT;
    const size_t vo = (size_t)b * TT * CC;
    float acc[64];
    #pragma unroll
    for (int i = 0; i < 64; i++) acc[i] = 0.0f;
    run_gemm<true>(g_Ph + po, TT, g_Vh + vo, CC, row0 + 128, row0, col0, acc);
    const int wid = threadIdx.x >> 5, lane = threadIdx.x & 31;
    const int rbase = row0 + (wid >> 2) * 64 + (lane >> 2);
    const int cbase = col0 + (wid & 3) * 32 + 2 * (lane & 3);
    float* O = out + (size_t)b * TT * CC;
    #pragma unroll
    for (int mt = 0; mt < 4; mt++)
        #pragma unroll
        for (int nt = 0; nt < 4; nt++) {
            const float* c = acc + (mt * 4 + nt) * 4;
            size_t r = rbase + mt * 16, cc = cbase + nt * 8;
            *(float2*)(O + r * CC + cc) = make_float2(c[0], c[1]);
            *(float2*)(O + (r + 8) * CC + cc) = make_float2(c[2], c[3]);
        }
}

// ---------------------------------------------------------------------------
// Kernel: fp32 -> fp16 for x. grid (8192), float4.
// ---------------------------------------------------------------------------
__global__ __launch_bounds__(256) void convert_x(const float* __restrict__ x)
{
    const size_t i = (size_t)blockIdx.x * 256 + threadIdx.x;
    float4 v = ((const float4*)x)[i];
    uint2 hw;
    hw.x = h2pack(v.x, v.y); hw.y = h2pack(v.z, v.w);
    ((uint2*)g_Xh)[i] = hw;
}

// ---------------------------------------------------------------------------
// Kernel: W prep, fused. Blocks [0,2048): convert Wk/Wv (float4).
// Blocks [2048,3072): transpose+convert Wq -> WqT (32x32 smem tile).
// ---------------------------------------------------------------------------
__global__ __launch_bounds__(256) void prep_w(
    const float* __restrict__ wq, const float* __restrict__ wk,
    const float* __restrict__ wv)
{
    if (blockIdx.x < 2048) {
        const size_t i = (size_t)blockIdx.x * 256 + threadIdx.x;
        const int w = (int)(i / 262144);
        const size_t off = i - (size_t)w * 262144;
        const float* src = (w == 0) ? wk : wv;
        fp16* dst = (w == 0) ? g_Wk : g_Wv;
        float4 v = ((const float4*)src)[off];
        uint2 hw;
        hw.x = h2pack(v.x, v.y); hw.y = h2pack(v.z, v.w);
        ((uint2*)dst)[off] = hw;
    } else {
        __shared__ float tbuf[32][33];
        const int t = blockIdx.x - 2048;
        const int c0 = (t & 31) * 32, d0 = (t >> 5) * 32;
        const int tx = threadIdx.x & 31, ty = threadIdx.x >> 5;
        #pragma unroll
        for (int i = 0; i < 4; i++)
            tbuf[ty + i * 8][tx] = wq[(size_t)(d0 + ty + i * 8) * CC + c0 + tx];
        __syncthreads();
        #pragma unroll
        for (int i = 0; i < 4; i++)
            g_WqT[(size_t)(c0 + ty + i * 8) * CC + d0 + tx] =
                __float2half_rn(tbuf[tx][ty + i * 8]);
    }
}

// ---------------------------------------------------------------------------
extern "C" void kernel_launch(void* const* d_in, const int* in_sizes, int n_in,
                              void* d_out, int out_size)
{
    const float* x  = (const float*)d_in[0];
    const float* Wq = (const float*)d_in[1];
    const float* Wk = (const float*)d_in[2];
    const float* Wv = (const float*)d_in[3];
    float* out = (float*)d_out;

    // One-time resource setup (first call is the uncaptured correctness run).
    // R10's passing footprint: 3 created streams, 7 events, <=18 graph nodes.
    static cudaStream_t st[3];
    static cudaEvent_t  evRoot, evW, evM, evG, evJ[3];
    static bool inited = false;
    if (!inited) {
        for (int i = 0; i < 3; i++)
            cudaStreamCreateWithFlags(&st[i], cudaStreamNonBlocking);
        cudaEventCreateWithFlags(&evRoot, cudaEventDisableTiming);
        cudaEventCreateWithFlags(&evW, cudaEventDisableTiming);
        cudaEventCreateWithFlags(&evM, cudaEventDisableTiming);
        cudaEventCreateWithFlags(&evG, cudaEventDisableTiming);
        for (int i = 0; i < 3; i++)
            cudaEventCreateWithFlags(&evJ[i], cudaEventDisableTiming);
        cudaFuncSetAttribute(m_gemm_split, cudaFuncAttributeMaxDynamicSharedMemorySize, SMEM_BYTES);
        cudaFuncSetAttribute(g_gemm,  cudaFuncAttributeMaxDynamicSharedMemorySize, SMEM_BYTES);
        cudaFuncSetAttribute(v_gemm,  cudaFuncAttributeMaxDynamicSharedMemorySize, SMEM_BYTES);
        cudaFuncSetAttribute(qk_gemm, cudaFuncAttributeMaxDynamicSharedMemorySize, SMEM_BYTES);
        cudaFuncSetAttribute(pv_gemm, cudaFuncAttributeMaxDynamicSharedMemorySize, SMEM_BYTES);
        inited = true;
    }

    // Root fork from the capture-origin stream (legal capture entry for st[]).
    cudaEventRecord(evRoot, 0);

    // W-side chain on st[2]: prep (convert Wk/Wv + transpose Wq) -> M chain.
    cudaStreamWaitEvent(st[2], evRoot, 0);
    prep_w<<<3072, 256, 0, st[2]>>>(Wq, Wk, Wv);
    cudaEventRecord(evW, st[2]);                    // Wv ready
    m_gemm_split<<<dim3(8, 8, 4), 256, SMEM_BYTES, st[2]>>>();
    m_reduce<<<1024, 256, 0, st[2]>>>();
    cudaEventRecord(evM, st[2]);                    // M ready

    // Main: X convert (concurrent with W chain), then V, then G.
    convert_x<<<8192, 256>>>(x);
    cudaStreamWaitEvent(0, evW, 0);
    v_gemm<<<dim3(8, 64), 256, SMEM_BYTES>>>();
    cudaStreamWaitEvent(0, evM, 0);
    g_gemm<<<dim3(8, 64), 256, SMEM_BYTES>>>();
    cudaEventRecord(evG, 0);

    // Batch 0 chain on main.
    qk_gemm<<<dim3(16, 16), 256, SMEM_BYTES>>>(0);
    softmax_k<<<2048, 256>>>(0);
    pv_gemm<<<dim3(8, 16), 256, SMEM_BYTES>>>(out, 0);

    // Batches 1..3 on side streams (st[2] reused after its W chain).
    for (int i = 0; i < 3; i++) {
        const int b = i + 1;
        cudaStreamWaitEvent(st[i], evG, 0);
        qk_gemm<<<dim3(16, 16), 256, SMEM_BYTES, st[i]>>>(b);
        softmax_k<<<2048, 256, 0, st[i]>>>(b);
        pv_gemm<<<dim3(8, 16), 256, SMEM_BYTES, st[i]>>>(out, b);
        cudaEventRecord(evJ[i], st[i]);
    }
    // Join back into the capture-origin stream.
    for (int i = 0; i < 3; i++)
        cudaStreamWaitEvent(0, evJ[i], 0);
}

// round 14
// speedup vs baseline: 8.1180x; 1.0614x over previous
#include <cuda_runtime.h>
#include <cuda_fp16.h>
#include <stdint.h>
#include <math.h>

#define BB 4
#define TT 2048
#define CC 1024
#define NTOK 8192   // BB*TT

typedef __half fp16;

// ---------------- scratch (__device__ globals; allocation-free rule) -------
__device__ __align__(256) fp16 g_Xh [NTOK * CC];
__device__ __align__(256) fp16 g_Wk [CC * CC];
__device__ __align__(256) fp16 g_Wv [CC * CC];
__device__ __align__(256) fp16 g_WqT[CC * CC];       // Wq transposed [c][d]
__device__ __align__(256) float g_Mp[4 * CC * CC];   // split-K partials (fp32)
__device__ __align__(256) fp16 g_M  [CC * CC];       // Wq^T Wk, [c][c']
__device__ __align__(256) fp16 g_Gh [NTOK * CC];     // X M
__device__ __align__(256) fp16 g_Vh [NTOK * CC];     // [token][channel]
__device__ __align__(256) float g_S[(size_t)BB * TT * TT];
__device__ __align__(256) fp16 g_Ph[(size_t)BB * TT * TT];

// ---------------- helpers ---------------------------------------------------
__device__ __forceinline__ uint32_t smem_u32(const void* p) {
    uint32_t a;
    asm("{ .reg .u64 t; cvta.to.shared.u64 t, %1; cvt.u32.u64 %0, t; }" : "=r"(a) : "l"(p));
    return a;
}
__device__ __forceinline__ void cp16(uint32_t s, const void* g) {
    asm volatile("cp.async.cg.shared.global [%0], [%1], 16;" :: "r"(s), "l"(g));
}
#define CP_COMMIT() asm volatile("cp.async.commit_group;" ::: "memory")
#define CP_WAIT1()  asm volatile("cp.async.wait_group 1;" ::: "memory")

__device__ __forceinline__ void ldsm4(uint32_t a, uint32_t& r0, uint32_t& r1,
                                      uint32_t& r2, uint32_t& r3) {
    asm volatile("ldmatrix.sync.aligned.m8n8.x4.shared.b16 {%0,%1,%2,%3}, [%4];"
                 : "=r"(r0), "=r"(r1), "=r"(r2), "=r"(r3) : "r"(a));
}
__device__ __forceinline__ void ldsm4t(uint32_t a, uint32_t& r0, uint32_t& r1,
                                       uint32_t& r2, uint32_t& r3) {
    asm volatile("ldmatrix.sync.aligned.m8n8.x4.trans.shared.b16 {%0,%1,%2,%3}, [%4];"
                 : "=r"(r0), "=r"(r1), "=r"(r2), "=r"(r3) : "r"(a));
}
__device__ __forceinline__ void mma16816(float* c, const uint32_t* a, uint32_t b0, uint32_t b1) {
    asm volatile(
        "mma.sync.aligned.m16n8k16.row.col.f32.f16.f16.f32 "
        "{%0,%1,%2,%3}, {%4,%5,%6,%7}, {%8,%9}, {%0,%1,%2,%3};"
        : "+f"(c[0]), "+f"(c[1]), "+f"(c[2]), "+f"(c[3])
        : "r"(a[0]), "r"(a[1]), "r"(a[2]), "r"(a[3]), "r"(b0), "r"(b1));
}
__device__ __forceinline__ uint32_t h2pack(float a, float b) {
    __half2 h = __floats2half2_rn(a, b);
    return *reinterpret_cast<uint32_t*>(&h);
}

// smem: 3 stages x 2 tiles (A, B) x 18432B = 110592B  -> 2 CTAs/SM
#define TILE_B  18432
#define STAGE_B (2 * TILE_B)
#define NSTAGE  3
#define SMEM_BYTES (NSTAGE * STAGE_B)
#define PAD_NT 144   // bytes per 64-elem k-row (128B + 16 pad)
#define PAD_TR 272   // bytes per 128-elem n-row (256B + 16 pad)

extern __shared__ char dsm[];

// ---------------------------------------------------------------------------
// 128x128 tile fp16 GEMM: C = A * B^T(NT, B [n][k]) or A * B(TRANSB, B [k][n]).
// 3-stage cp.async pipeline, single barrier per stage.
// ---------------------------------------------------------------------------
template <bool TRANSB>
__device__ __forceinline__ void run_gemm(
    const fp16* __restrict__ A, int lda,
    const fp16* __restrict__ B, int ldb,
    int Ktot, int row0, int col0, float* acc)
{
    const int tid = threadIdx.x;
    const int wid = tid >> 5, lane = tid & 31;
    const int wm = (wid >> 2) * 64, wn = (wid & 3) * 32;
    const uint32_t smem = smem_u32(dsm);
    const int nk = Ktot >> 6;

    auto load_stage = [&](int s, int buf) {
        const int kk0 = s << 6;
        const uint32_t base = smem + buf * STAGE_B;
        #pragma unroll
        for (int i = 0; i < 4; i++) {
            int c = tid + i * 256;                 // 0..1023
            int r = c >> 3, kc = c & 7;
            cp16(base + (uint32_t)r * PAD_NT + kc * 16,
                 A + (size_t)(row0 + r) * lda + kk0 + kc * 8);
            if (!TRANSB) {
                cp16(base + TILE_B + (uint32_t)r * PAD_NT + kc * 16,
                     B + (size_t)(col0 + r) * ldb + kk0 + kc * 8);
            } else {
                int rt = c >> 4, nc = c & 15;
                cp16(base + TILE_B + (uint32_t)rt * PAD_TR + nc * 16,
                     B + (size_t)(kk0 + rt) * ldb + col0 + nc * 8);
            }
        }
    };

    load_stage(0, 0); CP_COMMIT();
    if (nk > 1) load_stage(1, 1);
    CP_COMMIT();

    for (int s = 0; s < nk; s++) {
        const int buf = s % 3;
        const uint32_t base = smem + buf * STAGE_B;
        CP_WAIT1();
        __syncthreads();
        if (s + 2 < nk) load_stage(s + 2, (s + 2) % 3);
        CP_COMMIT();

        #pragma unroll
        for (int kk = 0; kk < 4; kk++) {
            uint32_t aF[4][4];
            #pragma unroll
            for (int mt = 0; mt < 4; mt++) {
                uint32_t a = base + (uint32_t)(wm + mt * 16 + (lane & 7) + ((lane >> 3) & 1) * 8) * PAD_NT
                           + kk * 32 + ((lane >> 4) & 1) * 16;
                ldsm4(a, aF[mt][0], aF[mt][1], aF[mt][2], aF[mt][3]);
            }
            uint32_t bF[4][2];
            #pragma unroll
            for (int pr = 0; pr < 2; pr++) {
                uint32_t r0, r1, r2, r3;
                if (!TRANSB) {
                    uint32_t a = base + TILE_B
                               + (uint32_t)(wn + pr * 16 + (lane & 7) + ((lane >> 3) & 1) * 8) * PAD_NT
                               + kk * 32 + ((lane >> 4) & 1) * 16;
                    ldsm4(a, r0, r1, r2, r3);
                } else {
                    uint32_t a = base + TILE_B
                               + (uint32_t)(kk * 16 + (lane & 7) + ((lane >> 4) & 1) * 8) * PAD_TR
                               + (wn + pr * 16) * 2 + ((lane >> 3) & 1) * 16;
                    ldsm4t(a, r0, r1, r2, r3);
                }
                bF[pr * 2 + 0][0] = r0; bF[pr * 2 + 0][1] = r2;
                bF[pr * 2 + 1][0] = r1; bF[pr * 2 + 1][1] = r3;
            }
            #pragma unroll
            for (int mt = 0; mt < 4; mt++)
                #pragma unroll
                for (int nt = 0; nt < 4; nt++)
                    mma16816(acc + (mt * 4 + nt) * 4, aF[mt], bF[nt][0], bF[nt][1]);
        }
    }
}

// Common fp16 epilogue: write 128x128 tile of acc to o[r][c], ld=CC.
__device__ __forceinline__ void epilogue_h(fp16* o, int row0, int col0, const float* acc)
{
    const int wid = threadIdx.x >> 5, lane = threadIdx.x & 31;
    const int rbase = row0 + (wid >> 2) * 64 + (lane >> 2);
    const int cbase = col0 + (wid & 3) * 32 + 2 * (lane & 3);
    #pragma unroll
    for (int mt = 0; mt < 4; mt++)
        #pragma unroll
        for (int nt = 0; nt < 4; nt++) {
            const float* c = acc + (mt * 4 + nt) * 4;
            size_t r = rbase + mt * 16, cc = cbase + nt * 8;
            *(uint32_t*)(o + r * CC + cc) = h2pack(c[0], c[1]);
            *(uint32_t*)(o + (r + 8) * CC + cc) = h2pack(c[2], c[3]);
        }
}

// ---------------------------------------------------------------------------
// Kernel: split-K M partials. grid (8, 8, 4): z = K-slice of 256.
// ---------------------------------------------------------------------------
__global__ __launch_bounds__(256, 2) void m_gemm_split()
{
    const int row0 = blockIdx.y * 128;   // c
    const int col0 = blockIdx.x * 128;   // c'
    const int z = blockIdx.z;
    float acc[64];
    #pragma unroll
    for (int i = 0; i < 64; i++) acc[i] = 0.0f;
    run_gemm<true>(g_WqT + z * 256, CC, g_Wk + (size_t)(z * 256) * CC, CC,
                   256, row0, col0, acc);
    float* o = g_Mp + (size_t)z * CC * CC;
    const int wid = threadIdx.x >> 5, lane = threadIdx.x & 31;
    const int rbase = row0 + (wid >> 2) * 64 + (lane >> 2);
    const int cbase = col0 + (wid & 3) * 32 + 2 * (lane & 3);
    #pragma unroll
    for (int mt = 0; mt < 4; mt++)
        #pragma unroll
        for (int nt = 0; nt < 4; nt++) {
            const float* c = acc + (mt * 4 + nt) * 4;
            size_t r = rbase + mt * 16, cc = cbase + nt * 8;
            *(float2*)(o + r * CC + cc) = make_float2(c[0], c[1]);
            *(float2*)(o + (r + 8) * CC + cc) = make_float2(c[2], c[3]);
        }
}

// ---------------------------------------------------------------------------
// Kernel: reduce 4 fp32 partials -> fp16 M. grid (1024), 256 thr, float4.
// ---------------------------------------------------------------------------
__global__ __launch_bounds__(256) void m_reduce()
{
    const size_t i = (size_t)blockIdx.x * 256 + threadIdx.x;   // float4 index
    float4 a = ((const float4*)g_Mp)[i];
    float4 b = ((const float4*)(g_Mp + CC * CC))[i];
    float4 c = ((const float4*)(g_Mp + 2 * CC * CC))[i];
    float4 d = ((const float4*)(g_Mp + 3 * CC * CC))[i];
    float x0 = a.x + b.x + c.x + d.x;
    float x1 = a.y + b.y + c.y + d.y;
    float x2 = a.z + b.z + c.z + d.z;
    float x3 = a.w + b.w + c.w + d.w;
    uint2 hw;
    hw.x = h2pack(x0, x1); hw.y = h2pack(x2, x3);
    ((uint2*)g_M)[i] = hw;
}

// ---------------------------------------------------------------------------
// Kernel: fused per-batch V and G. grid (8, 16, 2).
// z=0: V_b = X_b Wv^T (NT). z=1: G_b = X_b M (TRANSB).
// ---------------------------------------------------------------------------
__global__ __launch_bounds__(256, 2) void gv_gemm(int b)
{
    const int row0 = b * TT + blockIdx.y * 128;
    const int col0 = blockIdx.x * 128;
    float acc[64];
    #pragma unroll
    for (int i = 0; i < 64; i++) acc[i] = 0.0f;
    if (blockIdx.z == 0) {
        run_gemm<false>(g_Xh, CC, g_Wv, CC, CC, row0, col0, acc);
        epilogue_h(g_Vh, row0, col0, acc);
    } else {
        run_gemm<true>(g_Xh, CC, g_M, CC, CC, row0, col0, acc);
        epilogue_h(g_Gh, row0, col0, acc);
    }
}

// ---------------------------------------------------------------------------
// Kernel: S_b = scale * G_b X_b^T, causal tile skip. grid (16, 16). NT.
// ---------------------------------------------------------------------------
__global__ __launch_bounds__(256, 2) void qk_gemm(int b)
{
    const int row0 = blockIdx.y * 128;
    const int col0 = blockIdx.x * 128;
    if (col0 > row0 + 127) return;
    const size_t xo = (size_t)b * TT * CC;
    float acc[64];
    #pragma unroll
    for (int i = 0; i < 64; i++) acc[i] = 0.0f;
    run_gemm<false>(g_Gh + xo, CC, g_Xh + xo, CC, CC, row0, col0, acc);
    const int wid = threadIdx.x >> 5, lane = threadIdx.x & 31;
    const int rbase = row0 + (wid >> 2) * 64 + (lane >> 2);
    const int cbase = col0 + (wid & 3) * 32 + 2 * (lane & 3);
    float* S = g_S + (size_t)b * TT * TT;
    #pragma unroll
    for (int mt = 0; mt < 4; mt++)
        #pragma unroll
        for (int nt = 0; nt < 4; nt++) {
            const float* c = acc + (mt * 4 + nt) * 4;
            size_t r = rbase + mt * 16, cc = cbase + nt * 8;
            *(float2*)(S + r * TT + cc) = make_float2(c[0] * 0.03125f, c[1] * 0.03125f);
            *(float2*)(S + (r + 8) * TT + cc) = make_float2(c[2] * 0.03125f, c[3] * 0.03125f);
        }
}

// ---------------------------------------------------------------------------
// Kernel: causal softmax -> fp16 P, batch b. grid (2048). Row in registers.
// ---------------------------------------------------------------------------
__global__ __launch_bounds__(256) void softmax_k(int b)
{
    const int t = blockIdx.x;
    const float* row = g_S + ((size_t)b * TT + t) * TT;
    fp16* ph = g_Ph + ((size_t)b * TT + t) * TT;
    const int n = t + 1;
    const int nend = ((t >> 7) + 1) << 7;
    const int tid = threadIdx.x;
    const int lane = tid & 31, wrp = tid >> 5;
    __shared__ float red[8];

    float v[8];
    int cnt = 0;
    float m = -1e30f;
    for (int j = tid; j < n; j += 256) {
        float x = row[j];
        v[cnt++] = x;
        m = fmaxf(m, x);
    }
    #pragma unroll
    for (int o = 16; o > 0; o >>= 1)
        m = fmaxf(m, __shfl_xor_sync(0xffffffffu, m, o));
    if (lane == 0) red[wrp] = m;
    __syncthreads();
    m = red[0];
    #pragma unroll
    for (int w = 1; w < 8; w++) m = fmaxf(m, red[w]);
    __syncthreads();

    float sum = 0.0f;
    #pragma unroll
    for (int c = 0; c < 8; c++)
        if (c < cnt) {
            float e = __expf(v[c] - m);
            v[c] = e;
            sum += e;
        }
    #pragma unroll
    for (int o = 16; o > 0; o >>= 1)
        sum += __shfl_xor_sync(0xffffffffu, sum, o);
    if (lane == 0) red[wrp] = sum;
    __syncthreads();
    sum = red[0];
    #pragma unroll
    for (int w = 1; w < 8; w++) sum += red[w];
    const float inv = 1.0f / sum;

    int c = 0;
    for (int j = tid; j < n; j += 256)
        ph[j] = __float2half_rn(v[c++] * inv);
    const fp16 z = __float2half_rn(0.0f);
    for (int j = n + tid; j < nend; j += 256) ph[j] = z;
}

// ---------------------------------------------------------------------------
// Kernel: O_b = P_b V_b (K truncated causally). grid (8, 16).
// ---------------------------------------------------------------------------
__global__ __launch_bounds__(256, 2) void pv_gemm(float* __restrict__ out, int b)
{
    const int row0 = blockIdx.y * 128;     // query tile
    const int col0 = blockIdx.x * 128;     // channel tile
    const size_t po = (size_t)b * TT * TT;
    const size_t vo = (size_t)b * TT * CC;
    float acc[64];
    #pragma unroll
    for (int i = 0; i < 64; i++) acc[i] = 0.0f;
    run_gemm<true>(g_Ph + po, TT, g_Vh + vo, CC, row0 + 128, row0, col0, acc);
    const int wid = threadIdx.x >> 5, lane = threadIdx.x & 31;
    const int rbase = row0 + (wid >> 2) * 64 + (lane >> 2);
    const int cbase = col0 + (wid & 3) * 32 + 2 * (lane & 3);
    float* O = out + (size_t)b * TT * CC;
    #pragma unroll
    for (int mt = 0; mt < 4; mt++)
        #pragma unroll
        for (int nt = 0; nt < 4; nt++) {
            const float* c = acc + (mt * 4 + nt) * 4;
            size_t r = rbase + mt * 16, cc = cbase + nt * 8;
            *(float2*)(O + r * CC + cc) = make_float2(c[0], c[1]);
            *(float2*)(O + (r + 8) * CC + cc) = make_float2(c[2], c[3]);
        }
}

// ---------------------------------------------------------------------------
// Kernel: fp32 -> fp16 for x. grid (8192), float4.
// ---------------------------------------------------------------------------
__global__ __launch_bounds__(256) void convert_x(const float* __restrict__ x)
{
    const size_t i = (size_t)blockIdx.x * 256 + threadIdx.x;
    float4 v = ((const float4*)x)[i];
    uint2 hw;
    hw.x = h2pack(v.x, v.y); hw.y = h2pack(v.z, v.w);
    ((uint2*)g_Xh)[i] = hw;
}

// ---------------------------------------------------------------------------
// Kernel: W prep, fused. Blocks [0,2048): convert Wk/Wv (float4).
// Blocks [2048,3072): transpose+convert Wq -> WqT (32x32 smem tile).
// ---------------------------------------------------------------------------
__global__ __launch_bounds__(256) void prep_w(
    const float* __restrict__ wq, const float* __restrict__ wk,
    const float* __restrict__ wv)
{
    if (blockIdx.x < 2048) {
        const size_t i = (size_t)blockIdx.x * 256 + threadIdx.x;
        const int w = (int)(i / 262144);
        const size_t off = i - (size_t)w * 262144;
        const float* src = (w == 0) ? wk : wv;
        fp16* dst = (w == 0) ? g_Wk : g_Wv;
        float4 v = ((const float4*)src)[off];
        uint2 hw;
        hw.x = h2pack(v.x, v.y); hw.y = h2pack(v.z, v.w);
        ((uint2*)dst)[off] = hw;
    } else {
        __shared__ float tbuf[32][33];
        const int t = blockIdx.x - 2048;
        const int c0 = (t & 31) * 32, d0 = (t >> 5) * 32;
        const int tx = threadIdx.x & 31, ty = threadIdx.x >> 5;
        #pragma unroll
        for (int i = 0; i < 4; i++)
            tbuf[ty + i * 8][tx] = wq[(size_t)(d0 + ty + i * 8) * CC + c0 + tx];
        __syncthreads();
        #pragma unroll
        for (int i = 0; i < 4; i++)
            g_WqT[(size_t)(c0 + ty + i * 8) * CC + d0 + tx] =
                __float2half_rn(tbuf[tx][ty + i * 8]);
    }
}

// ---------------------------------------------------------------------------
extern "C" void kernel_launch(void* const* d_in, const int* in_sizes, int n_in,
                              void* d_out, int out_size)
{
    const float* x  = (const float*)d_in[0];
    const float* Wq = (const float*)d_in[1];
    const float* Wk = (const float*)d_in[2];
    const float* Wv = (const float*)d_in[3];
    float* out = (float*)d_out;

    // One-time resource setup (first call is the uncaptured correctness run).
    // Footprint: 3 created streams, 6 events, 20 kernel nodes.
    static cudaStream_t st[3];
    static cudaEvent_t  evRoot, evX, evM, evJ[3];
    static bool inited = false;
    if (!inited) {
        for (int i = 0; i < 3; i++)
            cudaStreamCreateWithFlags(&st[i], cudaStreamNonBlocking);
        cudaEventCreateWithFlags(&evRoot, cudaEventDisableTiming);
        cudaEventCreateWithFlags(&evX, cudaEventDisableTiming);
        cudaEventCreateWithFlags(&evM, cudaEventDisableTiming);
        for (int i = 0; i < 3; i++)
            cudaEventCreateWithFlags(&evJ[i], cudaEventDisableTiming);
        cudaFuncSetAttribute(m_gemm_split, cudaFuncAttributeMaxDynamicSharedMemorySize, SMEM_BYTES);
        cudaFuncSetAttribute(gv_gemm, cudaFuncAttributeMaxDynamicSharedMemorySize, SMEM_BYTES);
        cudaFuncSetAttribute(qk_gemm, cudaFuncAttributeMaxDynamicSharedMemorySize, SMEM_BYTES);
        cudaFuncSetAttribute(pv_gemm, cudaFuncAttributeMaxDynamicSharedMemorySize, SMEM_BYTES);
        inited = true;
    }

    // Root fork from the capture-origin stream.
    cudaEventRecord(evRoot, 0);

    // W-side chain on st[2]: prep (Wk/Wv convert + Wq transpose) -> M chain.
    // evM implies prep_w complete (in-stream), so gv needs only evM + evX.
    cudaStreamWaitEvent(st[2], evRoot, 0);
    prep_w<<<3072, 256, 0, st[2]>>>(Wq, Wk, Wv);
    m_gemm_split<<<dim3(8, 8, 4), 256, SMEM_BYTES, st[2]>>>();
    m_reduce<<<1024, 256, 0, st[2]>>>();
    cudaEventRecord(evM, st[2]);                    // M (and Wv) ready

    // X conversion on the capture-origin stream (concurrent with W chain).
    convert_x<<<8192, 256>>>(x);
    cudaEventRecord(evX, 0);

    // Four independent per-batch chains: GV_b -> QK_b -> softmax_b -> PV_b.
    // Batch 0 rides the capture-origin stream; 1..3 on side streams
    // (st[2] reused after its W chain; in-stream ordering covers evM there).
    cudaStreamWaitEvent(0, evM, 0);
    gv_gemm<<<dim3(8, 16, 2), 256, SMEM_BYTES>>>(0);
    qk_gemm<<<dim3(16, 16), 256, SMEM_BYTES>>>(0);
    softmax_k<<<2048, 256>>>(0);
    pv_gemm<<<dim3(8, 16), 256, SMEM_BYTES>>>(out, 0);

    for (int i = 0; i < 3; i++) {
        const int b = i + 1;
        cudaStreamWaitEvent(st[i], evX, 0);
        if (i != 2) cudaStreamWaitEvent(st[i], evM, 0);   // st[2]: in-stream
        gv_gemm<<<dim3(8, 16, 2), 256, SMEM_BYTES, st[i]>>>(b);
        qk_gemm<<<dim3(16, 16), 256, SMEM_BYTES, st[i]>>>(b);
        softmax_k<<<2048, 256, 0, st[i]>>>(b);
        pv_gemm<<<dim3(8, 16), 256, SMEM_BYTES, st[i]>>>(out, b);
        cudaEventRecord(evJ[i], st[i]);
    }
    // Join back into the capture-origin stream.
    for (int i = 0; i < 3; i++)
        cudaStreamWaitEvent(0, evJ[i], 0);
}

// round 16
// speedup vs baseline: 8.3666x; 1.0306x over previous
#include <cuda_runtime.h>
#include <cuda_fp16.h>
#include <stdint.h>
#include <math.h>

#define BB 4
#define TT 2048
#define CC 1024
#define NTOK 8192   // BB*TT

typedef __half fp16;

// ---------------- scratch (__device__ globals; allocation-free rule) -------
__device__ __align__(256) fp16 g_Xh [NTOK * CC];
__device__ __align__(256) fp16 g_Wk [CC * CC];
__device__ __align__(256) fp16 g_Wv [CC * CC];
__device__ __align__(256) fp16 g_WqT[CC * CC];       // Wq transposed [c][d]
__device__ __align__(256) float g_Mp[4 * CC * CC];   // split-K partials (fp32)
__device__ __align__(256) fp16 g_M  [CC * CC];       // Wq^T Wk, [c][c']
__device__ __align__(256) fp16 g_Gh [NTOK * CC];     // X M
__device__ __align__(256) fp16 g_Vh [NTOK * CC];     // [token][channel]
__device__ __align__(256) float g_S[(size_t)BB * TT * TT];
__device__ __align__(256) fp16 g_Ph[(size_t)BB * TT * TT];

// ---------------- helpers ---------------------------------------------------
__device__ __forceinline__ uint32_t smem_u32(const void* p) {
    uint32_t a;
    asm("{ .reg .u64 t; cvta.to.shared.u64 t, %1; cvt.u32.u64 %0, t; }" : "=r"(a) : "l"(p));
    return a;
}
__device__ __forceinline__ void cp16(uint32_t s, const void* g) {
    asm volatile("cp.async.cg.shared.global [%0], [%1], 16;" :: "r"(s), "l"(g));
}
#define CP_COMMIT() asm volatile("cp.async.commit_group;" ::: "memory")
#define CP_WAIT1()  asm volatile("cp.async.wait_group 1;" ::: "memory")

__device__ __forceinline__ void ldsm4(uint32_t a, uint32_t& r0, uint32_t& r1,
                                      uint32_t& r2, uint32_t& r3) {
    asm volatile("ldmatrix.sync.aligned.m8n8.x4.shared.b16 {%0,%1,%2,%3}, [%4];"
                 : "=r"(r0), "=r"(r1), "=r"(r2), "=r"(r3) : "r"(a));
}
__device__ __forceinline__ void ldsm4t(uint32_t a, uint32_t& r0, uint32_t& r1,
                                       uint32_t& r2, uint32_t& r3) {
    asm volatile("ldmatrix.sync.aligned.m8n8.x4.trans.shared.b16 {%0,%1,%2,%3}, [%4];"
                 : "=r"(r0), "=r"(r1), "=r"(r2), "=r"(r3) : "r"(a));
}
__device__ __forceinline__ void mma16816(float* c, const uint32_t* a, uint32_t b0, uint32_t b1) {
    asm volatile(
        "mma.sync.aligned.m16n8k16.row.col.f32.f16.f16.f32 "
        "{%0,%1,%2,%3}, {%4,%5,%6,%7}, {%8,%9}, {%0,%1,%2,%3};"
        : "+f"(c[0]), "+f"(c[1]), "+f"(c[2]), "+f"(c[3])
        : "r"(a[0]), "r"(a[1]), "r"(a[2]), "r"(a[3]), "r"(b0), "r"(b1));
}
__device__ __forceinline__ uint32_t h2pack(float a, float b) {
    __half2 h = __floats2half2_rn(a, b);
    return *reinterpret_cast<uint32_t*>(&h);
}

// smem: 3 stages x 2 tiles (A, B) x 18432B = 110592B  -> 2 CTAs/SM
#define TILE_B  18432
#define STAGE_B (2 * TILE_B)
#define NSTAGE  3
#define SMEM_BYTES (NSTAGE * STAGE_B)
#define PAD_NT 144   // bytes per 64-elem k-row (128B + 16 pad)
#define PAD_TR 272   // bytes per 128-elem n-row (256B + 16 pad)

extern __shared__ char dsm[];

// ---------------------------------------------------------------------------
// 128x128 tile fp16 GEMM: C = A * B^T(NT, B [n][k]) or A * B(TRANSB, B [k][n]).
// 3-stage cp.async pipeline, single barrier per stage.
// ---------------------------------------------------------------------------
template <bool TRANSB>
__device__ __forceinline__ void run_gemm(
    const fp16* __restrict__ A, int lda,
    const fp16* __restrict__ B, int ldb,
    int Ktot, int row0, int col0, float* acc)
{
    const int tid = threadIdx.x;
    const int wid = tid >> 5, lane = tid & 31;
    const int wm = (wid >> 2) * 64, wn = (wid & 3) * 32;
    const uint32_t smem = smem_u32(dsm);
    const int nk = Ktot >> 6;

    auto load_stage = [&](int s, int buf) {
        const int kk0 = s << 6;
        const uint32_t base = smem + buf * STAGE_B;
        #pragma unroll
        for (int i = 0; i < 4; i++) {
            int c = tid + i * 256;                 // 0..1023
            int r = c >> 3, kc = c & 7;
            cp16(base + (uint32_t)r * PAD_NT + kc * 16,
                 A + (size_t)(row0 + r) * lda + kk0 + kc * 8);
            if (!TRANSB) {
                cp16(base + TILE_B + (uint32_t)r * PAD_NT + kc * 16,
                     B + (size_t)(col0 + r) * ldb + kk0 + kc * 8);
            } else {
                int rt = c >> 4, nc = c & 15;
                cp16(base + TILE_B + (uint32_t)rt * PAD_TR + nc * 16,
                     B + (size_t)(kk0 + rt) * ldb + col0 + nc * 8);
            }
        }
    };

    load_stage(0, 0); CP_COMMIT();
    if (nk > 1) load_stage(1, 1);
    CP_COMMIT();

    for (int s = 0; s < nk; s++) {
        const int buf = s % 3;
        const uint32_t base = smem + buf * STAGE_B;
        CP_WAIT1();
        __syncthreads();
        if (s + 2 < nk) load_stage(s + 2, (s + 2) % 3);
        CP_COMMIT();

        #pragma unroll
        for (int kk = 0; kk < 4; kk++) {
            uint32_t aF[4][4];
            #pragma unroll
            for (int mt = 0; mt < 4; mt++) {
                uint32_t a = base + (uint32_t)(wm + mt * 16 + (lane & 7) + ((lane >> 3) & 1) * 8) * PAD_NT
                           + kk * 32 + ((lane >> 4) & 1) * 16;
                ldsm4(a, aF[mt][0], aF[mt][1], aF[mt][2], aF[mt][3]);
            }
            uint32_t bF[4][2];
            #pragma unroll
            for (int pr = 0; pr < 2; pr++) {
                uint32_t r0, r1, r2, r3;
                if (!TRANSB) {
                    uint32_t a = base + TILE_B
                               + (uint32_t)(wn + pr * 16 + (lane & 7) + ((lane >> 3) & 1) * 8) * PAD_NT
                               + kk * 32 + ((lane >> 4) & 1) * 16;
                    ldsm4(a, r0, r1, r2, r3);
                } else {
                    uint32_t a = base + TILE_B
                               + (uint32_t)(kk * 16 + (lane & 7) + ((lane >> 4) & 1) * 8) * PAD_TR
                               + (wn + pr * 16) * 2 + ((lane >> 3) & 1) * 16;
                    ldsm4t(a, r0, r1, r2, r3);
                }
                bF[pr * 2 + 0][0] = r0; bF[pr * 2 + 0][1] = r2;
                bF[pr * 2 + 1][0] = r1; bF[pr * 2 + 1][1] = r3;
            }
            #pragma unroll
            for (int mt = 0; mt < 4; mt++)
                #pragma unroll
                for (int nt = 0; nt < 4; nt++)
                    mma16816(acc + (mt * 4 + nt) * 4, aF[mt], bF[nt][0], bF[nt][1]);
        }
    }
}

// Common fp16 epilogue: write 128x128 tile of acc to o[r][c], ld=CC.
__device__ __forceinline__ void epilogue_h(fp16* o, int row0, int col0, const float* acc)
{
    const int wid = threadIdx.x >> 5, lane = threadIdx.x & 31;
    const int rbase = row0 + (wid >> 2) * 64 + (lane >> 2);
    const int cbase = col0 + (wid & 3) * 32 + 2 * (lane & 3);
    #pragma unroll
    for (int mt = 0; mt < 4; mt++)
        #pragma unroll
        for (int nt = 0; nt < 4; nt++) {
            const float* c = acc + (mt * 4 + nt) * 4;
            size_t r = rbase + mt * 16, cc = cbase + nt * 8;
            *(uint32_t*)(o + r * CC + cc) = h2pack(c[0], c[1]);
            *(uint32_t*)(o + (r + 8) * CC + cc) = h2pack(c[2], c[3]);
        }
}

// ---------------------------------------------------------------------------
// Kernel: split-K M partials. grid (8, 8, 4): z = K-slice of 256.
// ---------------------------------------------------------------------------
__global__ __launch_bounds__(256, 2) void m_gemm_split()
{
    const int row0 = blockIdx.y * 128;   // c
    const int col0 = blockIdx.x * 128;   // c'
    const int z = blockIdx.z;
    float acc[64];
    #pragma unroll
    for (int i = 0; i < 64; i++) acc[i] = 0.0f;
    run_gemm<true>(g_WqT + z * 256, CC, g_Wk + (size_t)(z * 256) * CC, CC,
                   256, row0, col0, acc);
    float* o = g_Mp + (size_t)z * CC * CC;
    const int wid = threadIdx.x >> 5, lane = threadIdx.x & 31;
    const int rbase = row0 + (wid >> 2) * 64 + (lane >> 2);
    const int cbase = col0 + (wid & 3) * 32 + 2 * (lane & 3);
    #pragma unroll
    for (int mt = 0; mt < 4; mt++)
        #pragma unroll
        for (int nt = 0; nt < 4; nt++) {
            const float* c = acc + (mt * 4 + nt) * 4;
            size_t r = rbase + mt * 16, cc = cbase + nt * 8;
            *(float2*)(o + r * CC + cc) = make_float2(c[0], c[1]);
            *(float2*)(o + (r + 8) * CC + cc) = make_float2(c[2], c[3]);
        }
}

// ---------------------------------------------------------------------------
// Kernel: reduce 4 fp32 partials -> fp16 M. grid (512), 2 quads/thread (MLP).
// ---------------------------------------------------------------------------
__global__ __launch_bounds__(256) void m_reduce()
{
    const size_t i0 = (size_t)blockIdx.x * 512 + threadIdx.x;
    #pragma unroll
    for (int q = 0; q < 2; q++) {
        const size_t i = i0 + q * 256;
        float4 a = ((const float4*)g_Mp)[i];
        float4 b = ((const float4*)(g_Mp + CC * CC))[i];
        float4 c = ((const float4*)(g_Mp + 2 * CC * CC))[i];
        float4 d = ((const float4*)(g_Mp + 3 * CC * CC))[i];
        float x0 = a.x + b.x + c.x + d.x;
        float x1 = a.y + b.y + c.y + d.y;
        float x2 = a.z + b.z + c.z + d.z;
        float x3 = a.w + b.w + c.w + d.w;
        uint2 hw;
        hw.x = h2pack(x0, x1); hw.y = h2pack(x2, x3);
        ((uint2*)g_M)[i] = hw;
    }
}

// ---------------------------------------------------------------------------
// Kernel: V_b = X_b Wv^T. grid (8, 16). NT. (needs only X + Wv)
// ---------------------------------------------------------------------------
__global__ __launch_bounds__(256, 2) void v_gemm(int b)
{
    const int row0 = b * TT + blockIdx.y * 128;
    const int col0 = blockIdx.x * 128;
    float acc[64];
    #pragma unroll
    for (int i = 0; i < 64; i++) acc[i] = 0.0f;
    run_gemm<false>(g_Xh, CC, g_Wv, CC, CC, row0, col0, acc);
    epilogue_h(g_Vh, row0, col0, acc);
}

// ---------------------------------------------------------------------------
// Kernel: G_b = X_b M. grid (8, 16). TRANSB (M [c][c']). (needs M)
// ---------------------------------------------------------------------------
__global__ __launch_bounds__(256, 2) void g_gemm(int b)
{
    const int row0 = b * TT + blockIdx.y * 128;
    const int col0 = blockIdx.x * 128;
    float acc[64];
    #pragma unroll
    for (int i = 0; i < 64; i++) acc[i] = 0.0f;
    run_gemm<true>(g_Xh, CC, g_M, CC, CC, row0, col0, acc);
    epilogue_h(g_Gh, row0, col0, acc);
}

// ---------------------------------------------------------------------------
// Kernel: S_b = scale * G_b X_b^T, causal tile skip. grid (16, 16). NT.
// ---------------------------------------------------------------------------
__global__ __launch_bounds__(256, 2) void qk_gemm(int b)
{
    const int row0 = blockIdx.y * 128;
    const int col0 = blockIdx.x * 128;
    if (col0 > row0 + 127) return;
    const size_t xo = (size_t)b * TT * CC;
    float acc[64];
    #pragma unroll
    for (int i = 0; i < 64; i++) acc[i] = 0.0f;
    run_gemm<false>(g_Gh + xo, CC, g_Xh + xo, CC, CC, row0, col0, acc);
    const int wid = threadIdx.x >> 5, lane = threadIdx.x & 31;
    const int rbase = row0 + (wid >> 2) * 64 + (lane >> 2);
    const int cbase = col0 + (wid & 3) * 32 + 2 * (lane & 3);
    float* S = g_S + (size_t)b * TT * TT;
    #pragma unroll
    for (int mt = 0; mt < 4; mt++)
        #pragma unroll
        for (int nt = 0; nt < 4; nt++) {
            const float* c = acc + (mt * 4 + nt) * 4;
            size_t r = rbase + mt * 16, cc = cbase + nt * 8;
            *(float2*)(S + r * TT + cc) = make_float2(c[0] * 0.03125f, c[1] * 0.03125f);
            *(float2*)(S + (r + 8) * TT + cc) = make_float2(c[2] * 0.03125f, c[3] * 0.03125f);
        }
}

// ---------------------------------------------------------------------------
// Kernel: causal softmax -> fp16 P, batch b. grid (2048). Row in registers.
// ---------------------------------------------------------------------------
__global__ __launch_bounds__(256) void softmax_k(int b)
{
    const int t = blockIdx.x;
    const float* row = g_S + ((size_t)b * TT + t) * TT;
    fp16* ph = g_Ph + ((size_t)b * TT + t) * TT;
    const int n = t + 1;
    const int nend = ((t >> 7) + 1) << 7;
    const int tid = threadIdx.x;
    const int lane = tid & 31, wrp = tid >> 5;
    __shared__ float red[8];

    float v[8];
    int cnt = 0;
    float m = -1e30f;
    for (int j = tid; j < n; j += 256) {
        float x = row[j];
        v[cnt++] = x;
        m = fmaxf(m, x);
    }
    #pragma unroll
    for (int o = 16; o > 0; o >>= 1)
        m = fmaxf(m, __shfl_xor_sync(0xffffffffu, m, o));
    if (lane == 0) red[wrp] = m;
    __syncthreads();
    m = red[0];
    #pragma unroll
    for (int w = 1; w < 8; w++) m = fmaxf(m, red[w]);
    __syncthreads();

    float sum = 0.0f;
    #pragma unroll
    for (int c = 0; c < 8; c++)
        if (c < cnt) {
            float e = __expf(v[c] - m);
            v[c] = e;
            sum += e;
        }
    #pragma unroll
    for (int o = 16; o > 0; o >>= 1)
        sum += __shfl_xor_sync(0xffffffffu, sum, o);
    if (lane == 0) red[wrp] = sum;
    __syncthreads();
    sum = red[0];
    #pragma unroll
    for (int w = 1; w < 8; w++) sum += red[w];
    const float inv = 1.0f / sum;

    int c = 0;
    for (int j = tid; j < n; j += 256)
        ph[j] = __float2half_rn(v[c++] * inv);
    const fp16 z = __float2half_rn(0.0f);
    for (int j = n + tid; j < nend; j += 256) ph[j] = z;
}

// ---------------------------------------------------------------------------
// Kernel: O_b = P_b V_b (K truncated causally). grid (8, 16).
// ---------------------------------------------------------------------------
__global__ __launch_bounds__(256, 2) void pv_gemm(float* __restrict__ out, int b)
{
    const int row0 = blockIdx.y * 128;     // query tile
    const int col0 = blockIdx.x * 128;     // channel tile
    const size_t po = (size_t)b * TT * TT;
    const size_t vo = (size_t)b * TT * CC;
    float acc[64];
    #pragma unroll
    for (int i = 0; i < 64; i++) acc[i] = 0.0f;
    run_gemm<true>(g_Ph + po, TT, g_Vh + vo, CC, row0 + 128, row0, col0, acc);
    const int wid = threadIdx.x >> 5, lane = threadIdx.x & 31;
    const int rbase = row0 + (wid >> 2) * 64 + (lane >> 2);
    const int cbase = col0 + (wid & 3) * 32 + 2 * (lane & 3);
    float* O = out + (size_t)b * TT * CC;
    #pragma unroll
    for (int mt = 0; mt < 4; mt++)
        #pragma unroll
        for (int nt = 0; nt < 4; nt++) {
            const float* c = acc + (mt * 4 + nt) * 4;
            size_t r = rbase + mt * 16, cc = cbase + nt * 8;
            *(float2*)(O + r * CC + cc) = make_float2(c[0], c[1]);
            *(float2*)(O + (r + 8) * CC + cc) = make_float2(c[2], c[3]);
        }
}

// ---------------------------------------------------------------------------
// Kernel: fp32 -> fp16 for x. grid (4096), 2 float4/thread (MLP).
// ---------------------------------------------------------------------------
__global__ __launch_bounds__(256) void convert_x(const float* __restrict__ x)
{
    const size_t i0 = (size_t)blockIdx.x * 512 + threadIdx.x;
    #pragma unroll
    for (int q = 0; q < 2; q++) {
        const size_t i = i0 + q * 256;
        float4 v = ((const float4*)x)[i];
        uint2 hw;
        hw.x = h2pack(v.x, v.y); hw.y = h2pack(v.z, v.w);
        ((uint2*)g_Xh)[i] = hw;
    }
}

// ---------------------------------------------------------------------------
// Kernel: W prep, fused. Blocks [0,2048): convert Wk/Wv (float4).
// Blocks [2048,3072): transpose+convert Wq -> WqT (32x32 smem tile).
// ---------------------------------------------------------------------------
__global__ __launch_bounds__(256) void prep_w(
    const float* __restrict__ wq, const float* __restrict__ wk,
    const float* __restrict__ wv)
{
    if (blockIdx.x < 2048) {
        const size_t i = (size_t)blockIdx.x * 256 + threadIdx.x;
        const int w = (int)(i / 262144);
        const size_t off = i - (size_t)w * 262144;
        const float* src = (w == 0) ? wk : wv;
        fp16* dst = (w == 0) ? g_Wk : g_Wv;
        float4 v = ((const float4*)src)[off];
        uint2 hw;
        hw.x = h2pack(v.x, v.y); hw.y = h2pack(v.z, v.w);
        ((uint2*)dst)[off] = hw;
    } else {
        __shared__ float tbuf[32][33];
        const int t = blockIdx.x - 2048;
        const int c0 = (t & 31) * 32, d0 = (t >> 5) * 32;
        const int tx = threadIdx.x & 31, ty = threadIdx.x >> 5;
        #pragma unroll
        for (int i = 0; i < 4; i++)
            tbuf[ty + i * 8][tx] = wq[(size_t)(d0 + ty + i * 8) * CC + c0 + tx];
        __syncthreads();
        #pragma unroll
        for (int i = 0; i < 4; i++)
            g_WqT[(size_t)(c0 + ty + i * 8) * CC + d0 + tx] =
                __float2half_rn(tbuf[tx][ty + i * 8]);
    }
}

// ---------------------------------------------------------------------------
extern "C" void kernel_launch(void* const* d_in, const int* in_sizes, int n_in,
                              void* d_out, int out_size)
{
    const float* x  = (const float*)d_in[0];
    const float* Wq = (const float*)d_in[1];
    const float* Wk = (const float*)d_in[2];
    const float* Wv = (const float*)d_in[3];
    float* out = (float*)d_out;

    // One-time resource setup (first call is the uncaptured correctness run).
    // Footprint: 3 created streams, 7 events, 24 kernel nodes.
    static cudaStream_t st[3];
    static cudaEvent_t  evRoot, evX, evW, evM, evJ[3];
    static bool inited = false;
    if (!inited) {
        for (int i = 0; i < 3; i++)
            cudaStreamCreateWithFlags(&st[i], cudaStreamNonBlocking);
        cudaEventCreateWithFlags(&evRoot, cudaEventDisableTiming);
        cudaEventCreateWithFlags(&evX, cudaEventDisableTiming);
        cudaEventCreateWithFlags(&evW, cudaEventDisableTiming);
        cudaEventCreateWithFlags(&evM, cudaEventDisableTiming);
        for (int i = 0; i < 3; i++)
            cudaEventCreateWithFlags(&evJ[i], cudaEventDisableTiming);
        cudaFuncSetAttribute(m_gemm_split, cudaFuncAttributeMaxDynamicSharedMemorySize, SMEM_BYTES);
        cudaFuncSetAttribute(v_gemm,  cudaFuncAttributeMaxDynamicSharedMemorySize, SMEM_BYTES);
        cudaFuncSetAttribute(g_gemm,  cudaFuncAttributeMaxDynamicSharedMemorySize, SMEM_BYTES);
        cudaFuncSetAttribute(qk_gemm, cudaFuncAttributeMaxDynamicSharedMemorySize, SMEM_BYTES);
        cudaFuncSetAttribute(pv_gemm, cudaFuncAttributeMaxDynamicSharedMemorySize, SMEM_BYTES);
        inited = true;
    }

    // Root fork from the capture-origin stream.
    cudaEventRecord(evRoot, 0);

    // W-side chain on st[2]: prep (Wk/Wv convert + Wq transpose) -> M chain.
    cudaStreamWaitEvent(st[2], evRoot, 0);
    prep_w<<<3072, 256, 0, st[2]>>>(Wq, Wk, Wv);
    cudaEventRecord(evW, st[2]);                    // Wk/Wv/WqT ready
    m_gemm_split<<<dim3(8, 8, 4), 256, SMEM_BYTES, st[2]>>>();
    m_reduce<<<512, 256, 0, st[2]>>>();
    cudaEventRecord(evM, st[2]);                    // M ready

    // X conversion on the capture-origin stream (concurrent with W chain).
    convert_x<<<4096, 256>>>(x);
    cudaEventRecord(evX, 0);

    // Batch 0 chain on main: V (needs X+Wv) fills the M-chain window, then G.
    cudaStreamWaitEvent(0, evW, 0);
    v_gemm<<<dim3(8, 16), 256, SMEM_BYTES>>>(0);
    cudaStreamWaitEvent(0, evM, 0);
    g_gemm<<<dim3(8, 16), 256, SMEM_BYTES>>>(0);
    qk_gemm<<<dim3(16, 16), 256, SMEM_BYTES>>>(0);
    softmax_k<<<2048, 256>>>(0);
    pv_gemm<<<dim3(8, 16), 256, SMEM_BYTES>>>(out, 0);

    // Batches 1..3 on side streams (st[2] reused; its W/M chain is in-stream).
    for (int i = 0; i < 3; i++) {
        const int b = i + 1;
        cudaStreamWaitEvent(st[i], evX, 0);
        if (i != 2) cudaStreamWaitEvent(st[i], evW, 0);
        v_gemm<<<dim3(8, 16), 256, SMEM_BYTES, st[i]>>>(b);
        if (i != 2) cudaStreamWaitEvent(st[i], evM, 0);
        g_gemm<<<dim3(8, 16), 256, SMEM_BYTES, st[i]>>>(b);
        qk_gemm<<<dim3(16, 16), 256, SMEM_BYTES, st[i]>>>(b);
        softmax_k<<<2048, 256, 0, st[i]>>>(b);
        pv_gemm<<<dim3(8, 16), 256, SMEM_BYTES, st[i]>>>(out, b);
        cudaEventRecord(evJ[i], st[i]);
    }
    // Join back into the capture-origin stream.
    for (int i = 0; i < 3; i++)
        cudaStreamWaitEvent(0, evJ[i], 0);
}

// round 17
// speedup vs baseline: 8.3941x; 1.0033x over previous
#include <cuda_runtime.h>
#include <cuda_fp16.h>
#include <stdint.h>
#include <math.h>

#define BB 4
#define TT 2048
#define CC 1024
#define NTOK 8192   // BB*TT

typedef __half fp16;

// ---------------- scratch (__device__ globals; allocation-free rule) -------
__device__ __align__(256) fp16 g_Xh [NTOK * CC];
__device__ __align__(256) fp16 g_Wk [CC * CC];
__device__ __align__(256) fp16 g_Wv [CC * CC];
__device__ __align__(256) fp16 g_WqT[CC * CC];       // Wq transposed [c][d]
__device__ __align__(256) float g_Mp[4 * CC * CC];   // split-K partials (fp32)
__device__ __align__(256) fp16 g_M  [CC * CC];       // Wq^T Wk, [c][c']
__device__ __align__(256) fp16 g_Gh [NTOK * CC];     // X M
__device__ __align__(256) fp16 g_Vh [NTOK * CC];     // [token][channel]
__device__ __align__(256) float g_S[(size_t)BB * TT * TT];
__device__ __align__(256) fp16 g_Ph[(size_t)BB * TT * TT];

// ---------------- helpers ---------------------------------------------------
__device__ __forceinline__ uint32_t smem_u32(const void* p) {
    uint32_t a;
    asm("{ .reg .u64 t; cvta.to.shared.u64 t, %1; cvt.u32.u64 %0, t; }" : "=r"(a) : "l"(p));
    return a;
}
__device__ __forceinline__ void cp16(uint32_t s, const void* g) {
    asm volatile("cp.async.cg.shared.global [%0], [%1], 16;" :: "r"(s), "l"(g));
}
#define CP_COMMIT() asm volatile("cp.async.commit_group;" ::: "memory")
#define CP_WAIT1()  asm volatile("cp.async.wait_group 1;" ::: "memory")

__device__ __forceinline__ void ldsm4(uint32_t a, uint32_t& r0, uint32_t& r1,
                                      uint32_t& r2, uint32_t& r3) {
    asm volatile("ldmatrix.sync.aligned.m8n8.x4.shared.b16 {%0,%1,%2,%3}, [%4];"
                 : "=r"(r0), "=r"(r1), "=r"(r2), "=r"(r3) : "r"(a));
}
__device__ __forceinline__ void ldsm4t(uint32_t a, uint32_t& r0, uint32_t& r1,
                                       uint32_t& r2, uint32_t& r3) {
    asm volatile("ldmatrix.sync.aligned.m8n8.x4.trans.shared.b16 {%0,%1,%2,%3}, [%4];"
                 : "=r"(r0), "=r"(r1), "=r"(r2), "=r"(r3) : "r"(a));
}
__device__ __forceinline__ void mma16816(float* c, const uint32_t* a, uint32_t b0, uint32_t b1) {
    asm volatile(
        "mma.sync.aligned.m16n8k16.row.col.f32.f16.f16.f32 "
        "{%0,%1,%2,%3}, {%4,%5,%6,%7}, {%8,%9}, {%0,%1,%2,%3};"
        : "+f"(c[0]), "+f"(c[1]), "+f"(c[2]), "+f"(c[3])
        : "r"(a[0]), "r"(a[1]), "r"(a[2]), "r"(a[3]), "r"(b0), "r"(b1));
}
__device__ __forceinline__ uint32_t h2pack(float a, float b) {
    __half2 h = __floats2half2_rn(a, b);
    return *reinterpret_cast<uint32_t*>(&h);
}

// smem: 3 stages x 2 tiles (A, B) x 18432B = 110592B  -> 2 CTAs/SM
#define TILE_B  18432
#define STAGE_B (2 * TILE_B)
#define NSTAGE  3
#define SMEM_BYTES (NSTAGE * STAGE_B)
#define PAD_NT 144   // bytes per 64-elem k-row (128B + 16 pad)
#define PAD_TR 272   // bytes per 128-elem n-row (256B + 16 pad)

extern __shared__ char dsm[];

// ---------------------------------------------------------------------------
// 128x128 tile fp16 GEMM: C = A * B^T(NT, B [n][k]) or A * B(TRANSB, B [k][n]).
// 3-stage cp.async pipeline, single barrier per stage.
// ---------------------------------------------------------------------------
template <bool TRANSB>
__device__ __forceinline__ void run_gemm(
    const fp16* __restrict__ A, int lda,
    const fp16* __restrict__ B, int ldb,
    int Ktot, int row0, int col0, float* acc)
{
    const int tid = threadIdx.x;
    const int wid = tid >> 5, lane = tid & 31;
    const int wm = (wid >> 2) * 64, wn = (wid & 3) * 32;
    const uint32_t smem = smem_u32(dsm);
    const int nk = Ktot >> 6;

    auto load_stage = [&](int s, int buf) {
        const int kk0 = s << 6;
        const uint32_t base = smem + buf * STAGE_B;
        #pragma unroll
        for (int i = 0; i < 4; i++) {
            int c = tid + i * 256;                 // 0..1023
            int r = c >> 3, kc = c & 7;
            cp16(base + (uint32_t)r * PAD_NT + kc * 16,
                 A + (size_t)(row0 + r) * lda + kk0 + kc * 8);
            if (!TRANSB) {
                cp16(base + TILE_B + (uint32_t)r * PAD_NT + kc * 16,
                     B + (size_t)(col0 + r) * ldb + kk0 + kc * 8);
            } else {
                int rt = c >> 4, nc = c & 15;
                cp16(base + TILE_B + (uint32_t)rt * PAD_TR + nc * 16,
                     B + (size_t)(kk0 + rt) * ldb + col0 + nc * 8);
            }
        }
    };

    load_stage(0, 0); CP_COMMIT();
    if (nk > 1) load_stage(1, 1);
    CP_COMMIT();

    for (int s = 0; s < nk; s++) {
        const int buf = s % 3;
        const uint32_t base = smem + buf * STAGE_B;
        CP_WAIT1();
        __syncthreads();
        if (s + 2 < nk) load_stage(s + 2, (s + 2) % 3);
        CP_COMMIT();

        #pragma unroll
        for (int kk = 0; kk < 4; kk++) {
            uint32_t aF[4][4];
            #pragma unroll
            for (int mt = 0; mt < 4; mt++) {
                uint32_t a = base + (uint32_t)(wm + mt * 16 + (lane & 7) + ((lane >> 3) & 1) * 8) * PAD_NT
                           + kk * 32 + ((lane >> 4) & 1) * 16;
                ldsm4(a, aF[mt][0], aF[mt][1], aF[mt][2], aF[mt][3]);
            }
            uint32_t bF[4][2];
            #pragma unroll
            for (int pr = 0; pr < 2; pr++) {
                uint32_t r0, r1, r2, r3;
                if (!TRANSB) {
                    uint32_t a = base + TILE_B
                               + (uint32_t)(wn + pr * 16 + (lane & 7) + ((lane >> 3) & 1) * 8) * PAD_NT
                               + kk * 32 + ((lane >> 4) & 1) * 16;
                    ldsm4(a, r0, r1, r2, r3);
                } else {
                    uint32_t a = base + TILE_B
                               + (uint32_t)(kk * 16 + (lane & 7) + ((lane >> 4) & 1) * 8) * PAD_TR
                               + (wn + pr * 16) * 2 + ((lane >> 3) & 1) * 16;
                    ldsm4t(a, r0, r1, r2, r3);
                }
                bF[pr * 2 + 0][0] = r0; bF[pr * 2 + 0][1] = r2;
                bF[pr * 2 + 1][0] = r1; bF[pr * 2 + 1][1] = r3;
            }
            #pragma unroll
            for (int mt = 0; mt < 4; mt++)
                #pragma unroll
                for (int nt = 0; nt < 4; nt++)
                    mma16816(acc + (mt * 4 + nt) * 4, aF[mt], bF[nt][0], bF[nt][1]);
        }
    }
}

// Common fp16 epilogue: write 128x128 tile of acc to o[r][c], ld=CC.
__device__ __forceinline__ void epilogue_h(fp16* o, int row0, int col0, const float* acc)
{
    const int wid = threadIdx.x >> 5, lane = threadIdx.x & 31;
    const int rbase = row0 + (wid >> 2) * 64 + (lane >> 2);
    const int cbase = col0 + (wid & 3) * 32 + 2 * (lane & 3);
    #pragma unroll
    for (int mt = 0; mt < 4; mt++)
        #pragma unroll
        for (int nt = 0; nt < 4; nt++) {
            const float* c = acc + (mt * 4 + nt) * 4;
            size_t r = rbase + mt * 16, cc = cbase + nt * 8;
            *(uint32_t*)(o + r * CC + cc) = h2pack(c[0], c[1]);
            *(uint32_t*)(o + (r + 8) * CC + cc) = h2pack(c[2], c[3]);
        }
}

// ---------------------------------------------------------------------------
// Kernel: split-K M partials. grid (8, 8, 4): z = K-slice of 256.
// ---------------------------------------------------------------------------
__global__ __launch_bounds__(256, 2) void m_gemm_split()
{
    const int row0 = blockIdx.y * 128;   // c
    const int col0 = blockIdx.x * 128;   // c'
    const int z = blockIdx.z;
    float acc[64];
    #pragma unroll
    for (int i = 0; i < 64; i++) acc[i] = 0.0f;
    run_gemm<true>(g_WqT + z * 256, CC, g_Wk + (size_t)(z * 256) * CC, CC,
                   256, row0, col0, acc);
    float* o = g_Mp + (size_t)z * CC * CC;
    const int wid = threadIdx.x >> 5, lane = threadIdx.x & 31;
    const int rbase = row0 + (wid >> 2) * 64 + (lane >> 2);
    const int cbase = col0 + (wid & 3) * 32 + 2 * (lane & 3);
    #pragma unroll
    for (int mt = 0; mt < 4; mt++)
        #pragma unroll
        for (int nt = 0; nt < 4; nt++) {
            const float* c = acc + (mt * 4 + nt) * 4;
            size_t r = rbase + mt * 16, cc = cbase + nt * 8;
            *(float2*)(o + r * CC + cc) = make_float2(c[0], c[1]);
            *(float2*)(o + (r + 8) * CC + cc) = make_float2(c[2], c[3]);
        }
}

// ---------------------------------------------------------------------------
// Kernel: reduce 4 fp32 partials -> fp16 M. grid (512), 2 quads/thread (MLP).
// ---------------------------------------------------------------------------
__global__ __launch_bounds__(256) void m_reduce()
{
    const size_t i0 = (size_t)blockIdx.x * 512 + threadIdx.x;
    #pragma unroll
    for (int q = 0; q < 2; q++) {
        const size_t i = i0 + q * 256;
        float4 a = ((const float4*)g_Mp)[i];
        float4 b = ((const float4*)(g_Mp + CC * CC))[i];
        float4 c = ((const float4*)(g_Mp + 2 * CC * CC))[i];
        float4 d = ((const float4*)(g_Mp + 3 * CC * CC))[i];
        float x0 = a.x + b.x + c.x + d.x;
        float x1 = a.y + b.y + c.y + d.y;
        float x2 = a.z + b.z + c.z + d.z;
        float x3 = a.w + b.w + c.w + d.w;
        uint2 hw;
        hw.x = h2pack(x0, x1); hw.y = h2pack(x2, x3);
        ((uint2*)g_M)[i] = hw;
    }
}

// ---------------------------------------------------------------------------
// Kernel: V_b = X_b Wv^T. grid (8, 16). NT. (needs only X_b + Wv)
// ---------------------------------------------------------------------------
__global__ __launch_bounds__(256, 2) void v_gemm(int b)
{
    const int row0 = b * TT + blockIdx.y * 128;
    const int col0 = blockIdx.x * 128;
    float acc[64];
    #pragma unroll
    for (int i = 0; i < 64; i++) acc[i] = 0.0f;
    run_gemm<false>(g_Xh, CC, g_Wv, CC, CC, row0, col0, acc);
    epilogue_h(g_Vh, row0, col0, acc);
}

// ---------------------------------------------------------------------------
// Kernel: G_b = X_b M. grid (8, 16). TRANSB (M [c][c']). (needs M)
// ---------------------------------------------------------------------------
__global__ __launch_bounds__(256, 2) void g_gemm(int b)
{
    const int row0 = b * TT + blockIdx.y * 128;
    const int col0 = blockIdx.x * 128;
    float acc[64];
    #pragma unroll
    for (int i = 0; i < 64; i++) acc[i] = 0.0f;
    run_gemm<true>(g_Xh, CC, g_M, CC, CC, row0, col0, acc);
    epilogue_h(g_Gh, row0, col0, acc);
}

// ---------------------------------------------------------------------------
// Kernel: S_b = scale * G_b X_b^T, causal tile skip. grid (16, 16). NT.
// ---------------------------------------------------------------------------
__global__ __launch_bounds__(256, 2) void qk_gemm(int b)
{
    const int row0 = blockIdx.y * 128;
    const int col0 = blockIdx.x * 128;
    if (col0 > row0 + 127) return;
    const size_t xo = (size_t)b * TT * CC;
    float acc[64];
    #pragma unroll
    for (int i = 0; i < 64; i++) acc[i] = 0.0f;
    run_gemm<false>(g_Gh + xo, CC, g_Xh + xo, CC, CC, row0, col0, acc);
    const int wid = threadIdx.x >> 5, lane = threadIdx.x & 31;
    const int rbase = row0 + (wid >> 2) * 64 + (lane >> 2);
    const int cbase = col0 + (wid & 3) * 32 + 2 * (lane & 3);
    float* S = g_S + (size_t)b * TT * TT;
    #pragma unroll
    for (int mt = 0; mt < 4; mt++)
        #pragma unroll
        for (int nt = 0; nt < 4; nt++) {
            const float* c = acc + (mt * 4 + nt) * 4;
            size_t r = rbase + mt * 16, cc = cbase + nt * 8;
            *(float2*)(S + r * TT + cc) = make_float2(c[0] * 0.03125f, c[1] * 0.03125f);
            *(float2*)(S + (r + 8) * TT + cc) = make_float2(c[2] * 0.03125f, c[3] * 0.03125f);
        }
}

// ---------------------------------------------------------------------------
// Kernel: causal softmax -> fp16 P, batch b. grid (2048). Row in registers.
// ---------------------------------------------------------------------------
__global__ __launch_bounds__(256) void softmax_k(int b)
{
    const int t = blockIdx.x;
    const float* row = g_S + ((size_t)b * TT + t) * TT;
    fp16* ph = g_Ph + ((size_t)b * TT + t) * TT;
    const int n = t + 1;
    const int nend = ((t >> 7) + 1) << 7;
    const int tid = threadIdx.x;
    const int lane = tid & 31, wrp = tid >> 5;
    __shared__ float red[8];

    float v[8];
    int cnt = 0;
    float m = -1e30f;
    for (int j = tid; j < n; j += 256) {
        float x = row[j];
        v[cnt++] = x;
        m = fmaxf(m, x);
    }
    #pragma unroll
    for (int o = 16; o > 0; o >>= 1)
        m = fmaxf(m, __shfl_xor_sync(0xffffffffu, m, o));
    if (lane == 0) red[wrp] = m;
    __syncthreads();
    m = red[0];
    #pragma unroll
    for (int w = 1; w < 8; w++) m = fmaxf(m, red[w]);
    __syncthreads();

    float sum = 0.0f;
    #pragma unroll
    for (int c = 0; c < 8; c++)
        if (c < cnt) {
            float e = __expf(v[c] - m);
            v[c] = e;
            sum += e;
        }
    #pragma unroll
    for (int o = 16; o > 0; o >>= 1)
        sum += __shfl_xor_sync(0xffffffffu, sum, o);
    if (lane == 0) red[wrp] = sum;
    __syncthreads();
    sum = red[0];
    #pragma unroll
    for (int w = 1; w < 8; w++) sum += red[w];
    const float inv = 1.0f / sum;

    int c = 0;
    for (int j = tid; j < n; j += 256)
        ph[j] = __float2half_rn(v[c++] * inv);
    const fp16 z = __float2half_rn(0.0f);
    for (int j = n + tid; j < nend; j += 256) ph[j] = z;
}

// ---------------------------------------------------------------------------
// Kernel: O_b = P_b V_b (K truncated causally). grid (8, 16).
// ---------------------------------------------------------------------------
__global__ __launch_bounds__(256, 2) void pv_gemm(float* __restrict__ out, int b)
{
    const int row0 = blockIdx.y * 128;     // query tile
    const int col0 = blockIdx.x * 128;     // channel tile
    const size_t po = (size_t)b * TT * TT;
    const size_t vo = (size_t)b * TT * CC;
    float acc[64];
    #pragma unroll
    for (int i = 0; i < 64; i++) acc[i] = 0.0f;
    run_gemm<true>(g_Ph + po, TT, g_Vh + vo, CC, row0 + 128, row0, col0, acc);
    const int wid = threadIdx.x >> 5, lane = threadIdx.x & 31;
    const int rbase = row0 + (wid >> 2) * 64 + (lane >> 2);
    const int cbase = col0 + (wid & 3) * 32 + 2 * (lane & 3);
    float* O = out + (size_t)b * TT * CC;
    #pragma unroll
    for (int mt = 0; mt < 4; mt++)
        #pragma unroll
        for (int nt = 0; nt < 4; nt++) {
            const float* c = acc + (mt * 4 + nt) * 4;
            size_t r = rbase + mt * 16, cc = cbase + nt * 8;
            *(float2*)(O + r * CC + cc) = make_float2(c[0], c[1]);
            *(float2*)(O + (r + 8) * CC + cc) = make_float2(c[2], c[3]);
        }
}

// ---------------------------------------------------------------------------
// Kernel: fp32 -> fp16 for X batch b (2M elems). grid (1024), 2 float4/thr.
// ---------------------------------------------------------------------------
__global__ __launch_bounds__(256) void convert_xb(const float* __restrict__ x, int b)
{
    const size_t base = (size_t)b * TT * CC / 4;       // float4 offset
    const size_t i0 = base + (size_t)blockIdx.x * 512 + threadIdx.x;
    #pragma unroll
    for (int q = 0; q < 2; q++) {
        const size_t i = i0 + q * 256;
        float4 v = ((const float4*)x)[i];
        uint2 hw;
        hw.x = h2pack(v.x, v.y); hw.y = h2pack(v.z, v.w);
        ((uint2*)g_Xh)[i] = hw;
    }
}

// ---------------------------------------------------------------------------
// Kernel: W prep, fused. Blocks [0,2048): convert Wk/Wv (float4).
// Blocks [2048,3072): transpose+convert Wq -> WqT (32x32 smem tile).
// ---------------------------------------------------------------------------
__global__ __launch_bounds__(256) void prep_w(
    const float* __restrict__ wq, const float* __restrict__ wk,
    const float* __restrict__ wv)
{
    if (blockIdx.x < 2048) {
        const size_t i = (size_t)blockIdx.x * 256 + threadIdx.x;
        const int w = (int)(i / 262144);
        const size_t off = i - (size_t)w * 262144;
        const float* src = (w == 0) ? wk : wv;
        fp16* dst = (w == 0) ? g_Wk : g_Wv;
        float4 v = ((const float4*)src)[off];
        uint2 hw;
        hw.x = h2pack(v.x, v.y); hw.y = h2pack(v.z, v.w);
        ((uint2*)dst)[off] = hw;
    } else {
        __shared__ float tbuf[32][33];
        const int t = blockIdx.x - 2048;
        const int c0 = (t & 31) * 32, d0 = (t >> 5) * 32;
        const int tx = threadIdx.x & 31, ty = threadIdx.x >> 5;
        #pragma unroll
        for (int i = 0; i < 4; i++)
            tbuf[ty + i * 8][tx] = wq[(size_t)(d0 + ty + i * 8) * CC + c0 + tx];
        __syncthreads();
        #pragma unroll
        for (int i = 0; i < 4; i++)
            g_WqT[(size_t)(c0 + ty + i * 8) * CC + d0 + tx] =
                __float2half_rn(tbuf[tx][ty + i * 8]);
    }
}

// ---------------------------------------------------------------------------
extern "C" void kernel_launch(void* const* d_in, const int* in_sizes, int n_in,
                              void* d_out, int out_size)
{
    const float* x  = (const float*)d_in[0];
    const float* Wq = (const float*)d_in[1];
    const float* Wk = (const float*)d_in[2];
    const float* Wv = (const float*)d_in[3];
    float* out = (float*)d_out;

    // One-time resource setup (first call is the uncaptured correctness run).
    // Footprint: 3 created streams, 6 events, 27 kernel nodes.
    static cudaStream_t st[3];
    static cudaEvent_t  evRoot, evW, evM, evJ[3];
    static bool inited = false;
    if (!inited) {
        for (int i = 0; i < 3; i++)
            cudaStreamCreateWithFlags(&st[i], cudaStreamNonBlocking);
        cudaEventCreateWithFlags(&evRoot, cudaEventDisableTiming);
        cudaEventCreateWithFlags(&evW, cudaEventDisableTiming);
        cudaEventCreateWithFlags(&evM, cudaEventDisableTiming);
        for (int i = 0; i < 3; i++)
            cudaEventCreateWithFlags(&evJ[i], cudaEventDisableTiming);
        cudaFuncSetAttribute(m_gemm_split, cudaFuncAttributeMaxDynamicSharedMemorySize, SMEM_BYTES);
        cudaFuncSetAttribute(v_gemm,  cudaFuncAttributeMaxDynamicSharedMemorySize, SMEM_BYTES);
        cudaFuncSetAttribute(g_gemm,  cudaFuncAttributeMaxDynamicSharedMemorySize, SMEM_BYTES);
        cudaFuncSetAttribute(qk_gemm, cudaFuncAttributeMaxDynamicSharedMemorySize, SMEM_BYTES);
        cudaFuncSetAttribute(pv_gemm, cudaFuncAttributeMaxDynamicSharedMemorySize, SMEM_BYTES);
        inited = true;
    }

    // Root fork from the capture-origin stream.
    cudaEventRecord(evRoot, 0);

    // W-side chain on st[2]: prep (Wk/Wv convert + Wq transpose) -> M chain.
    cudaStreamWaitEvent(st[2], evRoot, 0);
    prep_w<<<3072, 256, 0, st[2]>>>(Wq, Wk, Wv);
    cudaEventRecord(evW, st[2]);                    // Wk/Wv/WqT ready
    m_gemm_split<<<dim3(8, 8, 4), 256, SMEM_BYTES, st[2]>>>();
    m_reduce<<<512, 256, 0, st[2]>>>();
    cudaEventRecord(evM, st[2]);                    // M ready

    // Batch 0 chain on main: its own X-quarter convert, then V -> G -> ...
    convert_xb<<<1024, 256>>>(x, 0);
    cudaStreamWaitEvent(0, evW, 0);
    v_gemm<<<dim3(8, 16), 256, SMEM_BYTES>>>(0);
    cudaStreamWaitEvent(0, evM, 0);
    g_gemm<<<dim3(8, 16), 256, SMEM_BYTES>>>(0);
    qk_gemm<<<dim3(16, 16), 256, SMEM_BYTES>>>(0);
    softmax_k<<<2048, 256>>>(0);
    pv_gemm<<<dim3(8, 16), 256, SMEM_BYTES>>>(out, 0);

    // Batches 1..2 on st[0..1]: per-chain convert, then chain.
    for (int i = 0; i < 2; i++) {
        const int b = i + 1;
        cudaStreamWaitEvent(st[i], evRoot, 0);
        convert_xb<<<1024, 256, 0, st[i]>>>(x, b);
        cudaStreamWaitEvent(st[i], evW, 0);
        v_gemm<<<dim3(8, 16), 256, SMEM_BYTES, st[i]>>>(b);
        cudaStreamWaitEvent(st[i], evM, 0);
        g_gemm<<<dim3(8, 16), 256, SMEM_BYTES, st[i]>>>(b);
        qk_gemm<<<dim3(16, 16), 256, SMEM_BYTES, st[i]>>>(b);
        softmax_k<<<2048, 256, 0, st[i]>>>(b);
        pv_gemm<<<dim3(8, 16), 256, SMEM_BYTES, st[i]>>>(out, b);
        cudaEventRecord(evJ[i], st[i]);
    }

    // Batch 3 chain rides st[2] after the W/M chain (in-stream ordering).
    convert_xb<<<1024, 256, 0, st[2]>>>(x, 3);
    v_gemm<<<dim3(8, 16), 256, SMEM_BYTES, st[2]>>>(3);
    g_gemm<<<dim3(8, 16), 256, SMEM_BYTES, st[2]>>>(3);
    qk_gemm<<<dim3(16, 16), 256, SMEM_BYTES, st[2]>>>(3);
    softmax_k<<<2048, 256, 0, st[2]>>>(3);
    pv_gemm<<<dim3(8, 16), 256, SMEM_BYTES, st[2]>>>(out, 3);
    cudaEventRecord(evJ[2], st[2]);

    // Join back into the capture-origin stream.
    for (int i = 0; i < 3; i++)
        cudaStreamWaitEvent(0, evJ[i], 0);
}